// round 2
// baseline (speedup 1.0000x reference)
#include <cuda_runtime.h>

#define BT 80          // B * N_EXAMPLES
#define LQ 256         // L
#define SS 512         // S
#define HD 1024        // H
#define LH (LQ*HD)     // 262144

// scratch (allocation-free rule: __device__ globals)
__device__ float g_exc[(size_t)BT*LQ*HD];
__device__ float g_setc[(size_t)BT*LQ*HD];

// ---------------------------------------------------------------------------
// NT GEMM:  C[bz][m,n] = sum_k A(m,k) * B(n,k)   (both operands k-contiguous)
// A is split into up to three 1024-wide pieces (row stride of each piece = 1024):
//   piece = k / 1024  ->  A0 / A1 / A2.  For K==1024 only A0 is used.
// B row-major [N,K] (row stride = K).  Optional epilogue: tanh(x + bias[n]).
// Block tile 128x64, K-chunk 32, 256 threads, 8x4 per-thread microtile.
// All dims are exact multiples of the tiles (M=256, N in {256,512,1024},
// K in {1024,3072}) -> no bounds checks.
// ---------------------------------------------------------------------------
template<bool TANH>
__global__ __launch_bounds__(256, 2)
void gemm_nt(const float* __restrict__ A0, const float* __restrict__ A1,
             const float* __restrict__ A2, const float* __restrict__ Bm,
             const float* __restrict__ bias, float* __restrict__ C,
             int N, int K,
             long aStride, long bStride, long cStride, int bDiv)
{
    __shared__ float As[128][33];
    __shared__ float Bs[64][33];

    const int bz = blockIdx.z;
    const int m0 = blockIdx.x * 128;
    const int n0 = blockIdx.y * 64;

    const float* Bp = Bm + (long)(bz / bDiv) * bStride + (long)n0 * K;
    float*       Cp = C  + (long)bz * cStride;
    const long aOff  = (long)bz * aStride;

    const int tid = threadIdx.x;
    const int lr  = tid >> 3;          // 0..31
    const int lc  = (tid & 7) << 2;    // 0,4,..,28

    const int tm = (tid >> 4) << 3;    // 0..120 step 8
    const int tn = (tid & 15) << 2;    // 0..60  step 4

    float acc[8][4];
    #pragma unroll
    for (int i = 0; i < 8; i++)
        #pragma unroll
        for (int j = 0; j < 4; j++)
            acc[i][j] = 0.0f;

    for (int k0 = 0; k0 < K; k0 += 32) {
        const int p = k0 >> 10;
        const float* Apc = (p == 0 ? A0 : (p == 1 ? A1 : A2));
        const float* Ap  = Apc + aOff + (long)m0 * 1024 + (k0 & 1023);

        #pragma unroll
        for (int t = 0; t < 4; t++) {
            int r = lr + t * 32;
            float4 v = *(const float4*)(Ap + (long)r * 1024 + lc);
            As[r][lc + 0] = v.x; As[r][lc + 1] = v.y;
            As[r][lc + 2] = v.z; As[r][lc + 3] = v.w;
        }
        #pragma unroll
        for (int t = 0; t < 2; t++) {
            int r = lr + t * 32;
            float4 v = *(const float4*)(Bp + (long)r * K + k0 + lc);
            Bs[r][lc + 0] = v.x; Bs[r][lc + 1] = v.y;
            Bs[r][lc + 2] = v.z; Bs[r][lc + 3] = v.w;
        }
        __syncthreads();

        #pragma unroll
        for (int kk = 0; kk < 32; kk++) {
            float a[8], b[4];
            #pragma unroll
            for (int i = 0; i < 8; i++) a[i] = As[tm + i][kk];
            #pragma unroll
            for (int j = 0; j < 4; j++) b[j] = Bs[tn + j][kk];
            #pragma unroll
            for (int i = 0; i < 8; i++)
                #pragma unroll
                for (int j = 0; j < 4; j++)
                    acc[i][j] = fmaf(a[i], b[j], acc[i][j]);
        }
        __syncthreads();
    }

    #pragma unroll
    for (int i = 0; i < 8; i++) {
        #pragma unroll
        for (int j = 0; j < 4; j++) {
            int n = n0 + tn + j;
            float v = acc[i][j];
            if (TANH) v = tanhf(v + bias[n]);
            Cp[(long)(m0 + tm + i) * N + n] = v;
        }
    }
}

// ---------------------------------------------------------------------------
// NN GEMM:  C[bz][m,n] = sum_k A(m,k) * B(k,n),  N fixed = 1024.
// A row-major [M,K] (k contiguous), B row-major [K,1024] (n contiguous).
// Block tile 128x64, K-chunk 32, 256 threads, 8x4 microtile.
// ---------------------------------------------------------------------------
__global__ __launch_bounds__(256, 2)
void gemm_nn(const float* __restrict__ A, const float* __restrict__ Bm,
             float* __restrict__ C, int K,
             long aStride, long bStride, long cStride, int bDiv)
{
    __shared__ float As[128][33];
    __shared__ float Bs[32][64];

    const int bz = blockIdx.z;
    const int m0 = blockIdx.x * 128;
    const int n0 = blockIdx.y * 64;

    const float* Ap = A  + (long)bz * aStride + (long)m0 * K;
    const float* Bp = Bm + (long)(bz / bDiv) * bStride + n0;
    float*       Cp = C  + (long)bz * cStride;

    const int tid = threadIdx.x;
    const int lr  = tid >> 3;          // 0..31
    const int lc  = (tid & 7) << 2;    // 0,4,..,28
    const int br  = tid >> 4;          // 0..15
    const int bc  = (tid & 15) << 2;   // 0,4,..,60

    const int tm = (tid >> 4) << 3;
    const int tn = (tid & 15) << 2;

    float acc[8][4];
    #pragma unroll
    for (int i = 0; i < 8; i++)
        #pragma unroll
        for (int j = 0; j < 4; j++)
            acc[i][j] = 0.0f;

    for (int k0 = 0; k0 < K; k0 += 32) {
        #pragma unroll
        for (int t = 0; t < 4; t++) {
            int r = lr + t * 32;
            float4 v = *(const float4*)(Ap + (long)r * K + k0 + lc);
            As[r][lc + 0] = v.x; As[r][lc + 1] = v.y;
            As[r][lc + 2] = v.z; As[r][lc + 3] = v.w;
        }
        #pragma unroll
        for (int t = 0; t < 2; t++) {
            int r = br + t * 16;  // k-row within chunk, 0..31
            float4 v = *(const float4*)(Bp + (long)(k0 + r) * 1024 + bc);
            *(float4*)&Bs[r][bc] = v;
        }
        __syncthreads();

        #pragma unroll
        for (int kk = 0; kk < 32; kk++) {
            float a[8];
            #pragma unroll
            for (int i = 0; i < 8; i++) a[i] = As[tm + i][kk];
            float4 b4 = *(const float4*)&Bs[kk][tn];
            float b[4] = {b4.x, b4.y, b4.z, b4.w};
            #pragma unroll
            for (int i = 0; i < 8; i++)
                #pragma unroll
                for (int j = 0; j < 4; j++)
                    acc[i][j] = fmaf(a[i], b[j], acc[i][j]);
        }
        __syncthreads();
    }

    #pragma unroll
    for (int i = 0; i < 8; i++)
        #pragma unroll
        for (int j = 0; j < 4; j++)
            Cp[(long)(m0 + tm + i) * 1024 + (n0 + tn + j)] = acc[i][j];
}

// ---------------------------------------------------------------------------
// Row softmax in place. One 256-thread block per row, n in {256, 512}.
// ---------------------------------------------------------------------------
__global__ void softmax_rows(float* __restrict__ p, int n)
{
    __shared__ float red[256];
    const int tid = threadIdx.x;
    p += (long)blockIdx.x * n;

    float v0 = p[tid];
    float v1 = (n > 256) ? p[tid + 256] : -3.402823e38f;

    float m = fmaxf(v0, v1);
    red[tid] = m; __syncthreads();
    #pragma unroll
    for (int s = 128; s > 0; s >>= 1) {
        if (tid < s) red[tid] = fmaxf(red[tid], red[tid + s]);
        __syncthreads();
    }
    const float mx = red[0];
    __syncthreads();

    float e0 = __expf(v0 - mx);
    float e1 = (n > 256) ? __expf(v1 - mx) : 0.0f;
    red[tid] = e0 + e1; __syncthreads();
    #pragma unroll
    for (int s = 128; s > 0; s >>= 1) {
        if (tid < s) red[tid] += red[tid + s];
        __syncthreads();
    }
    const float inv = 1.0f / red[0];

    p[tid] = e0 * inv;
    if (n > 256) p[tid + 256] = e1 * inv;
}

// ---------------------------------------------------------------------------
extern "C" void kernel_launch(void* const* d_in, const int* in_sizes, int n_in,
                              void* d_out, int out_size)
{
    const float* Q  = (const float*)d_in[0];  // output  [80,256,1024]
    const float* C0 = (const float*)d_in[1];  // context0[80,256,1024]
    const float* C1 = (const float*)d_in[2];  // context1[8,512,1024]
    // d_in[3] = mask (unused, faithful to reference)
    const float* W  = (const float*)d_in[4];  // W_out [1024,3072]
    const float* bb = (const float*)d_in[5];  // b_out [1024]

    float* OUT = (float*)d_out;                         // [80,256,1024]
    float* EXA = OUT + (long)BT * LQ * HD;              // [80,256,256]
    float* SEA = EXA + (long)BT * LQ * LQ;              // [80,256,512]

    void *pexc, *psetc;
    cudaGetSymbolAddress(&pexc,  g_exc);
    cudaGetSymbolAddress(&psetc, g_setc);
    float* exc  = (float*)pexc;
    float* setc = (float*)psetc;

    // 1) logits
    gemm_nt<false><<<dim3(2, 4, BT), 256>>>(
        Q, nullptr, nullptr, C0, nullptr, EXA,
        /*N=*/LQ, /*K=*/HD, /*aS=*/LH, /*bS=*/LH, /*cS=*/(long)LQ*LQ, /*bDiv=*/1);
    gemm_nt<false><<<dim3(2, 8, BT), 256>>>(
        Q, nullptr, nullptr, C1, nullptr, SEA,
        /*N=*/SS, /*K=*/HD, /*aS=*/LH, /*bS=*/(long)SS*HD, /*cS=*/(long)LQ*SS, /*bDiv=*/10);

    // 2) softmax in place
    softmax_rows<<<BT * LQ, 256>>>(EXA, LQ);
    softmax_rows<<<BT * LQ, 256>>>(SEA, SS);

    // 3) attn @ V
    gemm_nn<<<dim3(2, 16, BT), 256>>>(
        EXA, C0, exc,  /*K=*/LQ, /*aS=*/(long)LQ*LQ, /*bS=*/LH,          /*cS=*/LH, 1);
    gemm_nn<<<dim3(2, 16, BT), 256>>>(
        SEA, C1, setc, /*K=*/SS, /*aS=*/(long)LQ*SS, /*bS=*/(long)SS*HD, /*cS=*/LH, 10);

    // 4) out = tanh([Q | exc | setc] @ W^T + b)
    gemm_nt<true><<<dim3(2, 16, BT), 256>>>(
        Q, exc, setc, W, bb, OUT,
        /*N=*/HD, /*K=*/3 * HD, /*aS=*/LH, /*bS=*/0, /*cS=*/LH, /*bDiv=*/1);
}

// round 3
// speedup vs baseline: 1.0574x; 1.0574x over previous
#include <cuda_runtime.h>

#define BT 80          // B * N_EXAMPLES
#define LQ 256         // L
#define SS 512         // S
#define HD 1024        // H
#define LH (LQ*HD)

// scratch (allocation-free rule: __device__ globals)
__device__ float g_exc[(size_t)BT*LQ*HD];
__device__ float g_setc[(size_t)BT*LQ*HD];

// ---------------------------------------------------------------------------
// NT GEMM: C[bz][m,n] = sum_k A(m,k)*B(n,k). A split into 1024-wide pieces
// (A0/A1/A2, each row stride 1024). B row-major [N,K]. Optional tanh+bias.
// Tile 128x128, K-chunk 16, 256 threads, 8x8 microtile, double-buffered.
// ---------------------------------------------------------------------------
template<bool TANH>
__global__ __launch_bounds__(256, 2)
void gemm_nt(const float* __restrict__ A0, const float* __restrict__ A1,
             const float* __restrict__ A2, const float* __restrict__ Bm,
             const float* __restrict__ bias, float* __restrict__ C,
             int N, int K, long aStride, long bStride, long cStride, int bDiv)
{
    __shared__ float As[2][16][132];
    __shared__ float Bs[2][16][132];

    const int bz = blockIdx.z;
    const int m0 = blockIdx.x * 128;
    const int n0 = blockIdx.y * 128;

    const float* Bp = Bm + (long)(bz / bDiv) * bStride + (long)n0 * K;
    float*       Cp = C  + (long)bz * cStride;
    const long aOff  = (long)bz * aStride + (long)m0 * 1024;

    const int tid   = threadIdx.x;
    const int ldRow = tid >> 2;          // 0..63
    const int ldK   = (tid & 3) << 2;    // 0,4,8,12

    const int tm = (tid >> 4) << 3;      // 0..120 step 8
    const int tn = (tid & 15) << 3;      // 0..120 step 8

    float4 ra0, ra1, rb0, rb1;

    auto ldg = [&](int k0) {
        const int p = k0 >> 10;
        const float* Ap = (p == 0 ? A0 : (p == 1 ? A1 : A2)) + aOff + (k0 & 1023);
        ra0 = *(const float4*)(Ap + (long)ldRow * 1024 + ldK);
        ra1 = *(const float4*)(Ap + (long)(ldRow + 64) * 1024 + ldK);
        const float* Bq = Bp + k0 + ldK;
        rb0 = *(const float4*)(Bq + (long)ldRow * K);
        rb1 = *(const float4*)(Bq + (long)(ldRow + 64) * K);
    };
    auto sts = [&](int buf) {
        As[buf][ldK+0][ldRow]    = ra0.x; As[buf][ldK+1][ldRow]    = ra0.y;
        As[buf][ldK+2][ldRow]    = ra0.z; As[buf][ldK+3][ldRow]    = ra0.w;
        As[buf][ldK+0][ldRow+64] = ra1.x; As[buf][ldK+1][ldRow+64] = ra1.y;
        As[buf][ldK+2][ldRow+64] = ra1.z; As[buf][ldK+3][ldRow+64] = ra1.w;
        Bs[buf][ldK+0][ldRow]    = rb0.x; Bs[buf][ldK+1][ldRow]    = rb0.y;
        Bs[buf][ldK+2][ldRow]    = rb0.z; Bs[buf][ldK+3][ldRow]    = rb0.w;
        Bs[buf][ldK+0][ldRow+64] = rb1.x; Bs[buf][ldK+1][ldRow+64] = rb1.y;
        Bs[buf][ldK+2][ldRow+64] = rb1.z; Bs[buf][ldK+3][ldRow+64] = rb1.w;
    };

    float acc[8][8];
    #pragma unroll
    for (int i = 0; i < 8; i++)
        #pragma unroll
        for (int j = 0; j < 8; j++) acc[i][j] = 0.0f;

    auto compute = [&](int buf) {
        #pragma unroll
        for (int kk = 0; kk < 16; kk++) {
            float4 a0 = *(const float4*)&As[buf][kk][tm];
            float4 a1 = *(const float4*)&As[buf][kk][tm+4];
            float4 b0 = *(const float4*)&Bs[buf][kk][tn];
            float4 b1 = *(const float4*)&Bs[buf][kk][tn+4];
            float a[8] = {a0.x,a0.y,a0.z,a0.w,a1.x,a1.y,a1.z,a1.w};
            float b[8] = {b0.x,b0.y,b0.z,b0.w,b1.x,b1.y,b1.z,b1.w};
            #pragma unroll
            for (int i = 0; i < 8; i++)
                #pragma unroll
                for (int j = 0; j < 8; j++)
                    acc[i][j] = fmaf(a[i], b[j], acc[i][j]);
        }
    };

    ldg(0); sts(0); __syncthreads();
    int buf = 0;
    for (int k0 = 16; k0 < K; k0 += 16) {
        ldg(k0);
        compute(buf);
        sts(buf ^ 1);
        __syncthreads();
        buf ^= 1;
    }
    compute(buf);

    float bv[8];
    if (TANH) {
        float4 t0 = *(const float4*)(bias + n0 + tn);
        float4 t1 = *(const float4*)(bias + n0 + tn + 4);
        bv[0]=t0.x; bv[1]=t0.y; bv[2]=t0.z; bv[3]=t0.w;
        bv[4]=t1.x; bv[5]=t1.y; bv[6]=t1.z; bv[7]=t1.w;
    }
    #pragma unroll
    for (int i = 0; i < 8; i++) {
        float4 v0, v1;
        float r[8];
        #pragma unroll
        for (int j = 0; j < 8; j++) {
            float v = acc[i][j];
            if (TANH) v = tanhf(v + bv[j]);
            r[j] = v;
        }
        v0 = make_float4(r[0], r[1], r[2], r[3]);
        v1 = make_float4(r[4], r[5], r[6], r[7]);
        float* cr = Cp + (long)(m0 + tm + i) * N + n0 + tn;
        *(float4*)cr       = v0;
        *(float4*)(cr + 4) = v1;
    }
}

// ---------------------------------------------------------------------------
// NN GEMM: C[bz][m,n] = sum_k A(m,k)*B(k,n). A row-major [M,K] (stride K),
// B row-major [K,1024]. Tile 128x128, K-chunk 16, double-buffered.
// ---------------------------------------------------------------------------
__global__ __launch_bounds__(256, 2)
void gemm_nn(const float* __restrict__ A, const float* __restrict__ Bm,
             float* __restrict__ C, int K,
             long aStride, long bStride, long cStride, int bDiv)
{
    __shared__ float As[2][16][132];
    __shared__ float Bs[2][16][132];

    const int bz = blockIdx.z;
    const int m0 = blockIdx.x * 128;
    const int n0 = blockIdx.y * 128;

    const float* Ap = A  + (long)bz * aStride + (long)m0 * K;
    const float* Bp = Bm + (long)(bz / bDiv) * bStride + n0;
    float*       Cp = C  + (long)bz * cStride;

    const int tid   = threadIdx.x;
    const int ldRow = tid >> 2;          // 0..63 (A rows)
    const int ldK   = (tid & 3) << 2;    // 0,4,8,12 (A k-cols)
    const int bRow  = tid >> 4;          // 0..15 (B k-rows)
    const int bCol  = (tid & 15) << 3;   // 0..120 step 8 (B n-cols)

    const int tm = (tid >> 4) << 3;
    const int tn = (tid & 15) << 3;

    float4 ra0, ra1, rb0, rb1;

    auto ldg = [&](int k0) {
        const float* Aq = Ap + k0 + ldK;
        ra0 = *(const float4*)(Aq + (long)ldRow * K);
        ra1 = *(const float4*)(Aq + (long)(ldRow + 64) * K);
        const float* Bq = Bp + (long)(k0 + bRow) * 1024 + bCol;
        rb0 = *(const float4*)(Bq);
        rb1 = *(const float4*)(Bq + 4);
    };
    auto sts = [&](int buf) {
        As[buf][ldK+0][ldRow]    = ra0.x; As[buf][ldK+1][ldRow]    = ra0.y;
        As[buf][ldK+2][ldRow]    = ra0.z; As[buf][ldK+3][ldRow]    = ra0.w;
        As[buf][ldK+0][ldRow+64] = ra1.x; As[buf][ldK+1][ldRow+64] = ra1.y;
        As[buf][ldK+2][ldRow+64] = ra1.z; As[buf][ldK+3][ldRow+64] = ra1.w;
        *(float4*)&Bs[buf][bRow][bCol]     = rb0;
        *(float4*)&Bs[buf][bRow][bCol + 4] = rb1;
    };

    float acc[8][8];
    #pragma unroll
    for (int i = 0; i < 8; i++)
        #pragma unroll
        for (int j = 0; j < 8; j++) acc[i][j] = 0.0f;

    auto compute = [&](int buf) {
        #pragma unroll
        for (int kk = 0; kk < 16; kk++) {
            float4 a0 = *(const float4*)&As[buf][kk][tm];
            float4 a1 = *(const float4*)&As[buf][kk][tm+4];
            float4 b0 = *(const float4*)&Bs[buf][kk][tn];
            float4 b1 = *(const float4*)&Bs[buf][kk][tn+4];
            float a[8] = {a0.x,a0.y,a0.z,a0.w,a1.x,a1.y,a1.z,a1.w};
            float b[8] = {b0.x,b0.y,b0.z,b0.w,b1.x,b1.y,b1.z,b1.w};
            #pragma unroll
            for (int i = 0; i < 8; i++)
                #pragma unroll
                for (int j = 0; j < 8; j++)
                    acc[i][j] = fmaf(a[i], b[j], acc[i][j]);
        }
    };

    ldg(0); sts(0); __syncthreads();
    int buf = 0;
    for (int k0 = 16; k0 < K; k0 += 16) {
        ldg(k0);
        compute(buf);
        sts(buf ^ 1);
        __syncthreads();
        buf ^= 1;
    }
    compute(buf);

    #pragma unroll
    for (int i = 0; i < 8; i++) {
        float* cr = Cp + (long)(m0 + tm + i) * 1024 + n0 + tn;
        *(float4*)cr       = make_float4(acc[i][0], acc[i][1], acc[i][2], acc[i][3]);
        *(float4*)(cr + 4) = make_float4(acc[i][4], acc[i][5], acc[i][6], acc[i][7]);
    }
}

// ---------------------------------------------------------------------------
// Row softmax in place. One 256-thread block per row, n in {256, 512}.
// ---------------------------------------------------------------------------
__global__ void softmax_rows(float* __restrict__ p, int n)
{
    __shared__ float red[256];
    const int tid = threadIdx.x;
    p += (long)blockIdx.x * n;

    float v0 = p[tid];
    float v1 = (n > 256) ? p[tid + 256] : -3.402823e38f;

    float m = fmaxf(v0, v1);
    red[tid] = m; __syncthreads();
    #pragma unroll
    for (int s = 128; s > 0; s >>= 1) {
        if (tid < s) red[tid] = fmaxf(red[tid], red[tid + s]);
        __syncthreads();
    }
    const float mx = red[0];
    __syncthreads();

    float e0 = __expf(v0 - mx);
    float e1 = (n > 256) ? __expf(v1 - mx) : 0.0f;
    red[tid] = e0 + e1; __syncthreads();
    #pragma unroll
    for (int s = 128; s > 0; s >>= 1) {
        if (tid < s) red[tid] += red[tid + s];
        __syncthreads();
    }
    const float inv = 1.0f / red[0];

    p[tid] = e0 * inv;
    if (n > 256) p[tid + 256] = e1 * inv;
}

// ---------------------------------------------------------------------------
extern "C" void kernel_launch(void* const* d_in, const int* in_sizes, int n_in,
                              void* d_out, int out_size)
{
    const float* Q  = (const float*)d_in[0];
    const float* C0 = (const float*)d_in[1];
    const float* C1 = (const float*)d_in[2];
    // d_in[3] = mask (unused, faithful to reference)
    const float* W  = (const float*)d_in[4];
    const float* bb = (const float*)d_in[5];

    float* OUT = (float*)d_out;
    float* EXA = OUT + (long)BT * LQ * HD;
    float* SEA = EXA + (long)BT * LQ * LQ;

    void *pexc, *psetc;
    cudaGetSymbolAddress(&pexc,  g_exc);
    cudaGetSymbolAddress(&psetc, g_setc);
    float* exc  = (float*)pexc;
    float* setc = (float*)psetc;

    // 1) logits
    gemm_nt<false><<<dim3(2, 2, BT), 256>>>(
        Q, nullptr, nullptr, C0, nullptr, EXA,
        LQ, HD, LH, LH, (long)LQ*LQ, 1);
    gemm_nt<false><<<dim3(2, 4, BT), 256>>>(
        Q, nullptr, nullptr, C1, nullptr, SEA,
        SS, HD, LH, (long)SS*HD, (long)LQ*SS, 10);

    // 2) softmax in place
    softmax_rows<<<BT * LQ, 256>>>(EXA, LQ);
    softmax_rows<<<BT * LQ, 256>>>(SEA, SS);

    // 3) attn @ V
    gemm_nn<<<dim3(2, 8, BT), 256>>>(
        EXA, C0, exc,  LQ, (long)LQ*LQ, LH, LH, 1);
    gemm_nn<<<dim3(2, 8, BT), 256>>>(
        SEA, C1, setc, SS, (long)LQ*SS, (long)SS*HD, LH, 10);

    // 4) out = tanh([Q | exc | setc] @ W^T + b)
    gemm_nt<true><<<dim3(2, 8, BT), 256>>>(
        Q, exc, setc, W, bb, OUT,
        HD, 3 * HD, LH, 0, LH, 1);
}

// round 5
// speedup vs baseline: 1.4761x; 1.3960x over previous
#include <cuda_runtime.h>
#include <cuda_bf16.h>
#include <cstdint>

#define BT 80
#define LQ 256
#define SS 512
#define HD 1024
#define LH (LQ*HD)

// ---------------- scratch (device globals; allocation-free rule) -----------
__device__ __nv_bfloat16 g_qh[(size_t)BT*LQ*HD];
__device__ __nv_bfloat16 g_ql[(size_t)BT*LQ*HD];
__device__ __nv_bfloat16 g_ech[(size_t)BT*LQ*HD];
__device__ __nv_bfloat16 g_ecl[(size_t)BT*LQ*HD];
__device__ __nv_bfloat16 g_sch[(size_t)BT*LQ*HD];
__device__ __nv_bfloat16 g_scl[(size_t)BT*LQ*HD];
__device__ __nv_bfloat16 g_wh[(size_t)HD*3*HD];
__device__ __nv_bfloat16 g_wl[(size_t)HD*3*HD];

// ---------------- portable PTX helpers (sm_80-era; safe on sm_103) ---------
__device__ __forceinline__ uint32_t smem_u32(const void* p) {
    uint32_t a;
    asm("{ .reg .u64 t; cvta.to.shared.u64 t, %1; cvt.u32.u64 %0, t; }" : "=r"(a) : "l"(p));
    return a;
}
__device__ __forceinline__ void cp16(uint32_t dst, const void* src) {
    asm volatile("cp.async.cg.shared.global [%0], [%1], 16;" :: "r"(dst), "l"(src));
}
#define CP_COMMIT() asm volatile("cp.async.commit_group;" ::: "memory")
#define CP_WAIT1()  asm volatile("cp.async.wait_group 1;" ::: "memory")
#define CP_WAIT0()  asm volatile("cp.async.wait_group 0;" ::: "memory")

__device__ __forceinline__ void ldm4(uint32_t* r, uint32_t addr) {
    asm volatile("ldmatrix.sync.aligned.m8n8.x4.shared.b16 {%0,%1,%2,%3}, [%4];"
        : "=r"(r[0]), "=r"(r[1]), "=r"(r[2]), "=r"(r[3]) : "r"(addr));
}
__device__ __forceinline__ void mma16816(float* c, const uint32_t* a,
                                         uint32_t b0, uint32_t b1) {
    asm volatile(
        "mma.sync.aligned.m16n8k16.row.col.f32.bf16.bf16.f32 "
        "{%0,%1,%2,%3}, {%4,%5,%6,%7}, {%8,%9}, {%0,%1,%2,%3};"
        : "+f"(c[0]), "+f"(c[1]), "+f"(c[2]), "+f"(c[3])
        : "r"(a[0]), "r"(a[1]), "r"(a[2]), "r"(a[3]), "r"(b0), "r"(b1));
}

// ---------------------------------------------------------------------------
// fp32 -> bf16 hi/lo split (4 elems/thread)
// ---------------------------------------------------------------------------
__global__ void split_bf16(const float* __restrict__ x,
                           __nv_bfloat16* __restrict__ h,
                           __nv_bfloat16* __restrict__ l)
{
    long i = ((long)blockIdx.x * blockDim.x + threadIdx.x) * 4;
    float4 v = *(const float4*)(x + i);
    float vv[4] = {v.x, v.y, v.z, v.w};
    __nv_bfloat16 hh[4], ll[4];
    #pragma unroll
    for (int j = 0; j < 4; j++) {
        hh[j] = __float2bfloat16(vv[j]);
        ll[j] = __float2bfloat16(vv[j] - __bfloat162float(hh[j]));
    }
    *(__nv_bfloat162*)(h + i)     = __nv_bfloat162(hh[0], hh[1]);
    *(__nv_bfloat162*)(h + i + 2) = __nv_bfloat162(hh[2], hh[3]);
    *(__nv_bfloat162*)(l + i)     = __nv_bfloat162(ll[0], ll[1]);
    *(__nv_bfloat162*)(l + i + 2) = __nv_bfloat162(ll[2], ll[3]);
}

// ---------------------------------------------------------------------------
// NT GEMM (fp32): logits. C[bz][m,n] = sum_k A(m,k)*B(n,k).
// Tile 128x128, K-chunk 16, double-buffered.
// ---------------------------------------------------------------------------
__global__ __launch_bounds__(256, 2)
void gemm_nt(const float* __restrict__ A, const float* __restrict__ Bm,
             float* __restrict__ C,
             int N, int K, long aStride, long bStride, long cStride, int bDiv)
{
    __shared__ float As[2][16][132];
    __shared__ float Bs[2][16][132];

    const int bz = blockIdx.z;
    const int m0 = blockIdx.x * 128;
    const int n0 = blockIdx.y * 128;

    const float* Bp = Bm + (long)(bz / bDiv) * bStride + (long)n0 * K;
    float*       Cp = C  + (long)bz * cStride;
    const float* Ap0 = A + (long)bz * aStride + (long)m0 * 1024;

    const int tid   = threadIdx.x;
    const int ldRow = tid >> 2;
    const int ldK   = (tid & 3) << 2;
    const int tm = (tid >> 4) << 3;
    const int tn = (tid & 15) << 3;

    float4 ra0, ra1, rb0, rb1;
    auto ldg = [&](int k0) {
        const float* Ap = Ap0 + k0;
        ra0 = *(const float4*)(Ap + (long)ldRow * 1024 + ldK);
        ra1 = *(const float4*)(Ap + (long)(ldRow + 64) * 1024 + ldK);
        const float* Bq = Bp + k0 + ldK;
        rb0 = *(const float4*)(Bq + (long)ldRow * K);
        rb1 = *(const float4*)(Bq + (long)(ldRow + 64) * K);
    };
    auto sts = [&](int buf) {
        As[buf][ldK+0][ldRow]    = ra0.x; As[buf][ldK+1][ldRow]    = ra0.y;
        As[buf][ldK+2][ldRow]    = ra0.z; As[buf][ldK+3][ldRow]    = ra0.w;
        As[buf][ldK+0][ldRow+64] = ra1.x; As[buf][ldK+1][ldRow+64] = ra1.y;
        As[buf][ldK+2][ldRow+64] = ra1.z; As[buf][ldK+3][ldRow+64] = ra1.w;
        Bs[buf][ldK+0][ldRow]    = rb0.x; Bs[buf][ldK+1][ldRow]    = rb0.y;
        Bs[buf][ldK+2][ldRow]    = rb0.z; Bs[buf][ldK+3][ldRow]    = rb0.w;
        Bs[buf][ldK+0][ldRow+64] = rb1.x; Bs[buf][ldK+1][ldRow+64] = rb1.y;
        Bs[buf][ldK+2][ldRow+64] = rb1.z; Bs[buf][ldK+3][ldRow+64] = rb1.w;
    };

    float acc[8][8];
    #pragma unroll
    for (int i = 0; i < 8; i++)
        #pragma unroll
        for (int j = 0; j < 8; j++) acc[i][j] = 0.0f;

    auto compute = [&](int buf) {
        #pragma unroll
        for (int kk = 0; kk < 16; kk++) {
            float4 a0 = *(const float4*)&As[buf][kk][tm];
            float4 a1 = *(const float4*)&As[buf][kk][tm+4];
            float4 b0 = *(const float4*)&Bs[buf][kk][tn];
            float4 b1 = *(const float4*)&Bs[buf][kk][tn+4];
            float a[8] = {a0.x,a0.y,a0.z,a0.w,a1.x,a1.y,a1.z,a1.w};
            float b[8] = {b0.x,b0.y,b0.z,b0.w,b1.x,b1.y,b1.z,b1.w};
            #pragma unroll
            for (int i = 0; i < 8; i++)
                #pragma unroll
                for (int j = 0; j < 8; j++)
                    acc[i][j] = fmaf(a[i], b[j], acc[i][j]);
        }
    };

    ldg(0); sts(0); __syncthreads();
    int buf = 0;
    for (int k0 = 16; k0 < K; k0 += 16) {
        ldg(k0); compute(buf); sts(buf ^ 1);
        __syncthreads(); buf ^= 1;
    }
    compute(buf);

    #pragma unroll
    for (int i = 0; i < 8; i++) {
        float* cr = Cp + (long)(m0 + tm + i) * N + n0 + tn;
        *(float4*)cr       = make_float4(acc[i][0],acc[i][1],acc[i][2],acc[i][3]);
        *(float4*)(cr + 4) = make_float4(acc[i][4],acc[i][5],acc[i][6],acc[i][7]);
    }
}

// ---------------------------------------------------------------------------
// NN GEMM (fp32): attn @ V.  Emits bf16 hi/lo split directly.
// ---------------------------------------------------------------------------
__global__ __launch_bounds__(256, 2)
void gemm_nn(const float* __restrict__ A, const float* __restrict__ Bm,
             __nv_bfloat16* __restrict__ Ch, __nv_bfloat16* __restrict__ Cl,
             int K, long aStride, long bStride, long cStride, int bDiv)
{
    __shared__ float As[2][16][132];
    __shared__ float Bs[2][16][132];

    const int bz = blockIdx.z;
    const int m0 = blockIdx.x * 128;
    const int n0 = blockIdx.y * 128;

    const float* Ap = A  + (long)bz * aStride + (long)m0 * K;
    const float* Bp = Bm + (long)(bz / bDiv) * bStride + n0;

    const int tid   = threadIdx.x;
    const int ldRow = tid >> 2;
    const int ldK   = (tid & 3) << 2;
    const int bRow  = tid >> 4;
    const int bCol  = (tid & 15) << 3;
    const int tm = (tid >> 4) << 3;
    const int tn = (tid & 15) << 3;

    float4 ra0, ra1, rb0, rb1;
    auto ldg = [&](int k0) {
        const float* Aq = Ap + k0 + ldK;
        ra0 = *(const float4*)(Aq + (long)ldRow * K);
        ra1 = *(const float4*)(Aq + (long)(ldRow + 64) * K);
        const float* Bq = Bp + (long)(k0 + bRow) * 1024 + bCol;
        rb0 = *(const float4*)(Bq);
        rb1 = *(const float4*)(Bq + 4);
    };
    auto sts = [&](int buf) {
        As[buf][ldK+0][ldRow]    = ra0.x; As[buf][ldK+1][ldRow]    = ra0.y;
        As[buf][ldK+2][ldRow]    = ra0.z; As[buf][ldK+3][ldRow]    = ra0.w;
        As[buf][ldK+0][ldRow+64] = ra1.x; As[buf][ldK+1][ldRow+64] = ra1.y;
        As[buf][ldK+2][ldRow+64] = ra1.z; As[buf][ldK+3][ldRow+64] = ra1.w;
        *(float4*)&Bs[buf][bRow][bCol]     = rb0;
        *(float4*)&Bs[buf][bRow][bCol + 4] = rb1;
    };

    float acc[8][8];
    #pragma unroll
    for (int i = 0; i < 8; i++)
        #pragma unroll
        for (int j = 0; j < 8; j++) acc[i][j] = 0.0f;

    auto compute = [&](int buf) {
        #pragma unroll
        for (int kk = 0; kk < 16; kk++) {
            float4 a0 = *(const float4*)&As[buf][kk][tm];
            float4 a1 = *(const float4*)&As[buf][kk][tm+4];
            float4 b0 = *(const float4*)&Bs[buf][kk][tn];
            float4 b1 = *(const float4*)&Bs[buf][kk][tn+4];
            float a[8] = {a0.x,a0.y,a0.z,a0.w,a1.x,a1.y,a1.z,a1.w};
            float b[8] = {b0.x,b0.y,b0.z,b0.w,b1.x,b1.y,b1.z,b1.w};
            #pragma unroll
            for (int i = 0; i < 8; i++)
                #pragma unroll
                for (int j = 0; j < 8; j++)
                    acc[i][j] = fmaf(a[i], b[j], acc[i][j]);
        }
    };

    ldg(0); sts(0); __syncthreads();
    int buf = 0;
    for (int k0 = 16; k0 < K; k0 += 16) {
        ldg(k0); compute(buf); sts(buf ^ 1);
        __syncthreads(); buf ^= 1;
    }
    compute(buf);

    const long base = (long)bz * cStride;
    #pragma unroll
    for (int i = 0; i < 8; i++) {
        long off = base + (long)(m0 + tm + i) * 1024 + n0 + tn;
        __nv_bfloat16 hh[8], ll[8];
        #pragma unroll
        for (int j = 0; j < 8; j++) {
            float v = acc[i][j];
            hh[j] = __float2bfloat16(v);
            ll[j] = __float2bfloat16(v - __bfloat162float(hh[j]));
        }
        #pragma unroll
        for (int j = 0; j < 8; j += 2) {
            *(__nv_bfloat162*)(Ch + off + j) = __nv_bfloat162(hh[j], hh[j+1]);
            *(__nv_bfloat162*)(Cl + off + j) = __nv_bfloat162(ll[j], ll[j+1]);
        }
    }
}

// ---------------------------------------------------------------------------
// Row softmax in place.
// ---------------------------------------------------------------------------
__global__ void softmax_rows(float* __restrict__ p, int n)
{
    __shared__ float red[256];
    const int tid = threadIdx.x;
    p += (long)blockIdx.x * n;

    float v0 = p[tid];
    float v1 = (n > 256) ? p[tid + 256] : -3.402823e38f;

    red[tid] = fmaxf(v0, v1); __syncthreads();
    #pragma unroll
    for (int s = 128; s > 0; s >>= 1) {
        if (tid < s) red[tid] = fmaxf(red[tid], red[tid + s]);
        __syncthreads();
    }
    const float mx = red[0];
    __syncthreads();

    float e0 = __expf(v0 - mx);
    float e1 = (n > 256) ? __expf(v1 - mx) : 0.0f;
    red[tid] = e0 + e1; __syncthreads();
    #pragma unroll
    for (int s = 128; s > 0; s >>= 1) {
        if (tid < s) red[tid] += red[tid + s];
        __syncthreads();
    }
    const float inv = 1.0f / red[0];

    p[tid] = e0 * inv;
    if (n > 256) p[tid + 256] = e1 * inv;
}

// ---------------------------------------------------------------------------
// Final projection: bf16 2-split (3 products) on mma.sync tensor cores.
// out = tanh([Q|exc|setc] @ W^T + b).  M=20480, N=1024, K=3072.
// CTA 128x128, K-chunk 32, 2-stage cp.async pipeline.
// smem per stage: 4 tiles (Ah, Al, Bh, Bl) of 128 x 40(pad) bf16 = 10240 B.
// ---------------------------------------------------------------------------
#define TILE_B   10240                 // 128 * 40 * 2
#define OFF_AH   0
#define OFF_AL   (TILE_B)
#define OFF_BH   (2*TILE_B)
#define OFF_BL   (3*TILE_B)
#define STAGE_B  (4*TILE_B)            // 40960
#define FG_SMEM  (2*STAGE_B)           // 81920
#define NCH      96                    // 3072 / 32

__global__ __launch_bounds__(256)
void final_gemm(const __nv_bfloat16* __restrict__ qh, const __nv_bfloat16* __restrict__ ql,
                const __nv_bfloat16* __restrict__ ech, const __nv_bfloat16* __restrict__ ecl,
                const __nv_bfloat16* __restrict__ sch, const __nv_bfloat16* __restrict__ scl,
                const __nv_bfloat16* __restrict__ wh, const __nv_bfloat16* __restrict__ wl,
                const float* __restrict__ bias, float* __restrict__ out)
{
    extern __shared__ char smem[];
    const uint32_t sb = smem_u32(smem);
    const int tid  = threadIdx.x;
    const int wid  = tid >> 5;
    const int lane = tid & 31;
    const long m0 = (long)blockIdx.y * 128;
    const int  n0 = blockIdx.x * 128;

    const int wm = (wid & 3) * 32;       // warp m offset in CTA tile
    const int wn = (wid >> 2) * 64;      // warp n offset

    // ldmatrix per-lane base offsets (elements): row = laneR, col = laneC8
    const int laneR  = lane & 15;
    const int laneC8 = (lane >> 4) << 3;
    const uint32_t aRow = (uint32_t)((wm + laneR) * 40 + laneC8) * 2;
    const uint32_t bRow = (uint32_t)((wn + laneR) * 40 + laneC8) * 2;

    // cp.async per-thread slots: 2 x (row, seg)
    const int r0 = tid >> 2,  s0 = (tid & 3);
    const int r1 = (tid + 256) >> 2, s1 = s0;   // idx+256: row+64, same seg

    auto issue = [&](int c) {
        const int k0  = c << 5;
        const int pc  = k0 >> 10;
        const __nv_bfloat16* Ah = pc == 0 ? qh : (pc == 1 ? ech : sch);
        const __nv_bfloat16* Al = pc == 0 ? ql : (pc == 1 ? ecl : scl);
        const int kin = k0 & 1023;
        const uint32_t st = sb + (uint32_t)(c & 1) * STAGE_B;

        uint32_t so0 = (uint32_t)(r0 * 40 + s0 * 8) * 2;
        uint32_t so1 = (uint32_t)(r1 * 40 + s1 * 8) * 2;
        long ao0 = (m0 + r0) * 1024 + kin + s0 * 8;
        long ao1 = (m0 + r1) * 1024 + kin + s1 * 8;
        long bo0 = (long)(n0 + r0) * 3072 + k0 + s0 * 8;
        long bo1 = (long)(n0 + r1) * 3072 + k0 + s1 * 8;

        cp16(st + OFF_AH + so0, Ah + ao0);
        cp16(st + OFF_AH + so1, Ah + ao1);
        cp16(st + OFF_AL + so0, Al + ao0);
        cp16(st + OFF_AL + so1, Al + ao1);
        cp16(st + OFF_BH + so0, wh + bo0);
        cp16(st + OFF_BH + so1, wh + bo1);
        cp16(st + OFF_BL + so0, wl + bo0);
        cp16(st + OFF_BL + so1, wl + bo1);
        CP_COMMIT();
    };

    float acc[2][8][4];
    #pragma unroll
    for (int i = 0; i < 2; i++)
        #pragma unroll
        for (int j = 0; j < 8; j++)
            #pragma unroll
            for (int k = 0; k < 4; k++) acc[i][j][k] = 0.0f;

    issue(0);

    for (int c = 0; c < NCH; c++) {
        if (c + 1 < NCH) { issue(c + 1); CP_WAIT1(); }
        else             { CP_WAIT0(); }
        __syncthreads();

        const uint32_t st = sb + (uint32_t)(c & 1) * STAGE_B;
        #pragma unroll
        for (int ks = 0; ks < 2; ks++) {
            const uint32_t kOff = (uint32_t)(ks * 16) * 2;
            uint32_t af[2][4], bh[4][4], bl[4][4];
            #pragma unroll
            for (int mt = 0; mt < 2; mt++)
                ldm4(af[mt], st + OFF_AH + aRow + (uint32_t)(mt * 640) * 2 + kOff);
            #pragma unroll
            for (int np = 0; np < 4; np++) {
                ldm4(bh[np], st + OFF_BH + bRow + (uint32_t)(np * 640) * 2 + kOff);
                ldm4(bl[np], st + OFF_BL + bRow + (uint32_t)(np * 640) * 2 + kOff);
            }
            // hh + hl products
            #pragma unroll
            for (int mt = 0; mt < 2; mt++)
                #pragma unroll
                for (int nt = 0; nt < 8; nt++) {
                    const int np = nt >> 1, sel = nt & 1;
                    mma16816(acc[mt][nt], af[mt], bh[np][sel], bh[np][sel + 2]);
                    mma16816(acc[mt][nt], af[mt], bl[np][sel], bl[np][sel + 2]);
                }
            // lh product (reload A-lo into same regs)
            #pragma unroll
            for (int mt = 0; mt < 2; mt++)
                ldm4(af[mt], st + OFF_AL + aRow + (uint32_t)(mt * 640) * 2 + kOff);
            #pragma unroll
            for (int mt = 0; mt < 2; mt++)
                #pragma unroll
                for (int nt = 0; nt < 8; nt++) {
                    const int np = nt >> 1, sel = nt & 1;
                    mma16816(acc[mt][nt], af[mt], bh[np][sel], bh[np][sel + 2]);
                }
        }
        __syncthreads();
    }

    // epilogue: tanh(acc + bias) -> out
    #pragma unroll
    for (int mt = 0; mt < 2; mt++) {
        const long gm = m0 + wm + mt * 16 + (lane >> 2);
        #pragma unroll
        for (int nt = 0; nt < 8; nt++) {
            const int gn = n0 + wn + nt * 8 + ((lane & 3) << 1);
            const float b0 = bias[gn], b1 = bias[gn + 1];
            float2 v0 = make_float2(tanhf(acc[mt][nt][0] + b0), tanhf(acc[mt][nt][1] + b1));
            float2 v1 = make_float2(tanhf(acc[mt][nt][2] + b0), tanhf(acc[mt][nt][3] + b1));
            *(float2*)(out + gm * 1024 + gn)       = v0;
            *(float2*)(out + (gm + 8) * 1024 + gn) = v1;
        }
    }
}

// ---------------------------------------------------------------------------
extern "C" void kernel_launch(void* const* d_in, const int* in_sizes, int n_in,
                              void* d_out, int out_size)
{
    const float* Q  = (const float*)d_in[0];
    const float* C0 = (const float*)d_in[1];
    const float* C1 = (const float*)d_in[2];
    // d_in[3] = mask (unused, faithful to reference)
    const float* W  = (const float*)d_in[4];
    const float* bb = (const float*)d_in[5];

    float* OUT = (float*)d_out;
    float* EXA = OUT + (long)BT * LQ * HD;
    float* SEA = EXA + (long)BT * LQ * LQ;

    void *p0,*p1,*p2,*p3,*p4,*p5,*p6,*p7;
    cudaGetSymbolAddress(&p0, g_qh);  cudaGetSymbolAddress(&p1, g_ql);
    cudaGetSymbolAddress(&p2, g_ech); cudaGetSymbolAddress(&p3, g_ecl);
    cudaGetSymbolAddress(&p4, g_sch); cudaGetSymbolAddress(&p5, g_scl);
    cudaGetSymbolAddress(&p6, g_wh);  cudaGetSymbolAddress(&p7, g_wl);
    __nv_bfloat16 *qh=(__nv_bfloat16*)p0, *ql=(__nv_bfloat16*)p1;
    __nv_bfloat16 *ech=(__nv_bfloat16*)p2, *ecl=(__nv_bfloat16*)p3;
    __nv_bfloat16 *sch=(__nv_bfloat16*)p4, *scl=(__nv_bfloat16*)p5;
    __nv_bfloat16 *wh=(__nv_bfloat16*)p6, *wl=(__nv_bfloat16*)p7;

    static int attr_set = 0;
    cudaFuncSetAttribute(final_gemm, cudaFuncAttributeMaxDynamicSharedMemorySize, FG_SMEM);
    (void)attr_set;

    // splits (Q, W)
    split_bf16<<<(BT*LQ*HD)/1024, 256>>>(Q, qh, ql);
    split_bf16<<<(HD*3*HD)/1024, 256>>>(W, wh, wl);

    // logits
    gemm_nt<<<dim3(2, 2, BT), 256>>>(Q, C0, EXA, LQ, HD, LH, LH, (long)LQ*LQ, 1);
    gemm_nt<<<dim3(2, 4, BT), 256>>>(Q, C1, SEA, SS, HD, LH, (long)SS*HD, (long)LQ*SS, 10);

    // softmax in place
    softmax_rows<<<BT * LQ, 256>>>(EXA, LQ);
    softmax_rows<<<BT * LQ, 256>>>(SEA, SS);

    // attn @ V  (emit bf16 hi/lo)
    gemm_nn<<<dim3(2, 8, BT), 256>>>(EXA, C0, ech, ecl, LQ, (long)LQ*LQ, LH, LH, 1);
    gemm_nn<<<dim3(2, 8, BT), 256>>>(SEA, C1, sch, scl, SS, (long)LQ*SS, (long)SS*HD, LH, 10);

    // final projection on tensor cores (mma.sync bf16 2-split)
    final_gemm<<<dim3(8, 160), 256, FG_SMEM>>>(qh, ql, ech, ecl, sch, scl, wh, wl, bb, OUT);
}

// round 6
// speedup vs baseline: 1.8713x; 1.2677x over previous
#include <cuda_runtime.h>
#include <cuda_bf16.h>
#include <cstdint>

#define BT 80
#define LQ 256
#define SS 512
#define HD 1024
#define LH (LQ*HD)

// ---------------- scratch (device globals; allocation-free rule) -----------
__device__ __nv_bfloat16 g_qh[(size_t)BT*LQ*HD],  g_ql[(size_t)BT*LQ*HD];
__device__ __nv_bfloat16 g_wh[(size_t)HD*3*HD],   g_wl[(size_t)HD*3*HD];
__device__ __nv_bfloat16 g_c0h[(size_t)BT*LQ*HD], g_c0l[(size_t)BT*LQ*HD];
__device__ __nv_bfloat16 g_c1h[(size_t)8*SS*HD],  g_c1l[(size_t)8*SS*HD];
__device__ __nv_bfloat16 g_t0h[(size_t)BT*HD*LQ], g_t0l[(size_t)BT*HD*LQ];
__device__ __nv_bfloat16 g_t1h[(size_t)8*HD*SS],  g_t1l[(size_t)8*HD*SS];
__device__ __nv_bfloat16 g_peh[(size_t)BT*LQ*LQ], g_pel[(size_t)BT*LQ*LQ];
__device__ __nv_bfloat16 g_psh[(size_t)BT*LQ*SS], g_psl[(size_t)BT*LQ*SS];
__device__ __nv_bfloat16 g_ech[(size_t)BT*LQ*HD], g_ecl[(size_t)BT*LQ*HD];
__device__ __nv_bfloat16 g_sch[(size_t)BT*LQ*HD], g_scl[(size_t)BT*LQ*HD];

// ---------------- portable PTX helpers -------------------------------------
__device__ __forceinline__ uint32_t smem_u32(const void* p) {
    uint32_t a;
    asm("{ .reg .u64 t; cvta.to.shared.u64 t, %1; cvt.u32.u64 %0, t; }" : "=r"(a) : "l"(p));
    return a;
}
__device__ __forceinline__ void cp16(uint32_t dst, const void* src) {
    asm volatile("cp.async.cg.shared.global [%0], [%1], 16;" :: "r"(dst), "l"(src));
}
#define CP_COMMIT() asm volatile("cp.async.commit_group;" ::: "memory")
#define CP_WAIT1()  asm volatile("cp.async.wait_group 1;" ::: "memory")
#define CP_WAIT0()  asm volatile("cp.async.wait_group 0;" ::: "memory")

__device__ __forceinline__ void ldm4(uint32_t* r, uint32_t addr) {
    asm volatile("ldmatrix.sync.aligned.m8n8.x4.shared.b16 {%0,%1,%2,%3}, [%4];"
        : "=r"(r[0]), "=r"(r[1]), "=r"(r[2]), "=r"(r[3]) : "r"(addr));
}
__device__ __forceinline__ void mma16816(float* c, const uint32_t* a,
                                         uint32_t b0, uint32_t b1) {
    asm volatile(
        "mma.sync.aligned.m16n8k16.row.col.f32.bf16.bf16.f32 "
        "{%0,%1,%2,%3}, {%4,%5,%6,%7}, {%8,%9}, {%0,%1,%2,%3};"
        : "+f"(c[0]), "+f"(c[1]), "+f"(c[2]), "+f"(c[3])
        : "r"(a[0]), "r"(a[1]), "r"(a[2]), "r"(a[3]), "r"(b0), "r"(b1));
}
__device__ __forceinline__ void split1(float v, __nv_bfloat16& h, __nv_bfloat16& l) {
    h = __float2bfloat16(v);
    l = __float2bfloat16(v - __bfloat162float(h));
}

// ---------------------------------------------------------------------------
// plain fp32 -> bf16 hi/lo split (4 elems/thread)
// ---------------------------------------------------------------------------
__global__ void split_bf16(const float* __restrict__ x,
                           __nv_bfloat16* __restrict__ h,
                           __nv_bfloat16* __restrict__ l)
{
    long i = ((long)blockIdx.x * blockDim.x + threadIdx.x) * 4;
    float4 v = *(const float4*)(x + i);
    float vv[4] = {v.x, v.y, v.z, v.w};
    __nv_bfloat16 hh[4], ll[4];
    #pragma unroll
    for (int j = 0; j < 4; j++) split1(vv[j], hh[j], ll[j]);
    *(__nv_bfloat162*)(h + i)     = __nv_bfloat162(hh[0], hh[1]);
    *(__nv_bfloat162*)(h + i + 2) = __nv_bfloat162(hh[2], hh[3]);
    *(__nv_bfloat162*)(l + i)     = __nv_bfloat162(ll[0], ll[1]);
    *(__nv_bfloat162*)(l + i + 2) = __nv_bfloat162(ll[2], ll[3]);
}

// ---------------------------------------------------------------------------
// transposed split: x [B][S][1024] -> h/l [B][1024][S]
// block (32,8), grid (S/32, 32, B)
// ---------------------------------------------------------------------------
__global__ void tsplit_bf16(const float* __restrict__ x,
                            __nv_bfloat16* __restrict__ h,
                            __nv_bfloat16* __restrict__ l, int S)
{
    __shared__ float t[32][33];
    const int b  = blockIdx.z;
    const int s0 = blockIdx.x * 32;
    const int d0 = blockIdx.y * 32;
    const int tx = threadIdx.x, ty = threadIdx.y;

    const float* xp = x + (long)b * S * 1024;
    #pragma unroll
    for (int r = 0; r < 4; r++) {
        int s = ty + r * 8;
        t[s][tx] = xp[(long)(s0 + s) * 1024 + d0 + tx];
    }
    __syncthreads();
    const long ob = (long)b * 1024 * S;
    #pragma unroll
    for (int r = 0; r < 4; r++) {
        int d = ty + r * 8;
        float v = t[tx][d];
        __nv_bfloat16 hh, ll;
        split1(v, hh, ll);
        long off = ob + (long)(d0 + d) * S + s0 + tx;
        h[off] = hh; l[off] = ll;
    }
}

// ---------------------------------------------------------------------------
// Row softmax in place + bf16 hi/lo prob splits.
// ---------------------------------------------------------------------------
__global__ void softmax_rows(float* __restrict__ p,
                             __nv_bfloat16* __restrict__ ph,
                             __nv_bfloat16* __restrict__ pl, int n)
{
    __shared__ float red[256];
    const int tid = threadIdx.x;
    const long base = (long)blockIdx.x * n;
    p += base; ph += base; pl += base;

    float v0 = p[tid];
    float v1 = (n > 256) ? p[tid + 256] : -3.402823e38f;

    red[tid] = fmaxf(v0, v1); __syncthreads();
    #pragma unroll
    for (int s = 128; s > 0; s >>= 1) {
        if (tid < s) red[tid] = fmaxf(red[tid], red[tid + s]);
        __syncthreads();
    }
    const float mx = red[0];
    __syncthreads();

    float e0 = __expf(v0 - mx);
    float e1 = (n > 256) ? __expf(v1 - mx) : 0.0f;
    red[tid] = e0 + e1; __syncthreads();
    #pragma unroll
    for (int s = 128; s > 0; s >>= 1) {
        if (tid < s) red[tid] += red[tid + s];
        __syncthreads();
    }
    const float inv = 1.0f / red[0];

    float p0 = e0 * inv;
    __nv_bfloat16 hh, ll;
    p[tid] = p0;
    split1(p0, hh, ll); ph[tid] = hh; pl[tid] = ll;
    if (n > 256) {
        float p1 = e1 * inv;
        p[tid + 256] = p1;
        split1(p1, hh, ll); ph[tid + 256] = hh; pl[tid + 256] = ll;
    }
}

// ---------------------------------------------------------------------------
// Shared tile geometry for all mma kernels
// ---------------------------------------------------------------------------
#define TILE_B   10240                 // 128 rows * 40 bf16 * 2B
#define OFF_AH   0
#define OFF_AL   (TILE_B)
#define OFF_BH   (2*TILE_B)
#define OFF_BL   (3*TILE_B)
#define STAGE_B  (4*TILE_B)            // 40960
#define MM_SMEM  (3*STAGE_B)           // 122880, 3-stage

// ---------------------------------------------------------------------------
// Generic NT mma GEMM (bf16 2-split, 3 products, fp32 acc).
// C[bz][m,n] = sum_k A(m,k)*B(n,k);  M=256/batch, CTA 128x128, K-chunk 32.
// MODE 0: store fp32 (logits).  MODE 1: store bf16 hi/lo split (PV output,
// row stride 1024 = N).
// ---------------------------------------------------------------------------
template<int MODE>
__global__ __launch_bounds__(256)
void mma_nt(const __nv_bfloat16* __restrict__ Ah, const __nv_bfloat16* __restrict__ Al,
            const __nv_bfloat16* __restrict__ Bh, const __nv_bfloat16* __restrict__ Bl,
            float* __restrict__ Cf,
            __nv_bfloat16* __restrict__ Ch, __nv_bfloat16* __restrict__ Cl,
            int K, int N, long bBatch, int bDiv)
{
    extern __shared__ char smem[];
    const uint32_t sb = smem_u32(smem);
    const int tid  = threadIdx.x;
    const int wid  = tid >> 5;
    const int lane = tid & 31;
    const int bz = blockIdx.z;
    const int m0 = blockIdx.y * 128;
    const int n0 = blockIdx.x * 128;
    const int NCH = K >> 5;

    const long aBase = (long)bz * 256 * K + (long)m0 * K;
    const long bBase = (long)(bz / bDiv) * bBatch + (long)n0 * K;

    const int wm = (wid & 3) * 32;
    const int wn = (wid >> 2) * 64;
    const int laneR  = lane & 15;
    const int laneC8 = (lane >> 4) << 3;
    const uint32_t aRow = (uint32_t)((wm + laneR) * 40 + laneC8) * 2;
    const uint32_t bRow = (uint32_t)((wn + laneR) * 40 + laneC8) * 2;

    const int r0 = tid >> 2, s0 = tid & 3;
    const int r1 = r0 + 64;

    auto issue = [&](int c) {
        const int k0 = c << 5;
        const uint32_t st = sb + (uint32_t)(c % 3) * STAGE_B;
        uint32_t so0 = (uint32_t)(r0 * 40 + s0 * 8) * 2;
        uint32_t so1 = (uint32_t)(r1 * 40 + s0 * 8) * 2;
        long ao0 = aBase + (long)r0 * K + k0 + s0 * 8;
        long ao1 = aBase + (long)r1 * K + k0 + s0 * 8;
        long bo0 = bBase + (long)r0 * K + k0 + s0 * 8;
        long bo1 = bBase + (long)r1 * K + k0 + s0 * 8;
        cp16(st + OFF_AH + so0, Ah + ao0);
        cp16(st + OFF_AH + so1, Ah + ao1);
        cp16(st + OFF_AL + so0, Al + ao0);
        cp16(st + OFF_AL + so1, Al + ao1);
        cp16(st + OFF_BH + so0, Bh + bo0);
        cp16(st + OFF_BH + so1, Bh + bo1);
        cp16(st + OFF_BL + so0, Bl + bo0);
        cp16(st + OFF_BL + so1, Bl + bo1);
        CP_COMMIT();
    };

    float acc[2][8][4];
    #pragma unroll
    for (int i = 0; i < 2; i++)
        #pragma unroll
        for (int j = 0; j < 8; j++)
            #pragma unroll
            for (int k = 0; k < 4; k++) acc[i][j][k] = 0.0f;

    issue(0); issue(1);

    for (int c = 0; c < NCH; c++) {
        if (c + 1 < NCH) CP_WAIT1(); else CP_WAIT0();
        __syncthreads();
        if (c + 2 < NCH) issue(c + 2);

        const uint32_t st = sb + (uint32_t)(c % 3) * STAGE_B;
        #pragma unroll
        for (int ks = 0; ks < 2; ks++) {
            const uint32_t kOff = (uint32_t)(ks * 16) * 2;
            uint32_t af[2][4], bh[4][4], bl[4][4];
            #pragma unroll
            for (int mt = 0; mt < 2; mt++)
                ldm4(af[mt], st + OFF_AH + aRow + (uint32_t)(mt * 640) * 2 + kOff);
            #pragma unroll
            for (int np = 0; np < 4; np++) {
                ldm4(bh[np], st + OFF_BH + bRow + (uint32_t)(np * 640) * 2 + kOff);
                ldm4(bl[np], st + OFF_BL + bRow + (uint32_t)(np * 640) * 2 + kOff);
            }
            #pragma unroll
            for (int mt = 0; mt < 2; mt++)
                #pragma unroll
                for (int nt = 0; nt < 8; nt++) {
                    const int np = nt >> 1, sel = nt & 1;
                    mma16816(acc[mt][nt], af[mt], bh[np][sel], bh[np][sel + 2]);
                    mma16816(acc[mt][nt], af[mt], bl[np][sel], bl[np][sel + 2]);
                }
            #pragma unroll
            for (int mt = 0; mt < 2; mt++)
                ldm4(af[mt], st + OFF_AL + aRow + (uint32_t)(mt * 640) * 2 + kOff);
            #pragma unroll
            for (int mt = 0; mt < 2; mt++)
                #pragma unroll
                for (int nt = 0; nt < 8; nt++) {
                    const int np = nt >> 1, sel = nt & 1;
                    mma16816(acc[mt][nt], af[mt], bh[np][sel], bh[np][sel + 2]);
                }
        }
        __syncthreads();
    }

    // epilogue
    if (MODE == 0) {
        float* Cp = Cf + (long)bz * 256 * N;
        #pragma unroll
        for (int mt = 0; mt < 2; mt++) {
            const int gm = m0 + wm + mt * 16 + (lane >> 2);
            #pragma unroll
            for (int nt = 0; nt < 8; nt++) {
                const int gn = n0 + wn + nt * 8 + ((lane & 3) << 1);
                *(float2*)(Cp + (long)gm * N + gn) =
                    make_float2(acc[mt][nt][0], acc[mt][nt][1]);
                *(float2*)(Cp + (long)(gm + 8) * N + gn) =
                    make_float2(acc[mt][nt][2], acc[mt][nt][3]);
            }
        }
    } else {
        const long cb = (long)bz * 256 * 1024;
        #pragma unroll
        for (int mt = 0; mt < 2; mt++) {
            const int gm = m0 + wm + mt * 16 + (lane >> 2);
            #pragma unroll
            for (int nt = 0; nt < 8; nt++) {
                const int gn = n0 + wn + nt * 8 + ((lane & 3) << 1);
                __nv_bfloat16 h0, l0, h1, l1;
                split1(acc[mt][nt][0], h0, l0);
                split1(acc[mt][nt][1], h1, l1);
                *(__nv_bfloat162*)(Ch + cb + (long)gm * 1024 + gn) = __nv_bfloat162(h0, h1);
                *(__nv_bfloat162*)(Cl + cb + (long)gm * 1024 + gn) = __nv_bfloat162(l0, l1);
                split1(acc[mt][nt][2], h0, l0);
                split1(acc[mt][nt][3], h1, l1);
                *(__nv_bfloat162*)(Ch + cb + (long)(gm + 8) * 1024 + gn) = __nv_bfloat162(h0, h1);
                *(__nv_bfloat162*)(Cl + cb + (long)(gm + 8) * 1024 + gn) = __nv_bfloat162(l0, l1);
            }
        }
    }
}

// ---------------------------------------------------------------------------
// Final projection: out = tanh([Q|exc|setc] @ W^T + b).  M=20480,N=1024,K=3072.
// Same skeleton, 3-piece A select, tanh+bias epilogue, 3-stage pipeline.
// ---------------------------------------------------------------------------
#define NCHF 96

__global__ __launch_bounds__(256)
void mma_final(const __nv_bfloat16* __restrict__ qh, const __nv_bfloat16* __restrict__ ql,
               const __nv_bfloat16* __restrict__ ech, const __nv_bfloat16* __restrict__ ecl,
               const __nv_bfloat16* __restrict__ sch, const __nv_bfloat16* __restrict__ scl,
               const __nv_bfloat16* __restrict__ wh, const __nv_bfloat16* __restrict__ wl,
               const float* __restrict__ bias, float* __restrict__ out)
{
    extern __shared__ char smem[];
    const uint32_t sb = smem_u32(smem);
    const int tid  = threadIdx.x;
    const int wid  = tid >> 5;
    const int lane = tid & 31;
    const long m0 = (long)blockIdx.y * 128;
    const int  n0 = blockIdx.x * 128;

    const int wm = (wid & 3) * 32;
    const int wn = (wid >> 2) * 64;
    const int laneR  = lane & 15;
    const int laneC8 = (lane >> 4) << 3;
    const uint32_t aRow = (uint32_t)((wm + laneR) * 40 + laneC8) * 2;
    const uint32_t bRow = (uint32_t)((wn + laneR) * 40 + laneC8) * 2;

    const int r0 = tid >> 2, s0 = tid & 3;
    const int r1 = r0 + 64;

    auto issue = [&](int c) {
        const int k0 = c << 5;
        const int pc = k0 >> 10;
        const __nv_bfloat16* Ah = pc == 0 ? qh : (pc == 1 ? ech : sch);
        const __nv_bfloat16* Al = pc == 0 ? ql : (pc == 1 ? ecl : scl);
        const int kin = k0 & 1023;
        const uint32_t st = sb + (uint32_t)(c % 3) * STAGE_B;
        uint32_t so0 = (uint32_t)(r0 * 40 + s0 * 8) * 2;
        uint32_t so1 = (uint32_t)(r1 * 40 + s0 * 8) * 2;
        long ao0 = (m0 + r0) * 1024 + kin + s0 * 8;
        long ao1 = (m0 + r1) * 1024 + kin + s0 * 8;
        long bo0 = (long)(n0 + r0) * 3072 + k0 + s0 * 8;
        long bo1 = (long)(n0 + r1) * 3072 + k0 + s0 * 8;
        cp16(st + OFF_AH + so0, Ah + ao0);
        cp16(st + OFF_AH + so1, Ah + ao1);
        cp16(st + OFF_AL + so0, Al + ao0);
        cp16(st + OFF_AL + so1, Al + ao1);
        cp16(st + OFF_BH + so0, wh + bo0);
        cp16(st + OFF_BH + so1, wh + bo1);
        cp16(st + OFF_BL + so0, wl + bo0);
        cp16(st + OFF_BL + so1, wl + bo1);
        CP_COMMIT();
    };

    float acc[2][8][4];
    #pragma unroll
    for (int i = 0; i < 2; i++)
        #pragma unroll
        for (int j = 0; j < 8; j++)
            #pragma unroll
            for (int k = 0; k < 4; k++) acc[i][j][k] = 0.0f;

    issue(0); issue(1);

    for (int c = 0; c < NCHF; c++) {
        if (c + 1 < NCHF) CP_WAIT1(); else CP_WAIT0();
        __syncthreads();
        if (c + 2 < NCHF) issue(c + 2);

        const uint32_t st = sb + (uint32_t)(c % 3) * STAGE_B;
        #pragma unroll
        for (int ks = 0; ks < 2; ks++) {
            const uint32_t kOff = (uint32_t)(ks * 16) * 2;
            uint32_t af[2][4], bh[4][4], bl[4][4];
            #pragma unroll
            for (int mt = 0; mt < 2; mt++)
                ldm4(af[mt], st + OFF_AH + aRow + (uint32_t)(mt * 640) * 2 + kOff);
            #pragma unroll
            for (int np = 0; np < 4; np++) {
                ldm4(bh[np], st + OFF_BH + bRow + (uint32_t)(np * 640) * 2 + kOff);
                ldm4(bl[np], st + OFF_BL + bRow + (uint32_t)(np * 640) * 2 + kOff);
            }
            #pragma unroll
            for (int mt = 0; mt < 2; mt++)
                #pragma unroll
                for (int nt = 0; nt < 8; nt++) {
                    const int np = nt >> 1, sel = nt & 1;
                    mma16816(acc[mt][nt], af[mt], bh[np][sel], bh[np][sel + 2]);
                    mma16816(acc[mt][nt], af[mt], bl[np][sel], bl[np][sel + 2]);
                }
            #pragma unroll
            for (int mt = 0; mt < 2; mt++)
                ldm4(af[mt], st + OFF_AL + aRow + (uint32_t)(mt * 640) * 2 + kOff);
            #pragma unroll
            for (int mt = 0; mt < 2; mt++)
                #pragma unroll
                for (int nt = 0; nt < 8; nt++) {
                    const int np = nt >> 1, sel = nt & 1;
                    mma16816(acc[mt][nt], af[mt], bh[np][sel], bh[np][sel + 2]);
                }
        }
        __syncthreads();
    }

    #pragma unroll
    for (int mt = 0; mt < 2; mt++) {
        const long gm = m0 + wm + mt * 16 + (lane >> 2);
        #pragma unroll
        for (int nt = 0; nt < 8; nt++) {
            const int gn = n0 + wn + nt * 8 + ((lane & 3) << 1);
            const float b0 = bias[gn], b1 = bias[gn + 1];
            *(float2*)(out + gm * 1024 + gn) =
                make_float2(tanhf(acc[mt][nt][0] + b0), tanhf(acc[mt][nt][1] + b1));
            *(float2*)(out + (gm + 8) * 1024 + gn) =
                make_float2(tanhf(acc[mt][nt][2] + b0), tanhf(acc[mt][nt][3] + b1));
        }
    }
}

// ---------------------------------------------------------------------------
extern "C" void kernel_launch(void* const* d_in, const int* in_sizes, int n_in,
                              void* d_out, int out_size)
{
    const float* Q  = (const float*)d_in[0];
    const float* C0 = (const float*)d_in[1];
    const float* C1 = (const float*)d_in[2];
    // d_in[3] = mask (unused, faithful to reference)
    const float* W  = (const float*)d_in[4];
    const float* bb = (const float*)d_in[5];

    float* OUT = (float*)d_out;
    float* EXA = OUT + (long)BT * LQ * HD;
    float* SEA = EXA + (long)BT * LQ * LQ;

    #define SYM(v, s) void* p_##v; cudaGetSymbolAddress(&p_##v, s); \
                      __nv_bfloat16* v = (__nv_bfloat16*)p_##v
    SYM(qh,  g_qh);  SYM(ql,  g_ql);
    SYM(wh,  g_wh);  SYM(wl,  g_wl);
    SYM(c0h, g_c0h); SYM(c0l, g_c0l);
    SYM(c1h, g_c1h); SYM(c1l, g_c1l);
    SYM(t0h, g_t0h); SYM(t0l, g_t0l);
    SYM(t1h, g_t1h); SYM(t1l, g_t1l);
    SYM(peh, g_peh); SYM(pel, g_pel);
    SYM(psh, g_psh); SYM(psl, g_psl);
    SYM(ech, g_ech); SYM(ecl, g_ecl);
    SYM(sch, g_sch); SYM(scl, g_scl);
    #undef SYM

    cudaFuncSetAttribute(mma_nt<0>, cudaFuncAttributeMaxDynamicSharedMemorySize, MM_SMEM);
    cudaFuncSetAttribute(mma_nt<1>, cudaFuncAttributeMaxDynamicSharedMemorySize, MM_SMEM);
    cudaFuncSetAttribute(mma_final, cudaFuncAttributeMaxDynamicSharedMemorySize, MM_SMEM);

    // splits
    split_bf16<<<(BT*LQ*HD)/1024, 256>>>(Q,  qh,  ql);
    split_bf16<<<(HD*3*HD)/1024, 256>>>(W,  wh,  wl);
    split_bf16<<<(BT*LQ*HD)/1024, 256>>>(C0, c0h, c0l);
    split_bf16<<<(8*SS*HD)/1024, 256>>>(C1, c1h, c1l);
    // transposed splits (V^T for PV gemms)
    tsplit_bf16<<<dim3(LQ/32, 32, BT), dim3(32, 8)>>>(C0, t0h, t0l, LQ);
    tsplit_bf16<<<dim3(SS/32, 32, 8),  dim3(32, 8)>>>(C1, t1h, t1l, SS);

    // logits (tensor cores)
    mma_nt<0><<<dim3(2, 2, BT), 256, MM_SMEM>>>(qh, ql, c0h, c0l, EXA, nullptr, nullptr,
                                                HD, LQ, (long)LQ*HD, 1);
    mma_nt<0><<<dim3(4, 2, BT), 256, MM_SMEM>>>(qh, ql, c1h, c1l, SEA, nullptr, nullptr,
                                                HD, SS, (long)SS*HD, 10);

    // softmax in place + prob splits
    softmax_rows<<<BT * LQ, 256>>>(EXA, peh, pel, LQ);
    softmax_rows<<<BT * LQ, 256>>>(SEA, psh, psl, SS);

    // attn @ V (tensor cores, emit bf16 splits)
    mma_nt<1><<<dim3(8, 2, BT), 256, MM_SMEM>>>(peh, pel, t0h, t0l, nullptr, ech, ecl,
                                                LQ, HD, (long)HD*LQ, 1);
    mma_nt<1><<<dim3(8, 2, BT), 256, MM_SMEM>>>(psh, psl, t1h, t1l, nullptr, sch, scl,
                                                SS, HD, (long)HD*SS, 10);

    // final projection
    mma_final<<<dim3(8, 160), 256, MM_SMEM>>>(qh, ql, ech, ecl, sch, scl, wh, wl, bb, OUT);
}

// round 7
// speedup vs baseline: 2.0430x; 1.0917x over previous
#include <cuda_runtime.h>
#include <cuda_bf16.h>
#include <cuda_fp16.h>
#include <cstdint>

#define BT 80
#define LQ 256
#define SS 512
#define HD 1024
#define LH (LQ*HD)

// ---------------- scratch (device globals; allocation-free rule) -----------
__device__ __nv_bfloat16 g_qh[(size_t)BT*LQ*HD],  g_ql[(size_t)BT*LQ*HD];
__device__ __nv_bfloat16 g_wh[(size_t)HD*3*HD],   g_wl[(size_t)HD*3*HD];
__device__ __nv_bfloat16 g_c0h[(size_t)BT*LQ*HD], g_c0l[(size_t)BT*LQ*HD];
__device__ __nv_bfloat16 g_c1h[(size_t)8*SS*HD],  g_c1l[(size_t)8*SS*HD];
__device__ __nv_bfloat16 g_ech[(size_t)BT*LQ*HD], g_ecl[(size_t)BT*LQ*HD];
__device__ __nv_bfloat16 g_sch[(size_t)BT*LQ*HD], g_scl[(size_t)BT*LQ*HD];
// fp16 PV path
__device__ __half g_pef[(size_t)BT*LQ*LQ], g_psf[(size_t)BT*LQ*SS];
__device__ __half g_t0f[(size_t)BT*HD*LQ], g_t1f[(size_t)8*HD*SS];

// ---------------- portable PTX helpers -------------------------------------
__device__ __forceinline__ uint32_t smem_u32(const void* p) {
    uint32_t a;
    asm("{ .reg .u64 t; cvta.to.shared.u64 t, %1; cvt.u32.u64 %0, t; }" : "=r"(a) : "l"(p));
    return a;
}
__device__ __forceinline__ void cp16(uint32_t dst, const void* src) {
    asm volatile("cp.async.cg.shared.global [%0], [%1], 16;" :: "r"(dst), "l"(src));
}
#define CP_COMMIT() asm volatile("cp.async.commit_group;" ::: "memory")
#define CP_WAIT1()  asm volatile("cp.async.wait_group 1;" ::: "memory")
#define CP_WAIT0()  asm volatile("cp.async.wait_group 0;" ::: "memory")

__device__ __forceinline__ void ldm4(uint32_t* r, uint32_t addr) {
    asm volatile("ldmatrix.sync.aligned.m8n8.x4.shared.b16 {%0,%1,%2,%3}, [%4];"
        : "=r"(r[0]), "=r"(r[1]), "=r"(r[2]), "=r"(r[3]) : "r"(addr));
}
__device__ __forceinline__ void mma16816(float* c, const uint32_t* a,
                                         uint32_t b0, uint32_t b1) {
    asm volatile(
        "mma.sync.aligned.m16n8k16.row.col.f32.bf16.bf16.f32 "
        "{%0,%1,%2,%3}, {%4,%5,%6,%7}, {%8,%9}, {%0,%1,%2,%3};"
        : "+f"(c[0]), "+f"(c[1]), "+f"(c[2]), "+f"(c[3])
        : "r"(a[0]), "r"(a[1]), "r"(a[2]), "r"(a[3]), "r"(b0), "r"(b1));
}
__device__ __forceinline__ void mma16816h(float* c, const uint32_t* a,
                                          uint32_t b0, uint32_t b1) {
    asm volatile(
        "mma.sync.aligned.m16n8k16.row.col.f32.f16.f16.f32 "
        "{%0,%1,%2,%3}, {%4,%5,%6,%7}, {%8,%9}, {%0,%1,%2,%3};"
        : "+f"(c[0]), "+f"(c[1]), "+f"(c[2]), "+f"(c[3])
        : "r"(a[0]), "r"(a[1]), "r"(a[2]), "r"(a[3]), "r"(b0), "r"(b1));
}
__device__ __forceinline__ void split1(float v, __nv_bfloat16& h, __nv_bfloat16& l) {
    h = __float2bfloat16(v);
    l = __float2bfloat16(v - __bfloat162float(h));
}

// ---------------------------------------------------------------------------
// plain fp32 -> bf16 hi/lo split (4 elems/thread)
// ---------------------------------------------------------------------------
__global__ void split_bf16(const float* __restrict__ x,
                           __nv_bfloat16* __restrict__ h,
                           __nv_bfloat16* __restrict__ l)
{
    long i = ((long)blockIdx.x * blockDim.x + threadIdx.x) * 4;
    float4 v = *(const float4*)(x + i);
    float vv[4] = {v.x, v.y, v.z, v.w};
    __nv_bfloat16 hh[4], ll[4];
    #pragma unroll
    for (int j = 0; j < 4; j++) split1(vv[j], hh[j], ll[j]);
    *(__nv_bfloat162*)(h + i)     = __nv_bfloat162(hh[0], hh[1]);
    *(__nv_bfloat162*)(h + i + 2) = __nv_bfloat162(hh[2], hh[3]);
    *(__nv_bfloat162*)(l + i)     = __nv_bfloat162(ll[0], ll[1]);
    *(__nv_bfloat162*)(l + i + 2) = __nv_bfloat162(ll[2], ll[3]);
}

// ---------------------------------------------------------------------------
// transposed fp16 copy: x [B][S][1024] -> f [B][1024][S]  (__half)
// block (32,8), grid (S/32, 32, B)
// ---------------------------------------------------------------------------
__global__ void tsplit_f16(const float* __restrict__ x,
                           __half* __restrict__ f, int S)
{
    __shared__ float t[32][33];
    const int b  = blockIdx.z;
    const int s0 = blockIdx.x * 32;
    const int d0 = blockIdx.y * 32;
    const int tx = threadIdx.x, ty = threadIdx.y;

    const float* xp = x + (long)b * S * 1024;
    #pragma unroll
    for (int r = 0; r < 4; r++) {
        int s = ty + r * 8;
        t[s][tx] = xp[(long)(s0 + s) * 1024 + d0 + tx];
    }
    __syncthreads();
    const long ob = (long)b * 1024 * S;
    #pragma unroll
    for (int r = 0; r < 4; r++) {
        int d = ty + r * 8;
        f[ob + (long)(d0 + d) * S + s0 + tx] = __float2half(t[tx][d]);
    }
}

// ---------------------------------------------------------------------------
// Row softmax in place + fp16 prob copy.
// ---------------------------------------------------------------------------
__global__ void softmax_rows(float* __restrict__ p,
                             __half* __restrict__ pf, int n)
{
    __shared__ float red[256];
    const int tid = threadIdx.x;
    const long base = (long)blockIdx.x * n;
    p += base; pf += base;

    float v0 = p[tid];
    float v1 = (n > 256) ? p[tid + 256] : -3.402823e38f;

    red[tid] = fmaxf(v0, v1); __syncthreads();
    #pragma unroll
    for (int s = 128; s > 0; s >>= 1) {
        if (tid < s) red[tid] = fmaxf(red[tid], red[tid + s]);
        __syncthreads();
    }
    const float mx = red[0];
    __syncthreads();

    float e0 = __expf(v0 - mx);
    float e1 = (n > 256) ? __expf(v1 - mx) : 0.0f;
    red[tid] = e0 + e1; __syncthreads();
    #pragma unroll
    for (int s = 128; s > 0; s >>= 1) {
        if (tid < s) red[tid] += red[tid + s];
        __syncthreads();
    }
    const float inv = 1.0f / red[0];

    float p0 = e0 * inv;
    p[tid] = p0; pf[tid] = __float2half(p0);
    if (n > 256) {
        float p1 = e1 * inv;
        p[tid + 256] = p1; pf[tid + 256] = __float2half(p1);
    }
}

// ---------------------------------------------------------------------------
// Shared tile geometry for bf16 split kernels
// ---------------------------------------------------------------------------
#define TILE_B   10240                 // 128 rows * 40 bf16 * 2B
#define OFF_AH   0
#define OFF_AL   (TILE_B)
#define OFF_BH   (2*TILE_B)
#define OFF_BL   (3*TILE_B)
#define STAGE_B  (4*TILE_B)            // 40960
#define MM_SMEM  (3*STAGE_B)           // 122880, 3-stage

// ---------------------------------------------------------------------------
// NT mma GEMM, bf16 2-split 3-product, fp32 store (logits).
// CTA 128x128, K-chunk 32, 3-stage cp.async.
// ---------------------------------------------------------------------------
__global__ __launch_bounds__(256)
void mma_nt(const __nv_bfloat16* __restrict__ Ah, const __nv_bfloat16* __restrict__ Al,
            const __nv_bfloat16* __restrict__ Bh, const __nv_bfloat16* __restrict__ Bl,
            float* __restrict__ Cf,
            int K, int N, long bBatch, int bDiv)
{
    extern __shared__ char smem[];
    const uint32_t sb = smem_u32(smem);
    const int tid  = threadIdx.x;
    const int wid  = tid >> 5;
    const int lane = tid & 31;
    const int bz = blockIdx.z;
    const int m0 = blockIdx.y * 128;
    const int n0 = blockIdx.x * 128;
    const int NCH = K >> 5;

    const long aBase = (long)bz * 256 * K + (long)m0 * K;
    const long bBase = (long)(bz / bDiv) * bBatch + (long)n0 * K;

    const int wm = (wid & 3) * 32;
    const int wn = (wid >> 2) * 64;
    const int laneR  = lane & 15;
    const int laneC8 = (lane >> 4) << 3;
    const uint32_t aRow = (uint32_t)((wm + laneR) * 40 + laneC8) * 2;
    const uint32_t bRow = (uint32_t)((wn + laneR) * 40 + laneC8) * 2;

    const int r0 = tid >> 2, s0 = tid & 3;
    const int r1 = r0 + 64;

    auto issue = [&](int c) {
        const int k0 = c << 5;
        const uint32_t st = sb + (uint32_t)(c % 3) * STAGE_B;
        uint32_t so0 = (uint32_t)(r0 * 40 + s0 * 8) * 2;
        uint32_t so1 = (uint32_t)(r1 * 40 + s0 * 8) * 2;
        long ao0 = aBase + (long)r0 * K + k0 + s0 * 8;
        long ao1 = aBase + (long)r1 * K + k0 + s0 * 8;
        long bo0 = bBase + (long)r0 * K + k0 + s0 * 8;
        long bo1 = bBase + (long)r1 * K + k0 + s0 * 8;
        cp16(st + OFF_AH + so0, Ah + ao0);
        cp16(st + OFF_AH + so1, Ah + ao1);
        cp16(st + OFF_AL + so0, Al + ao0);
        cp16(st + OFF_AL + so1, Al + ao1);
        cp16(st + OFF_BH + so0, Bh + bo0);
        cp16(st + OFF_BH + so1, Bh + bo1);
        cp16(st + OFF_BL + so0, Bl + bo0);
        cp16(st + OFF_BL + so1, Bl + bo1);
        CP_COMMIT();
    };

    float acc[2][8][4];
    #pragma unroll
    for (int i = 0; i < 2; i++)
        #pragma unroll
        for (int j = 0; j < 8; j++)
            #pragma unroll
            for (int k = 0; k < 4; k++) acc[i][j][k] = 0.0f;

    issue(0); issue(1);

    for (int c = 0; c < NCH; c++) {
        if (c + 1 < NCH) CP_WAIT1(); else CP_WAIT0();
        __syncthreads();
        if (c + 2 < NCH) issue(c + 2);

        const uint32_t st = sb + (uint32_t)(c % 3) * STAGE_B;
        #pragma unroll
        for (int ks = 0; ks < 2; ks++) {
            const uint32_t kOff = (uint32_t)(ks * 16) * 2;
            uint32_t af[2][4], bh[4][4], bl[4][4];
            #pragma unroll
            for (int mt = 0; mt < 2; mt++)
                ldm4(af[mt], st + OFF_AH + aRow + (uint32_t)(mt * 640) * 2 + kOff);
            #pragma unroll
            for (int np = 0; np < 4; np++) {
                ldm4(bh[np], st + OFF_BH + bRow + (uint32_t)(np * 640) * 2 + kOff);
                ldm4(bl[np], st + OFF_BL + bRow + (uint32_t)(np * 640) * 2 + kOff);
            }
            #pragma unroll
            for (int mt = 0; mt < 2; mt++)
                #pragma unroll
                for (int nt = 0; nt < 8; nt++) {
                    const int np = nt >> 1, sel = nt & 1;
                    mma16816(acc[mt][nt], af[mt], bh[np][sel], bh[np][sel + 2]);
                    mma16816(acc[mt][nt], af[mt], bl[np][sel], bl[np][sel + 2]);
                }
            #pragma unroll
            for (int mt = 0; mt < 2; mt++)
                ldm4(af[mt], st + OFF_AL + aRow + (uint32_t)(mt * 640) * 2 + kOff);
            #pragma unroll
            for (int mt = 0; mt < 2; mt++)
                #pragma unroll
                for (int nt = 0; nt < 8; nt++) {
                    const int np = nt >> 1, sel = nt & 1;
                    mma16816(acc[mt][nt], af[mt], bh[np][sel], bh[np][sel + 2]);
                }
        }
        __syncthreads();
    }

    float* Cp = Cf + (long)bz * 256 * N;
    #pragma unroll
    for (int mt = 0; mt < 2; mt++) {
        const int gm = m0 + wm + mt * 16 + (lane >> 2);
        #pragma unroll
        for (int nt = 0; nt < 8; nt++) {
            const int gn = n0 + wn + nt * 8 + ((lane & 3) << 1);
            *(float2*)(Cp + (long)gm * N + gn) =
                make_float2(acc[mt][nt][0], acc[mt][nt][1]);
            *(float2*)(Cp + (long)(gm + 8) * N + gn) =
                make_float2(acc[mt][nt][2], acc[mt][nt][3]);
        }
    }
}

// ---------------------------------------------------------------------------
// PV GEMM: fp16 single product, warp tile 64x64, CTA 256x128.
// C[bz] = P[bz] (256xK) * Vt[(bz/bDiv)] (128-n x K)  -> ec/sc bf16 split.
// grid (N/128, 1, BT).  K in {256, 512}.
// ---------------------------------------------------------------------------
#define PV_A_B   20480                 // 256 rows * 40 half * 2B
#define PV_B_B   10240                 // 128 rows * 40 half * 2B
#define PV_STAGE (PV_A_B + PV_B_B)     // 30720
#define PV_SMEM  (3*PV_STAGE)          // 92160

__global__ __launch_bounds__(256)
void mma_pv(const __half* __restrict__ Pf, const __half* __restrict__ Vt,
            __nv_bfloat16* __restrict__ Ch, __nv_bfloat16* __restrict__ Cl,
            int K, long bBatch, int bDiv)
{
    extern __shared__ char smem[];
    const uint32_t sb = smem_u32(smem);
    const int tid  = threadIdx.x;
    const int wid  = tid >> 5;
    const int lane = tid & 31;
    const int bz = blockIdx.z;
    const int n0 = blockIdx.x * 128;
    const int NCH = K >> 5;

    const long aBase = (long)bz * 256 * K;
    const long bBase = (long)(bz / bDiv) * bBatch + (long)n0 * K;

    const int wm = (wid & 3) * 64;
    const int wn = (wid >> 2) * 64;
    const int laneR  = lane & 15;
    const int laneC8 = (lane >> 4) << 3;
    const uint32_t aRow = (uint32_t)((wm + laneR) * 40 + laneC8) * 2;
    const uint32_t bRow = (uint32_t)((wn + laneR) * 40 + laneC8) * 2;

    const int r0 = tid >> 2, s0 = tid & 3;

    auto issue = [&](int c) {
        const int k0 = c << 5;
        const uint32_t st = sb + (uint32_t)(c % 3) * PV_STAGE;
        #pragma unroll
        for (int j = 0; j < 4; j++) {
            int row = r0 + j * 64;
            cp16(st + (uint32_t)(row * 40 + s0 * 8) * 2,
                 Pf + aBase + (long)row * K + k0 + s0 * 8);
        }
        #pragma unroll
        for (int j = 0; j < 2; j++) {
            int row = r0 + j * 64;
            cp16(st + PV_A_B + (uint32_t)(row * 40 + s0 * 8) * 2,
                 Vt + bBase + (long)row * K + k0 + s0 * 8);
        }
        CP_COMMIT();
    };

    float acc[4][8][4];
    #pragma unroll
    for (int i = 0; i < 4; i++)
        #pragma unroll
        for (int j = 0; j < 8; j++)
            #pragma unroll
            for (int k = 0; k < 4; k++) acc[i][j][k] = 0.0f;

    issue(0); issue(1);

    for (int c = 0; c < NCH; c++) {
        if (c + 1 < NCH) CP_WAIT1(); else CP_WAIT0();
        __syncthreads();
        if (c + 2 < NCH) issue(c + 2);

        const uint32_t st = sb + (uint32_t)(c % 3) * PV_STAGE;
        #pragma unroll
        for (int ks = 0; ks < 2; ks++) {
            const uint32_t kOff = (uint32_t)(ks * 16) * 2;
            uint32_t af[4][4], bf[4][4];
            #pragma unroll
            for (int mt = 0; mt < 4; mt++)
                ldm4(af[mt], st + aRow + (uint32_t)(mt * 640) * 2 + kOff);
            #pragma unroll
            for (int np = 0; np < 4; np++)
                ldm4(bf[np], st + PV_A_B + bRow + (uint32_t)(np * 640) * 2 + kOff);
            #pragma unroll
            for (int mt = 0; mt < 4; mt++)
                #pragma unroll
                for (int nt = 0; nt < 8; nt++) {
                    const int np = nt >> 1, sel = nt & 1;
                    mma16816h(acc[mt][nt], af[mt], bf[np][sel], bf[np][sel + 2]);
                }
        }
        __syncthreads();
    }

    const long cb = (long)bz * 256 * 1024;
    #pragma unroll
    for (int mt = 0; mt < 4; mt++) {
        const int gm = wm + mt * 16 + (lane >> 2);
        #pragma unroll
        for (int nt = 0; nt < 8; nt++) {
            const int gn = n0 + wn + nt * 8 + ((lane & 3) << 1);
            __nv_bfloat16 h0, l0, h1, l1;
            split1(acc[mt][nt][0], h0, l0);
            split1(acc[mt][nt][1], h1, l1);
            *(__nv_bfloat162*)(Ch + cb + (long)gm * 1024 + gn) = __nv_bfloat162(h0, h1);
            *(__nv_bfloat162*)(Cl + cb + (long)gm * 1024 + gn) = __nv_bfloat162(l0, l1);
            split1(acc[mt][nt][2], h0, l0);
            split1(acc[mt][nt][3], h1, l1);
            *(__nv_bfloat162*)(Ch + cb + (long)(gm + 8) * 1024 + gn) = __nv_bfloat162(h0, h1);
            *(__nv_bfloat162*)(Cl + cb + (long)(gm + 8) * 1024 + gn) = __nv_bfloat162(l0, l1);
        }
    }
}

// ---------------------------------------------------------------------------
// Final projection: out = tanh([Q|exc|setc] @ W^T + b).  M=20480,N=1024,K=3072.
// bf16 3-product, 3-stage pipeline.
// ---------------------------------------------------------------------------
#define NCHF 96

__global__ __launch_bounds__(256)
void mma_final(const __nv_bfloat16* __restrict__ qh, const __nv_bfloat16* __restrict__ ql,
               const __nv_bfloat16* __restrict__ ech, const __nv_bfloat16* __restrict__ ecl,
               const __nv_bfloat16* __restrict__ sch, const __nv_bfloat16* __restrict__ scl,
               const __nv_bfloat16* __restrict__ wh, const __nv_bfloat16* __restrict__ wl,
               const float* __restrict__ bias, float* __restrict__ out)
{
    extern __shared__ char smem[];
    const uint32_t sb = smem_u32(smem);
    const int tid  = threadIdx.x;
    const int wid  = tid >> 5;
    const int lane = tid & 31;
    const long m0 = (long)blockIdx.y * 128;
    const int  n0 = blockIdx.x * 128;

    const int wm = (wid & 3) * 32;
    const int wn = (wid >> 2) * 64;
    const int laneR  = lane & 15;
    const int laneC8 = (lane >> 4) << 3;
    const uint32_t aRow = (uint32_t)((wm + laneR) * 40 + laneC8) * 2;
    const uint32_t bRow = (uint32_t)((wn + laneR) * 40 + laneC8) * 2;

    const int r0 = tid >> 2, s0 = tid & 3;
    const int r1 = r0 + 64;

    auto issue = [&](int c) {
        const int k0 = c << 5;
        const int pc = k0 >> 10;
        const __nv_bfloat16* Ah = pc == 0 ? qh : (pc == 1 ? ech : sch);
        const __nv_bfloat16* Al = pc == 0 ? ql : (pc == 1 ? ecl : scl);
        const int kin = k0 & 1023;
        const uint32_t st = sb + (uint32_t)(c % 3) * STAGE_B;
        uint32_t so0 = (uint32_t)(r0 * 40 + s0 * 8) * 2;
        uint32_t so1 = (uint32_t)(r1 * 40 + s0 * 8) * 2;
        long ao0 = (m0 + r0) * 1024 + kin + s0 * 8;
        long ao1 = (m0 + r1) * 1024 + kin + s0 * 8;
        long bo0 = (long)(n0 + r0) * 3072 + k0 + s0 * 8;
        long bo1 = (long)(n0 + r1) * 3072 + k0 + s0 * 8;
        cp16(st + OFF_AH + so0, Ah + ao0);
        cp16(st + OFF_AH + so1, Ah + ao1);
        cp16(st + OFF_AL + so0, Al + ao0);
        cp16(st + OFF_AL + so1, Al + ao1);
        cp16(st + OFF_BH + so0, wh + bo0);
        cp16(st + OFF_BH + so1, wh + bo1);
        cp16(st + OFF_BL + so0, wl + bo0);
        cp16(st + OFF_BL + so1, wl + bo1);
        CP_COMMIT();
    };

    float acc[2][8][4];
    #pragma unroll
    for (int i = 0; i < 2; i++)
        #pragma unroll
        for (int j = 0; j < 8; j++)
            #pragma unroll
            for (int k = 0; k < 4; k++) acc[i][j][k] = 0.0f;

    issue(0); issue(1);

    for (int c = 0; c < NCHF; c++) {
        if (c + 1 < NCHF) CP_WAIT1(); else CP_WAIT0();
        __syncthreads();
        if (c + 2 < NCHF) issue(c + 2);

        const uint32_t st = sb + (uint32_t)(c % 3) * STAGE_B;
        #pragma unroll
        for (int ks = 0; ks < 2; ks++) {
            const uint32_t kOff = (uint32_t)(ks * 16) * 2;
            uint32_t af[2][4], bh[4][4], bl[4][4];
            #pragma unroll
            for (int mt = 0; mt < 2; mt++)
                ldm4(af[mt], st + OFF_AH + aRow + (uint32_t)(mt * 640) * 2 + kOff);
            #pragma unroll
            for (int np = 0; np < 4; np++) {
                ldm4(bh[np], st + OFF_BH + bRow + (uint32_t)(np * 640) * 2 + kOff);
                ldm4(bl[np], st + OFF_BL + bRow + (uint32_t)(np * 640) * 2 + kOff);
            }
            #pragma unroll
            for (int mt = 0; mt < 2; mt++)
                #pragma unroll
                for (int nt = 0; nt < 8; nt++) {
                    const int np = nt >> 1, sel = nt & 1;
                    mma16816(acc[mt][nt], af[mt], bh[np][sel], bh[np][sel + 2]);
                    mma16816(acc[mt][nt], af[mt], bl[np][sel], bl[np][sel + 2]);
                }
            #pragma unroll
            for (int mt = 0; mt < 2; mt++)
                ldm4(af[mt], st + OFF_AL + aRow + (uint32_t)(mt * 640) * 2 + kOff);
            #pragma unroll
            for (int mt = 0; mt < 2; mt++)
                #pragma unroll
                for (int nt = 0; nt < 8; nt++) {
                    const int np = nt >> 1, sel = nt & 1;
                    mma16816(acc[mt][nt], af[mt], bh[np][sel], bh[np][sel + 2]);
                }
        }
        __syncthreads();
    }

    #pragma unroll
    for (int mt = 0; mt < 2; mt++) {
        const long gm = m0 + wm + mt * 16 + (lane >> 2);
        #pragma unroll
        for (int nt = 0; nt < 8; nt++) {
            const int gn = n0 + wn + nt * 8 + ((lane & 3) << 1);
            const float b0 = bias[gn], b1 = bias[gn + 1];
            *(float2*)(out + gm * 1024 + gn) =
                make_float2(tanhf(acc[mt][nt][0] + b0), tanhf(acc[mt][nt][1] + b1));
            *(float2*)(out + (gm + 8) * 1024 + gn) =
                make_float2(tanhf(acc[mt][nt][2] + b0), tanhf(acc[mt][nt][3] + b1));
        }
    }
}

// ---------------------------------------------------------------------------
extern "C" void kernel_launch(void* const* d_in, const int* in_sizes, int n_in,
                              void* d_out, int out_size)
{
    const float* Q  = (const float*)d_in[0];
    const float* C0 = (const float*)d_in[1];
    const float* C1 = (const float*)d_in[2];
    // d_in[3] = mask (unused, faithful to reference)
    const float* W  = (const float*)d_in[4];
    const float* bb = (const float*)d_in[5];

    float* OUT = (float*)d_out;
    float* EXA = OUT + (long)BT * LQ * HD;
    float* SEA = EXA + (long)BT * LQ * LQ;

    #define SYM(t, v, s) void* p_##v; cudaGetSymbolAddress(&p_##v, s); \
                         t* v = (t*)p_##v
    SYM(__nv_bfloat16, qh,  g_qh);  SYM(__nv_bfloat16, ql,  g_ql);
    SYM(__nv_bfloat16, wh,  g_wh);  SYM(__nv_bfloat16, wl,  g_wl);
    SYM(__nv_bfloat16, c0h, g_c0h); SYM(__nv_bfloat16, c0l, g_c0l);
    SYM(__nv_bfloat16, c1h, g_c1h); SYM(__nv_bfloat16, c1l, g_c1l);
    SYM(__nv_bfloat16, ech, g_ech); SYM(__nv_bfloat16, ecl, g_ecl);
    SYM(__nv_bfloat16, sch, g_sch); SYM(__nv_bfloat16, scl, g_scl);
    SYM(__half, pef, g_pef); SYM(__half, psf, g_psf);
    SYM(__half, t0f, g_t0f); SYM(__half, t1f, g_t1f);
    #undef SYM

    cudaFuncSetAttribute(mma_nt,    cudaFuncAttributeMaxDynamicSharedMemorySize, MM_SMEM);
    cudaFuncSetAttribute(mma_pv,    cudaFuncAttributeMaxDynamicSharedMemorySize, PV_SMEM);
    cudaFuncSetAttribute(mma_final, cudaFuncAttributeMaxDynamicSharedMemorySize, MM_SMEM);

    // splits
    split_bf16<<<(BT*LQ*HD)/1024, 256>>>(Q,  qh,  ql);
    split_bf16<<<(HD*3*HD)/1024, 256>>>(W,  wh,  wl);
    split_bf16<<<(BT*LQ*HD)/1024, 256>>>(C0, c0h, c0l);
    split_bf16<<<(8*SS*HD)/1024, 256>>>(C1, c1h, c1l);
    // transposed fp16 V^T
    tsplit_f16<<<dim3(LQ/32, 32, BT), dim3(32, 8)>>>(C0, t0f, LQ);
    tsplit_f16<<<dim3(SS/32, 32, 8),  dim3(32, 8)>>>(C1, t1f, SS);

    // logits (bf16 3-product)
    mma_nt<<<dim3(2, 2, BT), 256, MM_SMEM>>>(qh, ql, c0h, c0l, EXA,
                                             HD, LQ, (long)LQ*HD, 1);
    mma_nt<<<dim3(4, 2, BT), 256, MM_SMEM>>>(qh, ql, c1h, c1l, SEA,
                                             HD, SS, (long)SS*HD, 10);

    // softmax in place + fp16 prob copy
    softmax_rows<<<BT * LQ, 256>>>(EXA, pef, LQ);
    softmax_rows<<<BT * LQ, 256>>>(SEA, psf, SS);

    // attn @ V (fp16 single product, emit bf16 splits)
    mma_pv<<<dim3(8, 1, BT), 256, PV_SMEM>>>(pef, t0f, ech, ecl,
                                             LQ, (long)HD*LQ, 1);
    mma_pv<<<dim3(8, 1, BT), 256, PV_SMEM>>>(psf, t1f, sch, scl,
                                             SS, (long)HD*SS, 10);

    // final projection (bf16 3-product)
    mma_final<<<dim3(8, 160), 256, MM_SMEM>>>(qh, ql, ech, ecl, sch, scl, wh, wl, bb, OUT);
}

// round 9
// speedup vs baseline: 3.3311x; 1.6305x over previous
#include <cuda_runtime.h>
#include <cuda_bf16.h>
#include <cuda_fp16.h>
#include <cstdint>

#define BT 80
#define LQ 256
#define SS 512
#define HD 1024
#define LH (LQ*HD)

// ---------------- scratch (device globals; allocation-free rule) -----------
__device__ __nv_bfloat16 g_qh[(size_t)BT*LQ*HD],  g_ql[(size_t)BT*LQ*HD];
__device__ __nv_bfloat16 g_c0h[(size_t)BT*LQ*HD], g_c0l[(size_t)BT*LQ*HD];
__device__ __nv_bfloat16 g_c1h[(size_t)8*SS*HD],  g_c1l[(size_t)8*SS*HD];
// fp16 path
__device__ __half g_qf[(size_t)BT*LQ*HD];
__device__ __half g_wf[(size_t)HD*3*HD];
__device__ __half g_ecf[(size_t)BT*LQ*HD], g_scf[(size_t)BT*LQ*HD];
__device__ __half g_pef[(size_t)BT*LQ*LQ], g_psf[(size_t)BT*LQ*SS];
__device__ __half g_t0f[(size_t)BT*HD*LQ], g_t1f[(size_t)8*HD*SS];

// ---------------- portable PTX helpers -------------------------------------
__device__ __forceinline__ uint32_t smem_u32(const void* p) {
    uint32_t a;
    asm("{ .reg .u64 t; cvta.to.shared.u64 t, %1; cvt.u32.u64 %0, t; }" : "=r"(a) : "l"(p));
    return a;
}
__device__ __forceinline__ void cp16(uint32_t dst, const void* src) {
    asm volatile("cp.async.cg.shared.global [%0], [%1], 16;" :: "r"(dst), "l"(src));
}
#define CP_COMMIT() asm volatile("cp.async.commit_group;" ::: "memory")
#define CP_WAIT1()  asm volatile("cp.async.wait_group 1;" ::: "memory")
#define CP_WAIT0()  asm volatile("cp.async.wait_group 0;" ::: "memory")

__device__ __forceinline__ void ldm4(uint32_t* r, uint32_t addr) {
    asm volatile("ldmatrix.sync.aligned.m8n8.x4.shared.b16 {%0,%1,%2,%3}, [%4];"
        : "=r"(r[0]), "=r"(r[1]), "=r"(r[2]), "=r"(r[3]) : "r"(addr));
}
__device__ __forceinline__ void mma16816(float* c, const uint32_t* a,
                                         uint32_t b0, uint32_t b1) {
    asm volatile(
        "mma.sync.aligned.m16n8k16.row.col.f32.bf16.bf16.f32 "
        "{%0,%1,%2,%3}, {%4,%5,%6,%7}, {%8,%9}, {%0,%1,%2,%3};"
        : "+f"(c[0]), "+f"(c[1]), "+f"(c[2]), "+f"(c[3])
        : "r"(a[0]), "r"(a[1]), "r"(a[2]), "r"(a[3]), "r"(b0), "r"(b1));
}
__device__ __forceinline__ void mma16816h(float* c, const uint32_t* a,
                                          uint32_t b0, uint32_t b1) {
    asm volatile(
        "mma.sync.aligned.m16n8k16.row.col.f32.f16.f16.f32 "
        "{%0,%1,%2,%3}, {%4,%5,%6,%7}, {%8,%9}, {%0,%1,%2,%3};"
        : "+f"(c[0]), "+f"(c[1]), "+f"(c[2]), "+f"(c[3])
        : "r"(a[0]), "r"(a[1]), "r"(a[2]), "r"(a[3]), "r"(b0), "r"(b1));
}
__device__ __forceinline__ void split1(float v, __nv_bfloat16& h, __nv_bfloat16& l) {
    h = __float2bfloat16(v);
    l = __float2bfloat16(v - __bfloat162float(h));
}

// ---------------------------------------------------------------------------
// fp32 -> bf16 hi/lo split (4 elems/thread)
// ---------------------------------------------------------------------------
__global__ void split_bf16(const float* __restrict__ x,
                           __nv_bfloat16* __restrict__ h,
                           __nv_bfloat16* __restrict__ l)
{
    long i = ((long)blockIdx.x * blockDim.x + threadIdx.x) * 4;
    float4 v = *(const float4*)(x + i);
    float vv[4] = {v.x, v.y, v.z, v.w};
    __nv_bfloat16 hh[4], ll[4];
    #pragma unroll
    for (int j = 0; j < 4; j++) split1(vv[j], hh[j], ll[j]);
    *(__nv_bfloat162*)(h + i)     = __nv_bfloat162(hh[0], hh[1]);
    *(__nv_bfloat162*)(h + i + 2) = __nv_bfloat162(hh[2], hh[3]);
    *(__nv_bfloat162*)(l + i)     = __nv_bfloat162(ll[0], ll[1]);
    *(__nv_bfloat162*)(l + i + 2) = __nv_bfloat162(ll[2], ll[3]);
}

// ---------------------------------------------------------------------------
// fp32 -> fp16 copy (4 elems/thread)
// ---------------------------------------------------------------------------
__global__ void copy_f16(const float* __restrict__ x, __half* __restrict__ f)
{
    long i = ((long)blockIdx.x * blockDim.x + threadIdx.x) * 4;
    float4 v = *(const float4*)(x + i);
    *(__half2*)(f + i)     = __floats2half2_rn(v.x, v.y);
    *(__half2*)(f + i + 2) = __floats2half2_rn(v.z, v.w);
}

// ---------------------------------------------------------------------------
// transposed fp16 copy: x [B][S][1024] -> f [B][1024][S]
// ---------------------------------------------------------------------------
__global__ void tsplit_f16(const float* __restrict__ x,
                           __half* __restrict__ f, int S)
{
    __shared__ float t[32][33];
    const int b  = blockIdx.z;
    const int s0 = blockIdx.x * 32;
    const int d0 = blockIdx.y * 32;
    const int tx = threadIdx.x, ty = threadIdx.y;

    const float* xp = x + (long)b * S * 1024;
    #pragma unroll
    for (int r = 0; r < 4; r++) {
        int s = ty + r * 8;
        t[s][tx] = xp[(long)(s0 + s) * 1024 + d0 + tx];
    }
    __syncthreads();
    const long ob = (long)b * 1024 * S;
    #pragma unroll
    for (int r = 0; r < 4; r++) {
        int d = ty + r * 8;
        f[ob + (long)(d0 + d) * S + s0 + tx] = __float2half(t[tx][d]);
    }
}

// ---------------------------------------------------------------------------
// Row softmax in place + fp16 prob copy.
// ---------------------------------------------------------------------------
__global__ void softmax_rows(float* __restrict__ p,
                             __half* __restrict__ pf, int n)
{
    __shared__ float red[256];
    const int tid = threadIdx.x;
    const long base = (long)blockIdx.x * n;
    p += base; pf += base;

    float v0 = p[tid];
    float v1 = (n > 256) ? p[tid + 256] : -3.402823e38f;

    red[tid] = fmaxf(v0, v1); __syncthreads();
    #pragma unroll
    for (int s = 128; s > 0; s >>= 1) {
        if (tid < s) red[tid] = fmaxf(red[tid], red[tid + s]);
        __syncthreads();
    }
    const float mx = red[0];
    __syncthreads();

    float e0 = __expf(v0 - mx);
    float e1 = (n > 256) ? __expf(v1 - mx) : 0.0f;
    red[tid] = e0 + e1; __syncthreads();
    #pragma unroll
    for (int s = 128; s > 0; s >>= 1) {
        if (tid < s) red[tid] += red[tid + s];
        __syncthreads();
    }
    const float inv = 1.0f / red[0];

    float p0 = e0 * inv;
    p[tid] = p0; pf[tid] = __float2half(p0);
    if (n > 256) {
        float p1 = e1 * inv;
        p[tid + 256] = p1; pf[tid + 256] = __float2half(p1);
    }
}

// ---------------------------------------------------------------------------
// bf16-split logits kernel geometry
// ---------------------------------------------------------------------------
#define TILE_B   10240                 // 128 rows * 40 bf16 * 2B
#define OFF_AH   0
#define OFF_AL   (TILE_B)
#define OFF_BH   (2*TILE_B)
#define OFF_BL   (3*TILE_B)
#define STAGE_B  (4*TILE_B)            // 40960
#define MM_SMEM  (3*STAGE_B)           // 122880

// ---------------------------------------------------------------------------
// Logits: NT mma GEMM, bf16 2-split 3-product, fp32 store.
// CTA 128x128, K-chunk 32, 3-stage cp.async.  (unchanged, proven)
// ---------------------------------------------------------------------------
__global__ __launch_bounds__(256)
void mma_nt(const __nv_bfloat16* __restrict__ Ah, const __nv_bfloat16* __restrict__ Al,
            const __nv_bfloat16* __restrict__ Bh, const __nv_bfloat16* __restrict__ Bl,
            float* __restrict__ Cf,
            int K, int N, long bBatch, int bDiv)
{
    extern __shared__ char smem[];
    const uint32_t sb = smem_u32(smem);
    const int tid  = threadIdx.x;
    const int wid  = tid >> 5;
    const int lane = tid & 31;
    const int bz = blockIdx.z;
    const int m0 = blockIdx.y * 128;
    const int n0 = blockIdx.x * 128;
    const int NCH = K >> 5;

    const long aBase = (long)bz * 256 * K + (long)m0 * K;
    const long bBase = (long)(bz / bDiv) * bBatch + (long)n0 * K;

    const int wm = (wid & 3) * 32;
    const int wn = (wid >> 2) * 64;
    const int laneR  = lane & 15;
    const int laneC8 = (lane >> 4) << 3;
    const uint32_t aRow = (uint32_t)((wm + laneR) * 40 + laneC8) * 2;
    const uint32_t bRow = (uint32_t)((wn + laneR) * 40 + laneC8) * 2;

    const int r0 = tid >> 2, s0 = tid & 3;
    const int r1 = r0 + 64;

    auto issue = [&](int c) {
        const int k0 = c << 5;
        const uint32_t st = sb + (uint32_t)(c % 3) * STAGE_B;
        uint32_t so0 = (uint32_t)(r0 * 40 + s0 * 8) * 2;
        uint32_t so1 = (uint32_t)(r1 * 40 + s0 * 8) * 2;
        long ao0 = aBase + (long)r0 * K + k0 + s0 * 8;
        long ao1 = aBase + (long)r1 * K + k0 + s0 * 8;
        long bo0 = bBase + (long)r0 * K + k0 + s0 * 8;
        long bo1 = bBase + (long)r1 * K + k0 + s0 * 8;
        cp16(st + OFF_AH + so0, Ah + ao0);
        cp16(st + OFF_AH + so1, Ah + ao1);
        cp16(st + OFF_AL + so0, Al + ao0);
        cp16(st + OFF_AL + so1, Al + ao1);
        cp16(st + OFF_BH + so0, Bh + bo0);
        cp16(st + OFF_BH + so1, Bh + bo1);
        cp16(st + OFF_BL + so0, Bl + bo0);
        cp16(st + OFF_BL + so1, Bl + bo1);
        CP_COMMIT();
    };

    float acc[2][8][4];
    #pragma unroll
    for (int i = 0; i < 2; i++)
        #pragma unroll
        for (int j = 0; j < 8; j++)
            #pragma unroll
            for (int k = 0; k < 4; k++) acc[i][j][k] = 0.0f;

    issue(0); issue(1);

    for (int c = 0; c < NCH; c++) {
        if (c + 1 < NCH) CP_WAIT1(); else CP_WAIT0();
        __syncthreads();
        if (c + 2 < NCH) issue(c + 2);

        const uint32_t st = sb + (uint32_t)(c % 3) * STAGE_B;
        #pragma unroll
        for (int ks = 0; ks < 2; ks++) {
            const uint32_t kOff = (uint32_t)(ks * 16) * 2;
            uint32_t af[2][4], bh[4][4], bl[4][4];
            #pragma unroll
            for (int mt = 0; mt < 2; mt++)
                ldm4(af[mt], st + OFF_AH + aRow + (uint32_t)(mt * 640) * 2 + kOff);
            #pragma unroll
            for (int np = 0; np < 4; np++) {
                ldm4(bh[np], st + OFF_BH + bRow + (uint32_t)(np * 640) * 2 + kOff);
                ldm4(bl[np], st + OFF_BL + bRow + (uint32_t)(np * 640) * 2 + kOff);
            }
            #pragma unroll
            for (int mt = 0; mt < 2; mt++)
                #pragma unroll
                for (int nt = 0; nt < 8; nt++) {
                    const int np = nt >> 1, sel = nt & 1;
                    mma16816(acc[mt][nt], af[mt], bh[np][sel], bh[np][sel + 2]);
                    mma16816(acc[mt][nt], af[mt], bl[np][sel], bl[np][sel + 2]);
                }
            #pragma unroll
            for (int mt = 0; mt < 2; mt++)
                ldm4(af[mt], st + OFF_AL + aRow + (uint32_t)(mt * 640) * 2 + kOff);
            #pragma unroll
            for (int mt = 0; mt < 2; mt++)
                #pragma unroll
                for (int nt = 0; nt < 8; nt++) {
                    const int np = nt >> 1, sel = nt & 1;
                    mma16816(acc[mt][nt], af[mt], bh[np][sel], bh[np][sel + 2]);
                }
        }
        __syncthreads();
    }

    float* Cp = Cf + (long)bz * 256 * N;
    #pragma unroll
    for (int mt = 0; mt < 2; mt++) {
        const int gm = m0 + wm + mt * 16 + (lane >> 2);
        #pragma unroll
        for (int nt = 0; nt < 8; nt++) {
            const int gn = n0 + wn + nt * 8 + ((lane & 3) << 1);
            *(float2*)(Cp + (long)gm * N + gn) =
                make_float2(acc[mt][nt][0], acc[mt][nt][1]);
            *(float2*)(Cp + (long)(gm + 8) * N + gn) =
                make_float2(acc[mt][nt][2], acc[mt][nt][3]);
        }
    }
}

// ---------------------------------------------------------------------------
// fp16 single-product GEMM geometry (PV + final): CTA 256x128, warp 64x64.
// ---------------------------------------------------------------------------
#define PV_A_B   20480                 // 256 rows * 40 half * 2B
#define PV_B_B   10240                 // 128 rows * 40 half * 2B
#define PV_STAGE (PV_A_B + PV_B_B)     // 30720
#define PV_SMEM  (3*PV_STAGE)          // 92160

// ---------------------------------------------------------------------------
// PV GEMM: fp16 single product. C[bz] = P (256xK) * Vt (128-cols x K).
// Output fp16 ec/sc (row stride 1024).  grid (8, 1, BT), K in {256,512}.
// ---------------------------------------------------------------------------
__global__ __launch_bounds__(256)
void mma_pv(const __half* __restrict__ Pf, const __half* __restrict__ Vt,
            __half* __restrict__ Co, int K, long bBatch, int bDiv)
{
    extern __shared__ char smem[];
    const uint32_t sb = smem_u32(smem);
    const int tid  = threadIdx.x;
    const int wid  = tid >> 5;
    const int lane = tid & 31;
    const int bz = blockIdx.z;
    const int n0 = blockIdx.x * 128;
    const int NCH = K >> 5;

    const long aBase = (long)bz * 256 * K;
    const long bBase = (long)(bz / bDiv) * bBatch + (long)n0 * K;

    const int wm = (wid & 3) * 64;
    const int wn = (wid >> 2) * 64;
    const int laneR  = lane & 15;
    const int laneC8 = (lane >> 4) << 3;
    const uint32_t aRow = (uint32_t)((wm + laneR) * 40 + laneC8) * 2;
    const uint32_t bRow = (uint32_t)((wn + laneR) * 40 + laneC8) * 2;

    const int r0 = tid >> 2, s0 = tid & 3;

    auto issue = [&](int c) {
        const int k0 = c << 5;
        const uint32_t st = sb + (uint32_t)(c % 3) * PV_STAGE;
        #pragma unroll
        for (int j = 0; j < 4; j++) {
            int row = r0 + j * 64;
            cp16(st + (uint32_t)(row * 40 + s0 * 8) * 2,
                 Pf + aBase + (long)row * K + k0 + s0 * 8);
        }
        #pragma unroll
        for (int j = 0; j < 2; j++) {
            int row = r0 + j * 64;
            cp16(st + PV_A_B + (uint32_t)(row * 40 + s0 * 8) * 2,
                 Vt + bBase + (long)row * K + k0 + s0 * 8);
        }
        CP_COMMIT();
    };

    float acc[4][8][4];
    #pragma unroll
    for (int i = 0; i < 4; i++)
        #pragma unroll
        for (int j = 0; j < 8; j++)
            #pragma unroll
            for (int k = 0; k < 4; k++) acc[i][j][k] = 0.0f;

    issue(0); issue(1);

    for (int c = 0; c < NCH; c++) {
        if (c + 1 < NCH) CP_WAIT1(); else CP_WAIT0();
        __syncthreads();
        if (c + 2 < NCH) issue(c + 2);

        const uint32_t st = sb + (uint32_t)(c % 3) * PV_STAGE;
        #pragma unroll
        for (int ks = 0; ks < 2; ks++) {
            const uint32_t kOff = (uint32_t)(ks * 16) * 2;
            uint32_t af[4][4], bf[4][4];
            #pragma unroll
            for (int mt = 0; mt < 4; mt++)
                ldm4(af[mt], st + aRow + (uint32_t)(mt * 640) * 2 + kOff);
            #pragma unroll
            for (int np = 0; np < 4; np++)
                ldm4(bf[np], st + PV_A_B + bRow + (uint32_t)(np * 640) * 2 + kOff);
            #pragma unroll
            for (int mt = 0; mt < 4; mt++)
                #pragma unroll
                for (int nt = 0; nt < 8; nt++) {
                    const int np = nt >> 1, sel = nt & 1;
                    mma16816h(acc[mt][nt], af[mt], bf[np][sel], bf[np][sel + 2]);
                }
        }
        __syncthreads();
    }

    const long cb = (long)bz * 256 * 1024;
    #pragma unroll
    for (int mt = 0; mt < 4; mt++) {
        const int gm = wm + mt * 16 + (lane >> 2);
        #pragma unroll
        for (int nt = 0; nt < 8; nt++) {
            const int gn = n0 + wn + nt * 8 + ((lane & 3) << 1);
            *(__half2*)(Co + cb + (long)gm * 1024 + gn) =
                __floats2half2_rn(acc[mt][nt][0], acc[mt][nt][1]);
            *(__half2*)(Co + cb + (long)(gm + 8) * 1024 + gn) =
                __floats2half2_rn(acc[mt][nt][2], acc[mt][nt][3]);
        }
    }
}

// ---------------------------------------------------------------------------
// Final projection: fp16 single product.
// out = tanh([Q|exc|setc] @ W^T + b).  M=20480, N=1024, K=3072.
// CTA 256x128 (warp 64x64), 3-stage pipeline, 3-piece A select.
// grid (8, 80).
// ---------------------------------------------------------------------------
#define NCHF 96

__global__ __launch_bounds__(256)
void mma_final(const __half* __restrict__ qf, const __half* __restrict__ ecf,
               const __half* __restrict__ scf, const __half* __restrict__ wf,
               const float* __restrict__ bias, float* __restrict__ out)
{
    extern __shared__ char smem[];
    const uint32_t sb = smem_u32(smem);
    const int tid  = threadIdx.x;
    const int wid  = tid >> 5;
    const int lane = tid & 31;
    const long m0 = (long)blockIdx.y * 256;
    const int  n0 = blockIdx.x * 128;

    const int wm = (wid & 3) * 64;
    const int wn = (wid >> 2) * 64;
    const int laneR  = lane & 15;
    const int laneC8 = (lane >> 4) << 3;
    const uint32_t aRow = (uint32_t)((wm + laneR) * 40 + laneC8) * 2;
    const uint32_t bRow = (uint32_t)((wn + laneR) * 40 + laneC8) * 2;

    const int r0 = tid >> 2, s0 = tid & 3;

    auto issue = [&](int c) {
        const int k0 = c << 5;
        const int pc = k0 >> 10;
        const __half* Af = pc == 0 ? qf : (pc == 1 ? ecf : scf);
        const int kin = k0 & 1023;
        const uint32_t st = sb + (uint32_t)(c % 3) * PV_STAGE;
        #pragma unroll
        for (int j = 0; j < 4; j++) {
            int row = r0 + j * 64;
            cp16(st + (uint32_t)(row * 40 + s0 * 8) * 2,
                 Af + (m0 + row) * 1024 + kin + s0 * 8);
        }
        #pragma unroll
        for (int j = 0; j < 2; j++) {
            int row = r0 + j * 64;
            cp16(st + PV_A_B + (uint32_t)(row * 40 + s0 * 8) * 2,
                 wf + (long)(n0 + row) * 3072 + k0 + s0 * 8);
        }
        CP_COMMIT();
    };

    float acc[4][8][4];
    #pragma unroll
    for (int i = 0; i < 4; i++)
        #pragma unroll
        for (int j = 0; j < 8; j++)
            #pragma unroll
            for (int k = 0; k < 4; k++) acc[i][j][k] = 0.0f;

    issue(0); issue(1);

    for (int c = 0; c < NCHF; c++) {
        if (c + 1 < NCHF) CP_WAIT1(); else CP_WAIT0();
        __syncthreads();
        if (c + 2 < NCHF) issue(c + 2);

        const uint32_t st = sb + (uint32_t)(c % 3) * PV_STAGE;
        #pragma unroll
        for (int ks = 0; ks < 2; ks++) {
            const uint32_t kOff = (uint32_t)(ks * 16) * 2;
            uint32_t af[4][4], bf[4][4];
            #pragma unroll
            for (int mt = 0; mt < 4; mt++)
                ldm4(af[mt], st + aRow + (uint32_t)(mt * 640) * 2 + kOff);
            #pragma unroll
            for (int np = 0; np < 4; np++)
                ldm4(bf[np], st + PV_A_B + bRow + (uint32_t)(np * 640) * 2 + kOff);
            #pragma unroll
            for (int mt = 0; mt < 4; mt++)
                #pragma unroll
                for (int nt = 0; nt < 8; nt++) {
                    const int np = nt >> 1, sel = nt & 1;
                    mma16816h(acc[mt][nt], af[mt], bf[np][sel], bf[np][sel + 2]);
                }
        }
        __syncthreads();
    }

    #pragma unroll
    for (int mt = 0; mt < 4; mt++) {
        const long gm = m0 + wm + mt * 16 + (lane >> 2);
        #pragma unroll
        for (int nt = 0; nt < 8; nt++) {
            const int gn = n0 + wn + nt * 8 + ((lane & 3) << 1);
            const float b0 = bias[gn], b1 = bias[gn + 1];
            *(float2*)(out + gm * 1024 + gn) =
                make_float2(tanhf(acc[mt][nt][0] + b0), tanhf(acc[mt][nt][1] + b1));
            *(float2*)(out + (gm + 8) * 1024 + gn) =
                make_float2(tanhf(acc[mt][nt][2] + b0), tanhf(acc[mt][nt][3] + b1));
        }
    }
}

// ---------------------------------------------------------------------------
extern "C" void kernel_launch(void* const* d_in, const int* in_sizes, int n_in,
                              void* d_out, int out_size)
{
    const float* Q  = (const float*)d_in[0];
    const float* C0 = (const float*)d_in[1];
    const float* C1 = (const float*)d_in[2];
    // d_in[3] = mask (unused, faithful to reference)
    const float* W  = (const float*)d_in[4];
    const float* bb = (const float*)d_in[5];

    float* OUT = (float*)d_out;
    float* EXA = OUT + (long)BT * LQ * HD;
    float* SEA = EXA + (long)BT * LQ * LQ;

    #define SYM(t, v, s) void* p_##v; cudaGetSymbolAddress(&p_##v, s); \
                         t* v = (t*)p_##v
    SYM(__nv_bfloat16, qh,  g_qh);  SYM(__nv_bfloat16, ql,  g_ql);
    SYM(__nv_bfloat16, c0h, g_c0h); SYM(__nv_bfloat16, c0l, g_c0l);
    SYM(__nv_bfloat16, c1h, g_c1h); SYM(__nv_bfloat16, c1l, g_c1l);
    SYM(__half, qf,  g_qf);  SYM(__half, wf,  g_wf);
    SYM(__half, ecf, g_ecf); SYM(__half, scf, g_scf);
    SYM(__half, pef, g_pef); SYM(__half, psf, g_psf);
    SYM(__half, t0f, g_t0f); SYM(__half, t1f, g_t1f);
    #undef SYM

    cudaFuncSetAttribute(mma_nt,    cudaFuncAttributeMaxDynamicSharedMemorySize, MM_SMEM);
    cudaFuncSetAttribute(mma_pv,    cudaFuncAttributeMaxDynamicSharedMemorySize, PV_SMEM);
    cudaFuncSetAttribute(mma_final, cudaFuncAttributeMaxDynamicSharedMemorySize, PV_SMEM);

    // conversions
    split_bf16<<<(BT*LQ*HD)/1024, 256>>>(Q,  qh,  ql);
    split_bf16<<<(BT*LQ*HD)/1024, 256>>>(C0, c0h, c0l);
    split_bf16<<<(8*SS*HD)/1024, 256>>>(C1, c1h, c1l);
    copy_f16<<<(BT*LQ*HD)/1024, 256>>>(Q, qf);
    copy_f16<<<(HD*3*HD)/1024, 256>>>(W, wf);
    tsplit_f16<<<dim3(LQ/32, 32, BT), dim3(32, 8)>>>(C0, t0f, LQ);
    tsplit_f16<<<dim3(SS/32, 32, 8),  dim3(32, 8)>>>(C1, t1f, SS);

    // logits (bf16 3-product, exact-grade)
    mma_nt<<<dim3(2, 2, BT), 256, MM_SMEM>>>(qh, ql, c0h, c0l, EXA,
                                             HD, LQ, (long)LQ*HD, 1);
    mma_nt<<<dim3(4, 2, BT), 256, MM_SMEM>>>(qh, ql, c1h, c1l, SEA,
                                             HD, SS, (long)SS*HD, 10);

    // softmax in place + fp16 prob copy
    softmax_rows<<<BT * LQ, 256>>>(EXA, pef, LQ);
    softmax_rows<<<BT * LQ, 256>>>(SEA, psf, SS);

    // attn @ V (fp16 single product -> fp16 ec/sc)
    mma_pv<<<dim3(8, 1, BT), 256, PV_SMEM>>>(pef, t0f, ecf, LQ, (long)HD*LQ, 1);
    mma_pv<<<dim3(8, 1, BT), 256, PV_SMEM>>>(psf, t1f, scf, SS, (long)HD*SS, 10);

    // final projection (fp16 single product)
    mma_final<<<dim3(8, 80), 256, PV_SMEM>>>(qf, ecf, scf, wf, bb, OUT);
}

// round 10
// speedup vs baseline: 3.6897x; 1.1077x over previous
#include <cuda_runtime.h>
#include <cuda_bf16.h>
#include <cuda_fp16.h>
#include <cstdint>

#define BT 80
#define LQ 256
#define SS 512
#define HD 1024

// ---------------- scratch (device globals; allocation-free rule) -----------
__device__ __nv_bfloat16 g_qh[(size_t)BT*LQ*HD],  g_ql[(size_t)BT*LQ*HD];
__device__ __nv_bfloat16 g_c0h[(size_t)BT*LQ*HD], g_c0l[(size_t)BT*LQ*HD];
__device__ __nv_bfloat16 g_c1h[(size_t)8*SS*HD],  g_c1l[(size_t)8*SS*HD];
__device__ __half g_qf[(size_t)BT*LQ*HD];
__device__ __half g_wf[(size_t)HD*3*HD];
__device__ __half g_ecf[(size_t)BT*LQ*HD], g_scf[(size_t)BT*LQ*HD];
__device__ __half g_pef[(size_t)BT*LQ*LQ], g_psf[(size_t)BT*LQ*SS];
__device__ __half g_t0f[(size_t)BT*HD*LQ], g_t1f[(size_t)8*HD*SS];

// ---------------- portable PTX helpers -------------------------------------
__device__ __forceinline__ uint32_t smem_u32(const void* p) {
    uint32_t a;
    asm("{ .reg .u64 t; cvta.to.shared.u64 t, %1; cvt.u32.u64 %0, t; }" : "=r"(a) : "l"(p));
    return a;
}
__device__ __forceinline__ void cp16(uint32_t dst, const void* src) {
    asm volatile("cp.async.cg.shared.global [%0], [%1], 16;" :: "r"(dst), "l"(src));
}
#define CP_COMMIT() asm volatile("cp.async.commit_group;" ::: "memory")
#define CP_WAIT1()  asm volatile("cp.async.wait_group 1;" ::: "memory")
#define CP_WAIT0()  asm volatile("cp.async.wait_group 0;" ::: "memory")

__device__ __forceinline__ void ldm4(uint32_t* r, uint32_t addr) {
    asm volatile("ldmatrix.sync.aligned.m8n8.x4.shared.b16 {%0,%1,%2,%3}, [%4];"
        : "=r"(r[0]), "=r"(r[1]), "=r"(r[2]), "=r"(r[3]) : "r"(addr));
}
__device__ __forceinline__ void mma16816(float* c, const uint32_t* a,
                                         uint32_t b0, uint32_t b1) {
    asm volatile(
        "mma.sync.aligned.m16n8k16.row.col.f32.bf16.bf16.f32 "
        "{%0,%1,%2,%3}, {%4,%5,%6,%7}, {%8,%9}, {%0,%1,%2,%3};"
        : "+f"(c[0]), "+f"(c[1]), "+f"(c[2]), "+f"(c[3])
        : "r"(a[0]), "r"(a[1]), "r"(a[2]), "r"(a[3]), "r"(b0), "r"(b1));
}
__device__ __forceinline__ void mma16816h(float* c, const uint32_t* a,
                                          uint32_t b0, uint32_t b1) {
    asm volatile(
        "mma.sync.aligned.m16n8k16.row.col.f32.f16.f16.f32 "
        "{%0,%1,%2,%3}, {%4,%5,%6,%7}, {%8,%9}, {%0,%1,%2,%3};"
        : "+f"(c[0]), "+f"(c[1]), "+f"(c[2]), "+f"(c[3])
        : "r"(a[0]), "r"(a[1]), "r"(a[2]), "r"(a[3]), "r"(b0), "r"(b1));
}
__device__ __forceinline__ void split1(float v, __nv_bfloat16& h, __nv_bfloat16& l) {
    h = __float2bfloat16(v);
    l = __float2bfloat16(v - __bfloat162float(h));
}

// ---------------------------------------------------------------------------
// Q: fp32 -> bf16 hi/lo + fp16 in one pass (4 elems/thread)
// ---------------------------------------------------------------------------
__global__ void conv_q(const float* __restrict__ x,
                       __nv_bfloat16* __restrict__ h,
                       __nv_bfloat16* __restrict__ l,
                       __half* __restrict__ f)
{
    long i = ((long)blockIdx.x * blockDim.x + threadIdx.x) * 4;
    float4 v = *(const float4*)(x + i);
    float vv[4] = {v.x, v.y, v.z, v.w};
    __nv_bfloat16 hh[4], ll[4];
    #pragma unroll
    for (int j = 0; j < 4; j++) split1(vv[j], hh[j], ll[j]);
    *(__nv_bfloat162*)(h + i)     = __nv_bfloat162(hh[0], hh[1]);
    *(__nv_bfloat162*)(h + i + 2) = __nv_bfloat162(hh[2], hh[3]);
    *(__nv_bfloat162*)(l + i)     = __nv_bfloat162(ll[0], ll[1]);
    *(__nv_bfloat162*)(l + i + 2) = __nv_bfloat162(ll[2], ll[3]);
    *(__half2*)(f + i)     = __floats2half2_rn(v.x, v.y);
    *(__half2*)(f + i + 2) = __floats2half2_rn(v.z, v.w);
}

// ---------------------------------------------------------------------------
// W: fp32 -> fp16 copy
// ---------------------------------------------------------------------------
__global__ void conv_w(const float* __restrict__ x, __half* __restrict__ f)
{
    long i = ((long)blockIdx.x * blockDim.x + threadIdx.x) * 4;
    float4 v = *(const float4*)(x + i);
    *(__half2*)(f + i)     = __floats2half2_rn(v.x, v.y);
    *(__half2*)(f + i + 2) = __floats2half2_rn(v.z, v.w);
}

// ---------------------------------------------------------------------------
// Context: one pass -> bf16 hi/lo (straight) + fp16 (transposed)
// x [B][S][1024] -> h/l same layout, tf [B][1024][S]
// block (32,8), grid (S/32, 32, B)
// ---------------------------------------------------------------------------
__global__ void conv_ctx(const float* __restrict__ x,
                         __nv_bfloat16* __restrict__ h,
                         __nv_bfloat16* __restrict__ l,
                         __half* __restrict__ tf, int S)
{
    __shared__ float t[32][33];
    const int b  = blockIdx.z;
    const int s0 = blockIdx.x * 32;
    const int d0 = blockIdx.y * 32;
    const int tx = threadIdx.x, ty = threadIdx.y;

    const float* xp = x + (long)b * S * 1024;
    #pragma unroll
    for (int r = 0; r < 4; r++) {
        int s = ty + r * 8;
        float v = xp[(long)(s0 + s) * 1024 + d0 + tx];
        t[s][tx] = v;
        __nv_bfloat16 hh, ll;
        split1(v, hh, ll);
        long off = ((long)b * S + s0 + s) * 1024 + d0 + tx;
        h[off] = hh; l[off] = ll;
    }
    __syncthreads();
    const long ob = (long)b * 1024 * S;
    #pragma unroll
    for (int r = 0; r < 4; r++) {
        int d = ty + r * 8;
        tf[ob + (long)(d0 + d) * S + s0 + tx] = __float2half(t[tx][d]);
    }
}

// ---------------------------------------------------------------------------
// Combined softmax: grid.x = 2*20480.  bid<20480: EXA row (n=256),
// else SEA row (n=512).  Warp-shuffle reductions, 2 barriers.
// ---------------------------------------------------------------------------
__global__ void softmax2(float* __restrict__ exa, __half* __restrict__ pef,
                         float* __restrict__ sea, __half* __restrict__ psf)
{
    __shared__ float wm[8], ws[8];
    const int bid = blockIdx.x;
    const int tid = threadIdx.x;
    const int lane = tid & 31, wid = tid >> 5;

    float* p; __half* pf; int n;
    if (bid < BT * LQ) {
        p = exa + (long)bid * LQ;  pf = pef + (long)bid * LQ;  n = LQ;
    } else {
        const int r = bid - BT * LQ;
        p = sea + (long)r * SS;    pf = psf + (long)r * SS;    n = SS;
    }

    float v0 = p[tid];
    float v1 = (n > 256) ? p[tid + 256] : -3.402823e38f;

    float m = fmaxf(v0, v1);
    #pragma unroll
    for (int o = 16; o > 0; o >>= 1) m = fmaxf(m, __shfl_xor_sync(~0u, m, o));
    if (lane == 0) wm[wid] = m;
    __syncthreads();
    float mx = wm[0];
    #pragma unroll
    for (int i = 1; i < 8; i++) mx = fmaxf(mx, wm[i]);

    float e0 = __expf(v0 - mx);
    float e1 = (n > 256) ? __expf(v1 - mx) : 0.0f;
    float s = e0 + e1;
    #pragma unroll
    for (int o = 16; o > 0; o >>= 1) s += __shfl_xor_sync(~0u, s, o);
    if (lane == 0) ws[wid] = s;
    __syncthreads();
    float tot = ws[0];
    #pragma unroll
    for (int i = 1; i < 8; i++) tot += ws[i];
    const float inv = 1.0f / tot;

    float p0 = e0 * inv;
    p[tid] = p0; pf[tid] = __float2half(p0);
    if (n > 256) {
        float p1 = e1 * inv;
        p[tid + 256] = p1; pf[tid + 256] = __float2half(p1);
    }
}

// ---------------------------------------------------------------------------
// bf16-split logits geometry
// ---------------------------------------------------------------------------
#define TILE_B   10240
#define OFF_AH   0
#define OFF_AL   (TILE_B)
#define OFF_BH   (2*TILE_B)
#define OFF_BL   (3*TILE_B)
#define STAGE_B  (4*TILE_B)
#define MM_SMEM  (3*STAGE_B)           // 122880

// ---------------------------------------------------------------------------
// Combined logits: grid (6, 2, 80).  bx<2 -> ex branch (N=256), else set
// (N=512).  K=1024 for both (identical per-CTA cost).  bf16 3-product.
// ---------------------------------------------------------------------------
__global__ __launch_bounds__(256)
void mma_logits(const __nv_bfloat16* __restrict__ Ah, const __nv_bfloat16* __restrict__ Al,
                const __nv_bfloat16* __restrict__ c0h, const __nv_bfloat16* __restrict__ c0l,
                const __nv_bfloat16* __restrict__ c1h, const __nv_bfloat16* __restrict__ c1l,
                float* __restrict__ exa, float* __restrict__ sea)
{
    extern __shared__ char smem[];
    const uint32_t sb = smem_u32(smem);
    const int tid  = threadIdx.x;
    const int wid  = tid >> 5;
    const int lane = tid & 31;
    const int bz = blockIdx.z;
    const int m0 = blockIdx.y * 128;

    const bool isSet = blockIdx.x >= 2;
    const int  n0 = (isSet ? blockIdx.x - 2 : blockIdx.x) * 128;
    const int  N  = isSet ? SS : LQ;
    const __nv_bfloat16* Bh = isSet ? c1h : c0h;
    const __nv_bfloat16* Bl = isSet ? c1l : c0l;
    float* Cf = isSet ? sea : exa;
    const long bBatch = isSet ? (long)SS * HD : (long)LQ * HD;
    const int  bDiv   = isSet ? 10 : 1;
    const int  K = HD;                  // 1024 both branches
    const int  NCH = K >> 5;            // 32

    const long aBase = (long)bz * 256 * K + (long)m0 * K;
    const long bBase = (long)(bz / bDiv) * bBatch + (long)n0 * K;

    const int wm = (wid & 3) * 32;
    const int wn = (wid >> 2) * 64;
    const int laneR  = lane & 15;
    const int laneC8 = (lane >> 4) << 3;
    const uint32_t aRow = (uint32_t)((wm + laneR) * 40 + laneC8) * 2;
    const uint32_t bRow = (uint32_t)((wn + laneR) * 40 + laneC8) * 2;

    const int r0 = tid >> 2, s0 = tid & 3;
    const int r1 = r0 + 64;

    auto issue = [&](int c) {
        const int k0 = c << 5;
        const uint32_t st = sb + (uint32_t)(c % 3) * STAGE_B;
        uint32_t so0 = (uint32_t)(r0 * 40 + s0 * 8) * 2;
        uint32_t so1 = (uint32_t)(r1 * 40 + s0 * 8) * 2;
        long ao0 = aBase + (long)r0 * K + k0 + s0 * 8;
        long ao1 = aBase + (long)r1 * K + k0 + s0 * 8;
        long bo0 = bBase + (long)r0 * K + k0 + s0 * 8;
        long bo1 = bBase + (long)r1 * K + k0 + s0 * 8;
        cp16(st + OFF_AH + so0, Ah + ao0);
        cp16(st + OFF_AH + so1, Ah + ao1);
        cp16(st + OFF_AL + so0, Al + ao0);
        cp16(st + OFF_AL + so1, Al + ao1);
        cp16(st + OFF_BH + so0, Bh + bo0);
        cp16(st + OFF_BH + so1, Bh + bo1);
        cp16(st + OFF_BL + so0, Bl + bo0);
        cp16(st + OFF_BL + so1, Bl + bo1);
        CP_COMMIT();
    };

    float acc[2][8][4];
    #pragma unroll
    for (int i = 0; i < 2; i++)
        #pragma unroll
        for (int j = 0; j < 8; j++)
            #pragma unroll
            for (int k = 0; k < 4; k++) acc[i][j][k] = 0.0f;

    issue(0); issue(1);

    for (int c = 0; c < NCH; c++) {
        if (c + 1 < NCH) CP_WAIT1(); else CP_WAIT0();
        __syncthreads();
        if (c + 2 < NCH) issue(c + 2);

        const uint32_t st = sb + (uint32_t)(c % 3) * STAGE_B;
        #pragma unroll
        for (int ks = 0; ks < 2; ks++) {
            const uint32_t kOff = (uint32_t)(ks * 16) * 2;
            uint32_t af[2][4], bh[4][4], bl[4][4];
            #pragma unroll
            for (int mt = 0; mt < 2; mt++)
                ldm4(af[mt], st + OFF_AH + aRow + (uint32_t)(mt * 640) * 2 + kOff);
            #pragma unroll
            for (int np = 0; np < 4; np++) {
                ldm4(bh[np], st + OFF_BH + bRow + (uint32_t)(np * 640) * 2 + kOff);
                ldm4(bl[np], st + OFF_BL + bRow + (uint32_t)(np * 640) * 2 + kOff);
            }
            #pragma unroll
            for (int mt = 0; mt < 2; mt++)
                #pragma unroll
                for (int nt = 0; nt < 8; nt++) {
                    const int np = nt >> 1, sel = nt & 1;
                    mma16816(acc[mt][nt], af[mt], bh[np][sel], bh[np][sel + 2]);
                    mma16816(acc[mt][nt], af[mt], bl[np][sel], bl[np][sel + 2]);
                }
            #pragma unroll
            for (int mt = 0; mt < 2; mt++)
                ldm4(af[mt], st + OFF_AL + aRow + (uint32_t)(mt * 640) * 2 + kOff);
            #pragma unroll
            for (int mt = 0; mt < 2; mt++)
                #pragma unroll
                for (int nt = 0; nt < 8; nt++) {
                    const int np = nt >> 1, sel = nt & 1;
                    mma16816(acc[mt][nt], af[mt], bh[np][sel], bh[np][sel + 2]);
                }
        }
        __syncthreads();
    }

    float* Cp = Cf + (long)bz * 256 * N;
    #pragma unroll
    for (int mt = 0; mt < 2; mt++) {
        const int gm = m0 + wm + mt * 16 + (lane >> 2);
        #pragma unroll
        for (int nt = 0; nt < 8; nt++) {
            const int gn = n0 + wn + nt * 8 + ((lane & 3) << 1);
            *(float2*)(Cp + (long)gm * N + gn) =
                make_float2(acc[mt][nt][0], acc[mt][nt][1]);
            *(float2*)(Cp + (long)(gm + 8) * N + gn) =
                make_float2(acc[mt][nt][2], acc[mt][nt][3]);
        }
    }
}

// ---------------------------------------------------------------------------
// fp16 single-product geometry (PV + final): CTA 256x128, warp 64x64.
// ---------------------------------------------------------------------------
#define PV_A_B   20480
#define PV_B_B   10240
#define PV_STAGE (PV_A_B + PV_B_B)
#define PV_SMEM  (3*PV_STAGE)          // 92160

// ---------------------------------------------------------------------------
// Combined PV: grid (16, 1, 80).  bx<8 -> ex (K=256), else set (K=512).
// C[bz] = P (256xK) * Vt (128-cols x K) -> fp16 ec/sc (row stride 1024).
// ---------------------------------------------------------------------------
__global__ __launch_bounds__(256)
void mma_pv(const __half* __restrict__ pef, const __half* __restrict__ t0f,
            __half* __restrict__ ecf,
            const __half* __restrict__ psf, const __half* __restrict__ t1f,
            __half* __restrict__ scf)
{
    extern __shared__ char smem[];
    const uint32_t sb = smem_u32(smem);
    const int tid  = threadIdx.x;
    const int wid  = tid >> 5;
    const int lane = tid & 31;
    const int bz = blockIdx.z;

    const bool isSet = blockIdx.x >= 8;
    const int  n0 = (isSet ? blockIdx.x - 8 : blockIdx.x) * 128;
    const int  K  = isSet ? SS : LQ;
    const __half* Pf = isSet ? psf : pef;
    const __half* Vt = isSet ? t1f : t0f;
    __half* Co = isSet ? scf : ecf;
    const long bBatch = isSet ? (long)HD * SS : (long)HD * LQ;
    const int  bDiv   = isSet ? 10 : 1;
    const int  NCH = K >> 5;

    const long aBase = (long)bz * 256 * K;
    const long bBase = (long)(bz / bDiv) * bBatch + (long)n0 * K;

    const int wm = (wid & 3) * 64;
    const int wn = (wid >> 2) * 64;
    const int laneR  = lane & 15;
    const int laneC8 = (lane >> 4) << 3;
    const uint32_t aRow = (uint32_t)((wm + laneR) * 40 + laneC8) * 2;
    const uint32_t bRow = (uint32_t)((wn + laneR) * 40 + laneC8) * 2;

    const int r0 = tid >> 2, s0 = tid & 3;

    auto issue = [&](int c) {
        const int k0 = c << 5;
        const uint32_t st = sb + (uint32_t)(c % 3) * PV_STAGE;
        #pragma unroll
        for (int j = 0; j < 4; j++) {
            int row = r0 + j * 64;
            cp16(st + (uint32_t)(row * 40 + s0 * 8) * 2,
                 Pf + aBase + (long)row * K + k0 + s0 * 8);
        }
        #pragma unroll
        for (int j = 0; j < 2; j++) {
            int row = r0 + j * 64;
            cp16(st + PV_A_B + (uint32_t)(row * 40 + s0 * 8) * 2,
                 Vt + bBase + (long)row * K + k0 + s0 * 8);
        }
        CP_COMMIT();
    };

    float acc[4][8][4];
    #pragma unroll
    for (int i = 0; i < 4; i++)
        #pragma unroll
        for (int j = 0; j < 8; j++)
            #pragma unroll
            for (int k = 0; k < 4; k++) acc[i][j][k] = 0.0f;

    issue(0); issue(1);

    for (int c = 0; c < NCH; c++) {
        if (c + 1 < NCH) CP_WAIT1(); else CP_WAIT0();
        __syncthreads();
        if (c + 2 < NCH) issue(c + 2);

        const uint32_t st = sb + (uint32_t)(c % 3) * PV_STAGE;
        #pragma unroll
        for (int ks = 0; ks < 2; ks++) {
            const uint32_t kOff = (uint32_t)(ks * 16) * 2;
            uint32_t af[4][4], bf[4][4];
            #pragma unroll
            for (int mt = 0; mt < 4; mt++)
                ldm4(af[mt], st + aRow + (uint32_t)(mt * 640) * 2 + kOff);
            #pragma unroll
            for (int np = 0; np < 4; np++)
                ldm4(bf[np], st + PV_A_B + bRow + (uint32_t)(np * 640) * 2 + kOff);
            #pragma unroll
            for (int mt = 0; mt < 4; mt++)
                #pragma unroll
                for (int nt = 0; nt < 8; nt++) {
                    const int np = nt >> 1, sel = nt & 1;
                    mma16816h(acc[mt][nt], af[mt], bf[np][sel], bf[np][sel + 2]);
                }
        }
        __syncthreads();
    }

    const long cb = (long)bz * 256 * 1024;
    #pragma unroll
    for (int mt = 0; mt < 4; mt++) {
        const int gm = wm + mt * 16 + (lane >> 2);
        #pragma unroll
        for (int nt = 0; nt < 8; nt++) {
            const int gn = n0 + wn + nt * 8 + ((lane & 3) << 1);
            *(__half2*)(Co + cb + (long)gm * 1024 + gn) =
                __floats2half2_rn(acc[mt][nt][0], acc[mt][nt][1]);
            *(__half2*)(Co + cb + (long)(gm + 8) * 1024 + gn) =
                __floats2half2_rn(acc[mt][nt][2], acc[mt][nt][3]);
        }
    }
}

// ---------------------------------------------------------------------------
// Final projection: fp16 single product, CTA 256x128, 3-piece A select.
// out = tanh([Q|exc|setc] @ W^T + b).  grid (8, 80).
// ---------------------------------------------------------------------------
#define NCHF 96

__global__ __launch_bounds__(256)
void mma_final(const __half* __restrict__ qf, const __half* __restrict__ ecf,
               const __half* __restrict__ scf, const __half* __restrict__ wf,
               const float* __restrict__ bias, float* __restrict__ out)
{
    extern __shared__ char smem[];
    const uint32_t sb = smem_u32(smem);
    const int tid  = threadIdx.x;
    const int wid  = tid >> 5;
    const int lane = tid & 31;
    const long m0 = (long)blockIdx.y * 256;
    const int  n0 = blockIdx.x * 128;

    const int wm = (wid & 3) * 64;
    const int wn = (wid >> 2) * 64;
    const int laneR  = lane & 15;
    const int laneC8 = (lane >> 4) << 3;
    const uint32_t aRow = (uint32_t)((wm + laneR) * 40 + laneC8) * 2;
    const uint32_t bRow = (uint32_t)((wn + laneR) * 40 + laneC8) * 2;

    const int r0 = tid >> 2, s0 = tid & 3;

    auto issue = [&](int c) {
        const int k0 = c << 5;
        const int pc = k0 >> 10;
        const __half* Af = pc == 0 ? qf : (pc == 1 ? ecf : scf);
        const int kin = k0 & 1023;
        const uint32_t st = sb + (uint32_t)(c % 3) * PV_STAGE;
        #pragma unroll
        for (int j = 0; j < 4; j++) {
            int row = r0 + j * 64;
            cp16(st + (uint32_t)(row * 40 + s0 * 8) * 2,
                 Af + (m0 + row) * 1024 + kin + s0 * 8);
        }
        #pragma unroll
        for (int j = 0; j < 2; j++) {
            int row = r0 + j * 64;
            cp16(st + PV_A_B + (uint32_t)(row * 40 + s0 * 8) * 2,
                 wf + (long)(n0 + row) * 3072 + k0 + s0 * 8);
        }
        CP_COMMIT();
    };

    float acc[4][8][4];
    #pragma unroll
    for (int i = 0; i < 4; i++)
        #pragma unroll
        for (int j = 0; j < 8; j++)
            #pragma unroll
            for (int k = 0; k < 4; k++) acc[i][j][k] = 0.0f;

    issue(0); issue(1);

    for (int c = 0; c < NCHF; c++) {
        if (c + 1 < NCHF) CP_WAIT1(); else CP_WAIT0();
        __syncthreads();
        if (c + 2 < NCHF) issue(c + 2);

        const uint32_t st = sb + (uint32_t)(c % 3) * PV_STAGE;
        #pragma unroll
        for (int ks = 0; ks < 2; ks++) {
            const uint32_t kOff = (uint32_t)(ks * 16) * 2;
            uint32_t af[4][4], bf[4][4];
            #pragma unroll
            for (int mt = 0; mt < 4; mt++)
                ldm4(af[mt], st + aRow + (uint32_t)(mt * 640) * 2 + kOff);
            #pragma unroll
            for (int np = 0; np < 4; np++)
                ldm4(bf[np], st + PV_A_B + bRow + (uint32_t)(np * 640) * 2 + kOff);
            #pragma unroll
            for (int mt = 0; mt < 4; mt++)
                #pragma unroll
                for (int nt = 0; nt < 8; nt++) {
                    const int np = nt >> 1, sel = nt & 1;
                    mma16816h(acc[mt][nt], af[mt], bf[np][sel], bf[np][sel + 2]);
                }
        }
        __syncthreads();
    }

    #pragma unroll
    for (int mt = 0; mt < 4; mt++) {
        const long gm = m0 + wm + mt * 16 + (lane >> 2);
        #pragma unroll
        for (int nt = 0; nt < 8; nt++) {
            const int gn = n0 + wn + nt * 8 + ((lane & 3) << 1);
            const float b0 = bias[gn], b1 = bias[gn + 1];
            *(float2*)(out + gm * 1024 + gn) =
                make_float2(tanhf(acc[mt][nt][0] + b0), tanhf(acc[mt][nt][1] + b1));
            *(float2*)(out + (gm + 8) * 1024 + gn) =
                make_float2(tanhf(acc[mt][nt][2] + b0), tanhf(acc[mt][nt][3] + b1));
        }
    }
}

// ---------------------------------------------------------------------------
extern "C" void kernel_launch(void* const* d_in, const int* in_sizes, int n_in,
                              void* d_out, int out_size)
{
    const float* Q  = (const float*)d_in[0];
    const float* C0 = (const float*)d_in[1];
    const float* C1 = (const float*)d_in[2];
    // d_in[3] = mask (unused, faithful to reference)
    const float* W  = (const float*)d_in[4];
    const float* bb = (const float*)d_in[5];

    float* OUT = (float*)d_out;
    float* EXA = OUT + (long)BT * LQ * HD;
    float* SEA = EXA + (long)BT * LQ * LQ;

    #define SYM(t, v, s) void* p_##v; cudaGetSymbolAddress(&p_##v, s); \
                         t* v = (t*)p_##v
    SYM(__nv_bfloat16, qh,  g_qh);  SYM(__nv_bfloat16, ql,  g_ql);
    SYM(__nv_bfloat16, c0h, g_c0h); SYM(__nv_bfloat16, c0l, g_c0l);
    SYM(__nv_bfloat16, c1h, g_c1h); SYM(__nv_bfloat16, c1l, g_c1l);
    SYM(__half, qf,  g_qf);  SYM(__half, wf,  g_wf);
    SYM(__half, ecf, g_ecf); SYM(__half, scf, g_scf);
    SYM(__half, pef, g_pef); SYM(__half, psf, g_psf);
    SYM(__half, t0f, g_t0f); SYM(__half, t1f, g_t1f);
    #undef SYM

    cudaFuncSetAttribute(mma_logits, cudaFuncAttributeMaxDynamicSharedMemorySize, MM_SMEM);
    cudaFuncSetAttribute(mma_pv,     cudaFuncAttributeMaxDynamicSharedMemorySize, PV_SMEM);
    cudaFuncSetAttribute(mma_final,  cudaFuncAttributeMaxDynamicSharedMemorySize, PV_SMEM);

    // fused conversions
    conv_q<<<(BT*LQ*HD)/1024, 256>>>(Q, qh, ql, qf);
    conv_w<<<(HD*3*HD)/1024, 256>>>(W, wf);
    conv_ctx<<<dim3(LQ/32, 32, BT), dim3(32, 8)>>>(C0, c0h, c0l, t0f, LQ);
    conv_ctx<<<dim3(SS/32, 32, 8),  dim3(32, 8)>>>(C1, c1h, c1l, t1f, SS);

    // logits (combined ex+set, bf16 3-product)
    mma_logits<<<dim3(6, 2, BT), 256, MM_SMEM>>>(qh, ql, c0h, c0l, c1h, c1l, EXA, SEA);

    // softmax (combined), in place + fp16 prob copy
    softmax2<<<2 * BT * LQ, 256>>>(EXA, pef, SEA, psf);

    // attn @ V (combined ex+set, fp16 single product)
    mma_pv<<<dim3(16, 1, BT), 256, PV_SMEM>>>(pef, t0f, ecf, psf, t1f, scf);

    // final projection (fp16 single product)
    mma_final<<<dim3(8, 80), 256, PV_SMEM>>>(qf, ecf, scf, wf, bb, OUT);
}

// round 15
// speedup vs baseline: 3.7062x; 1.0045x over previous
#include <cuda_runtime.h>
#include <cuda_bf16.h>
#include <cuda_fp16.h>
#include <cstdint>

#define BT 80
#define LQ 256
#define SS 512
#define HD 1024

// ---------------- scratch (device globals; allocation-free rule) -----------
__device__ __nv_bfloat16 g_qh[(size_t)BT*LQ*HD],  g_ql[(size_t)BT*LQ*HD];
__device__ __nv_bfloat16 g_c0h[(size_t)BT*LQ*HD], g_c0l[(size_t)BT*LQ*HD];
__device__ __nv_bfloat16 g_c1h[(size_t)8*SS*HD],  g_c1l[(size_t)8*SS*HD];
__device__ __half g_qf[(size_t)BT*LQ*HD];
__device__ __half g_wf[(size_t)HD*3*HD];
__device__ __half g_ecf[(size_t)BT*LQ*HD], g_scf[(size_t)BT*LQ*HD];
__device__ __half g_pef[(size_t)BT*LQ*LQ], g_psf[(size_t)BT*LQ*SS];
__device__ __half g_t0f[(size_t)BT*HD*LQ], g_t1f[(size_t)8*HD*SS];
__device__ float  g_part[(size_t)BT*LQ*HD];   // Q @ W1 fp32 partial

// ---------------- portable PTX helpers -------------------------------------
__device__ __forceinline__ uint32_t smem_u32(const void* p) {
    uint32_t a;
    asm("{ .reg .u64 t; cvta.to.shared.u64 t, %1; cvt.u32.u64 %0, t; }" : "=r"(a) : "l"(p));
    return a;
}
__device__ __forceinline__ void cp16(uint32_t dst, const void* src) {
    asm volatile("cp.async.cg.shared.global [%0], [%1], 16;" :: "r"(dst), "l"(src));
}
#define CP_COMMIT() asm volatile("cp.async.commit_group;" ::: "memory")
#define CP_WAIT1()  asm volatile("cp.async.wait_group 1;" ::: "memory")
#define CP_WAIT0()  asm volatile("cp.async.wait_group 0;" ::: "memory")

__device__ __forceinline__ void ldm4(uint32_t* r, uint32_t addr) {
    asm volatile("ldmatrix.sync.aligned.m8n8.x4.shared.b16 {%0,%1,%2,%3}, [%4];"
        : "=r"(r[0]), "=r"(r[1]), "=r"(r[2]), "=r"(r[3]) : "r"(addr));
}
__device__ __forceinline__ void mma16816(float* c, const uint32_t* a,
                                         uint32_t b0, uint32_t b1) {
    asm volatile(
        "mma.sync.aligned.m16n8k16.row.col.f32.bf16.bf16.f32 "
        "{%0,%1,%2,%3}, {%4,%5,%6,%7}, {%8,%9}, {%0,%1,%2,%3};"
        : "+f"(c[0]), "+f"(c[1]), "+f"(c[2]), "+f"(c[3])
        : "r"(a[0]), "r"(a[1]), "r"(a[2]), "r"(a[3]), "r"(b0), "r"(b1));
}
__device__ __forceinline__ void mma16816h(float* c, const uint32_t* a,
                                          uint32_t b0, uint32_t b1) {
    asm volatile(
        "mma.sync.aligned.m16n8k16.row.col.f32.f16.f16.f32 "
        "{%0,%1,%2,%3}, {%4,%5,%6,%7}, {%8,%9}, {%0,%1,%2,%3};"
        : "+f"(c[0]), "+f"(c[1]), "+f"(c[2]), "+f"(c[3])
        : "r"(a[0]), "r"(a[1]), "r"(a[2]), "r"(a[3]), "r"(b0), "r"(b1));
}
__device__ __forceinline__ void split1(float v, __nv_bfloat16& h, __nv_bfloat16& l) {
    h = __float2bfloat16(v);
    l = __float2bfloat16(v - __bfloat162float(h));
}

// ---------------------------------------------------------------------------
// Merged Q/W conversion.  blocks [0, 20480): Q -> bf16 h/l + fp16.
// blocks [20480, 23552): W -> fp16.  4 elems/thread.
// ---------------------------------------------------------------------------
__global__ void conv_qw(const float* __restrict__ Q,
                        __nv_bfloat16* __restrict__ h,
                        __nv_bfloat16* __restrict__ l,
                        __half* __restrict__ qf,
                        const float* __restrict__ W,
                        __half* __restrict__ wf)
{
    const int bid = blockIdx.x;
    if (bid < 20480) {
        long i = ((long)bid * 256 + threadIdx.x) * 4;
        float4 v = *(const float4*)(Q + i);
        float vv[4] = {v.x, v.y, v.z, v.w};
        __nv_bfloat16 hh[4], ll[4];
        #pragma unroll
        for (int j = 0; j < 4; j++) split1(vv[j], hh[j], ll[j]);
        *(__nv_bfloat162*)(h + i)     = __nv_bfloat162(hh[0], hh[1]);
        *(__nv_bfloat162*)(h + i + 2) = __nv_bfloat162(hh[2], hh[3]);
        *(__nv_bfloat162*)(l + i)     = __nv_bfloat162(ll[0], ll[1]);
        *(__nv_bfloat162*)(l + i + 2) = __nv_bfloat162(ll[2], ll[3]);
        *(__half2*)(qf + i)     = __floats2half2_rn(v.x, v.y);
        *(__half2*)(qf + i + 2) = __floats2half2_rn(v.z, v.w);
    } else {
        long i = ((long)(bid - 20480) * 256 + threadIdx.x) * 4;
        float4 v = *(const float4*)(W + i);
        *(__half2*)(wf + i)     = __floats2half2_rn(v.x, v.y);
        *(__half2*)(wf + i + 2) = __floats2half2_rn(v.z, v.w);
    }
}

// ---------------------------------------------------------------------------
// Merged context conversion (C0 + C1): bf16 h/l straight + fp16 transposed.
// blocks [0, 20480): C0 (S=256, 80 batches); [20480, 24576): C1 (S=512, 8).
// ---------------------------------------------------------------------------
__global__ void conv_ctx2(const float* __restrict__ C0,
                          __nv_bfloat16* __restrict__ h0, __nv_bfloat16* __restrict__ l0,
                          __half* __restrict__ t0,
                          const float* __restrict__ C1,
                          __nv_bfloat16* __restrict__ h1, __nv_bfloat16* __restrict__ l1,
                          __half* __restrict__ t1)
{
    __shared__ float t[32][33];
    const int bid = blockIdx.x;
    const float* x; __nv_bfloat16 *h, *l; __half* tf; int S, b, st, dt;
    if (bid < 20480) {
        x = C0; h = h0; l = l0; tf = t0; S = LQ;
        st = bid & 7; dt = (bid >> 3) & 31; b = bid >> 8;
    } else {
        const int r = bid - 20480;
        x = C1; h = h1; l = l1; tf = t1; S = SS;
        st = r & 15; dt = (r >> 4) & 31; b = r >> 9;
    }
    const int s0 = st * 32, d0 = dt * 32;
    const int tx = threadIdx.x, ty = threadIdx.y;

    const float* xp = x + (long)b * S * 1024;
    #pragma unroll
    for (int r = 0; r < 4; r++) {
        int s = ty + r * 8;
        float v = xp[(long)(s0 + s) * 1024 + d0 + tx];
        t[s][tx] = v;
        __nv_bfloat16 hh, ll;
        split1(v, hh, ll);
        long off = ((long)b * S + s0 + s) * 1024 + d0 + tx;
        h[off] = hh; l[off] = ll;
    }
    __syncthreads();
    const long ob = (long)b * 1024 * S;
    #pragma unroll
    for (int r = 0; r < 4; r++) {
        int d = ty + r * 8;
        tf[ob + (long)(d0 + d) * S + s0 + tx] = __float2half(t[tx][d]);
    }
}

// ---------------------------------------------------------------------------
// Combined softmax: grid.x = 2*20480.  bid<20480: EXA row (n=256),
// else SEA row (n=512).  Warp-shuffle reductions.
// ---------------------------------------------------------------------------
__global__ void softmax2(float* __restrict__ exa, __half* __restrict__ pef,
                         float* __restrict__ sea, __half* __restrict__ psf)
{
    __shared__ float wm[8], ws[8];
    const int bid = blockIdx.x;
    const int tid = threadIdx.x;
    const int lane = tid & 31, wid = tid >> 5;

    float* p; __half* pf; int n;
    if (bid < BT * LQ) {
        p = exa + (long)bid * LQ;  pf = pef + (long)bid * LQ;  n = LQ;
    } else {
        const int r = bid - BT * LQ;
        p = sea + (long)r * SS;    pf = psf + (long)r * SS;    n = SS;
    }

    float v0 = p[tid];
    float v1 = (n > 256) ? p[tid + 256] : -3.402823e38f;

    float m = fmaxf(v0, v1);
    #pragma unroll
    for (int o = 16; o > 0; o >>= 1) m = fmaxf(m, __shfl_xor_sync(~0u, m, o));
    if (lane == 0) wm[wid] = m;
    __syncthreads();
    float mx = wm[0];
    #pragma unroll
    for (int i = 1; i < 8; i++) mx = fmaxf(mx, wm[i]);

    float e0 = __expf(v0 - mx);
    float e1 = (n > 256) ? __expf(v1 - mx) : 0.0f;
    float s = e0 + e1;
    #pragma unroll
    for (int o = 16; o > 0; o >>= 1) s += __shfl_xor_sync(~0u, s, o);
    if (lane == 0) ws[wid] = s;
    __syncthreads();
    float tot = ws[0];
    #pragma unroll
    for (int i = 1; i < 8; i++) tot += ws[i];
    const float inv = 1.0f / tot;

    float p0 = e0 * inv;
    p[tid] = p0; pf[tid] = __float2half(p0);
    if (n > 256) {
        float p1 = e1 * inv;
        p[tid + 256] = p1; pf[tid + 256] = __float2half(p1);
    }
}

// ---------------------------------------------------------------------------
// bf16-split logits geometry
// ---------------------------------------------------------------------------
#define TILE_B   10240
#define OFF_AH   0
#define OFF_AL   (TILE_B)
#define OFF_BH   (2*TILE_B)
#define OFF_BL   (3*TILE_B)
#define STAGE_B  (4*TILE_B)
#define MM_SMEM  (3*STAGE_B)           // 122880

// ---------------------------------------------------------------------------
// Combined logits: grid (6, 2, 80).  bx<2 -> ex (N=256), else set (N=512).
// K=1024 both.  bf16 3-product.  (unchanged, proven)
// ---------------------------------------------------------------------------
__global__ __launch_bounds__(256)
void mma_logits(const __nv_bfloat16* __restrict__ Ah, const __nv_bfloat16* __restrict__ Al,
                const __nv_bfloat16* __restrict__ c0h, const __nv_bfloat16* __restrict__ c0l,
                const __nv_bfloat16* __restrict__ c1h, const __nv_bfloat16* __restrict__ c1l,
                float* __restrict__ exa, float* __restrict__ sea)
{
    extern __shared__ char smem[];
    const uint32_t sb = smem_u32(smem);
    const int tid  = threadIdx.x;
    const int wid  = tid >> 5;
    const int lane = tid & 31;
    const int bz = blockIdx.z;
    const int m0 = blockIdx.y * 128;

    const bool isSet = blockIdx.x >= 2;
    const int  n0 = (isSet ? blockIdx.x - 2 : blockIdx.x) * 128;
    const int  N  = isSet ? SS : LQ;
    const __nv_bfloat16* Bh = isSet ? c1h : c0h;
    const __nv_bfloat16* Bl = isSet ? c1l : c0l;
    float* Cf = isSet ? sea : exa;
    const long bBatch = isSet ? (long)SS * HD : (long)LQ * HD;
    const int  bDiv   = isSet ? 10 : 1;
    const int  K = HD;
    const int  NCH = K >> 5;

    const long aBase = (long)bz * 256 * K + (long)m0 * K;
    const long bBase = (long)(bz / bDiv) * bBatch + (long)n0 * K;

    const int wm = (wid & 3) * 32;
    const int wn = (wid >> 2) * 64;
    const int laneR  = lane & 15;
    const int laneC8 = (lane >> 4) << 3;
    const uint32_t aRow = (uint32_t)((wm + laneR) * 40 + laneC8) * 2;
    const uint32_t bRow = (uint32_t)((wn + laneR) * 40 + laneC8) * 2;

    const int r0 = tid >> 2, s0 = tid & 3;
    const int r1 = r0 + 64;

    auto issue = [&](int c) {
        const int k0 = c << 5;
        const uint32_t st = sb + (uint32_t)(c % 3) * STAGE_B;
        uint32_t so0 = (uint32_t)(r0 * 40 + s0 * 8) * 2;
        uint32_t so1 = (uint32_t)(r1 * 40 + s0 * 8) * 2;
        long ao0 = aBase + (long)r0 * K + k0 + s0 * 8;
        long ao1 = aBase + (long)r1 * K + k0 + s0 * 8;
        long bo0 = bBase + (long)r0 * K + k0 + s0 * 8;
        long bo1 = bBase + (long)r1 * K + k0 + s0 * 8;
        cp16(st + OFF_AH + so0, Ah + ao0);
        cp16(st + OFF_AH + so1, Ah + ao1);
        cp16(st + OFF_AL + so0, Al + ao0);
        cp16(st + OFF_AL + so1, Al + ao1);
        cp16(st + OFF_BH + so0, Bh + bo0);
        cp16(st + OFF_BH + so1, Bh + bo1);
        cp16(st + OFF_BL + so0, Bl + bo0);
        cp16(st + OFF_BL + so1, Bl + bo1);
        CP_COMMIT();
    };

    float acc[2][8][4];
    #pragma unroll
    for (int i = 0; i < 2; i++)
        #pragma unroll
        for (int j = 0; j < 8; j++)
            #pragma unroll
            for (int k = 0; k < 4; k++) acc[i][j][k] = 0.0f;

    issue(0); issue(1);

    for (int c = 0; c < NCH; c++) {
        if (c + 1 < NCH) CP_WAIT1(); else CP_WAIT0();
        __syncthreads();
        if (c + 2 < NCH) issue(c + 2);

        const uint32_t st = sb + (uint32_t)(c % 3) * STAGE_B;
        #pragma unroll
        for (int ks = 0; ks < 2; ks++) {
            const uint32_t kOff = (uint32_t)(ks * 16) * 2;
            uint32_t af[2][4], bh[4][4], bl[4][4];
            #pragma unroll
            for (int mt = 0; mt < 2; mt++)
                ldm4(af[mt], st + OFF_AH + aRow + (uint32_t)(mt * 640) * 2 + kOff);
            #pragma unroll
            for (int np = 0; np < 4; np++) {
                ldm4(bh[np], st + OFF_BH + bRow + (uint32_t)(np * 640) * 2 + kOff);
                ldm4(bl[np], st + OFF_BL + bRow + (uint32_t)(np * 640) * 2 + kOff);
            }
            #pragma unroll
            for (int mt = 0; mt < 2; mt++)
                #pragma unroll
                for (int nt = 0; nt < 8; nt++) {
                    const int np = nt >> 1, sel = nt & 1;
                    mma16816(acc[mt][nt], af[mt], bh[np][sel], bh[np][sel + 2]);
                    mma16816(acc[mt][nt], af[mt], bl[np][sel], bl[np][sel + 2]);
                }
            #pragma unroll
            for (int mt = 0; mt < 2; mt++)
                ldm4(af[mt], st + OFF_AL + aRow + (uint32_t)(mt * 640) * 2 + kOff);
            #pragma unroll
            for (int mt = 0; mt < 2; mt++)
                #pragma unroll
                for (int nt = 0; nt < 8; nt++) {
                    const int np = nt >> 1, sel = nt & 1;
                    mma16816(acc[mt][nt], af[mt], bh[np][sel], bh[np][sel + 2]);
                }
        }
        __syncthreads();
    }

    float* Cp = Cf + (long)bz * 256 * N;
    #pragma unroll
    for (int mt = 0; mt < 2; mt++) {
        const int gm = m0 + wm + mt * 16 + (lane >> 2);
        #pragma unroll
        for (int nt = 0; nt < 8; nt++) {
            const int gn = n0 + wn + nt * 8 + ((lane & 3) << 1);
            *(float2*)(Cp + (long)gm * N + gn) =
                make_float2(acc[mt][nt][0], acc[mt][nt][1]);
            *(float2*)(Cp + (long)(gm + 8) * N + gn) =
                make_float2(acc[mt][nt][2], acc[mt][nt][3]);
        }
    }
}

// ---------------------------------------------------------------------------
// fp16 single-product geometry: CTA 256x128, warp 64x64.
// ---------------------------------------------------------------------------
#define PV_A_B   20480
#define PV_B_B   10240
#define PV_STAGE (PV_A_B + PV_B_B)
#define PV_SMEM  (3*PV_STAGE)          // 92160

// ---------------------------------------------------------------------------
// Combined PV + Q@W1 partial.  grid (24, 1, 80):
//   bx 0-7  : Q@W1  (K=1024, B=wf stride 3072) -> fp32 partial   [longest first]
//   bx 8-15 : set PV (K=512) -> fp16 scf
//   bx 16-23: ex PV  (K=256) -> fp16 ecf
// ---------------------------------------------------------------------------
__global__ __launch_bounds__(256)
void mma_pvqw(const __half* __restrict__ qf, const __half* __restrict__ wf,
              float* __restrict__ part,
              const __half* __restrict__ pef, const __half* __restrict__ t0f,
              __half* __restrict__ ecf,
              const __half* __restrict__ psf, const __half* __restrict__ t1f,
              __half* __restrict__ scf)
{
    extern __shared__ char smem[];
    const uint32_t sb = smem_u32(smem);
    const int tid  = threadIdx.x;
    const int wid  = tid >> 5;
    const int lane = tid & 31;
    const int bz = blockIdx.z;
    const int bx = blockIdx.x;

    int kind, K, n0; const __half *Ap, *Bp; long aBase, bBase, bStr;
    if (bx < 8) {            // Q @ W1
        kind = 0; K = 1024; n0 = bx * 128;
        Ap = qf;  aBase = (long)bz * 256 * 1024;
        Bp = wf;  bBase = (long)n0 * 3072; bStr = 3072;
    } else if (bx < 16) {    // set PV
        kind = 1; K = SS; n0 = (bx - 8) * 128;
        Ap = psf; aBase = (long)bz * 256 * SS;
        Bp = t1f; bBase = (long)(bz / 10) * HD * SS + (long)n0 * SS; bStr = SS;
    } else {                 // ex PV
        kind = 2; K = LQ; n0 = (bx - 16) * 128;
        Ap = pef; aBase = (long)bz * 256 * LQ;
        Bp = t0f; bBase = (long)bz * HD * LQ + (long)n0 * LQ; bStr = LQ;
    }
    const int NCH = K >> 5;

    const int wm = (wid & 3) * 64;
    const int wn = (wid >> 2) * 64;
    const int laneR  = lane & 15;
    const int laneC8 = (lane >> 4) << 3;
    const uint32_t aRow = (uint32_t)((wm + laneR) * 40 + laneC8) * 2;
    const uint32_t bRow = (uint32_t)((wn + laneR) * 40 + laneC8) * 2;

    const int r0 = tid >> 2, s0 = tid & 3;

    auto issue = [&](int c) {
        const int k0 = c << 5;
        const uint32_t st = sb + (uint32_t)(c % 3) * PV_STAGE;
        #pragma unroll
        for (int j = 0; j < 4; j++) {
            int row = r0 + j * 64;
            cp16(st + (uint32_t)(row * 40 + s0 * 8) * 2,
                 Ap + aBase + (long)row * K + k0 + s0 * 8);
        }
        #pragma unroll
        for (int j = 0; j < 2; j++) {
            int row = r0 + j * 64;
            cp16(st + PV_A_B + (uint32_t)(row * 40 + s0 * 8) * 2,
                 Bp + bBase + (long)row * bStr + k0 + s0 * 8);
        }
        CP_COMMIT();
    };

    float acc[4][8][4];
    #pragma unroll
    for (int i = 0; i < 4; i++)
        #pragma unroll
        for (int j = 0; j < 8; j++)
            #pragma unroll
            for (int k = 0; k < 4; k++) acc[i][j][k] = 0.0f;

    issue(0); issue(1);

    for (int c = 0; c < NCH; c++) {
        if (c + 1 < NCH) CP_WAIT1(); else CP_WAIT0();
        __syncthreads();
        if (c + 2 < NCH) issue(c + 2);

        const uint32_t st = sb + (uint32_t)(c % 3) * PV_STAGE;
        #pragma unroll
        for (int ks = 0; ks < 2; ks++) {
            const uint32_t kOff = (uint32_t)(ks * 16) * 2;
            uint32_t af[4][4], bf[4][4];
            #pragma unroll
            for (int mt = 0; mt < 4; mt++)
                ldm4(af[mt], st + aRow + (uint32_t)(mt * 640) * 2 + kOff);
            #pragma unroll
            for (int np = 0; np < 4; np++)
                ldm4(bf[np], st + PV_A_B + bRow + (uint32_t)(np * 640) * 2 + kOff);
            #pragma unroll
            for (int mt = 0; mt < 4; mt++)
                #pragma unroll
                for (int nt = 0; nt < 8; nt++) {
                    const int np = nt >> 1, sel = nt & 1;
                    mma16816h(acc[mt][nt], af[mt], bf[np][sel], bf[np][sel + 2]);
                }
        }
        __syncthreads();
    }

    const long cb = (long)bz * 256 * 1024;
    if (kind == 0) {
        #pragma unroll
        for (int mt = 0; mt < 4; mt++) {
            const int gm = wm + mt * 16 + (lane >> 2);
            #pragma unroll
            for (int nt = 0; nt < 8; nt++) {
                const int gn = n0 + wn + nt * 8 + ((lane & 3) << 1);
                *(float2*)(part + cb + (long)gm * 1024 + gn) =
                    make_float2(acc[mt][nt][0], acc[mt][nt][1]);
                *(float2*)(part + cb + (long)(gm + 8) * 1024 + gn) =
                    make_float2(acc[mt][nt][2], acc[mt][nt][3]);
            }
        }
    } else {
        __half* Co = (kind == 1) ? scf : ecf;
        #pragma unroll
        for (int mt = 0; mt < 4; mt++) {
            const int gm = wm + mt * 16 + (lane >> 2);
            #pragma unroll
            for (int nt = 0; nt < 8; nt++) {
                const int gn = n0 + wn + nt * 8 + ((lane & 3) << 1);
                *(__half2*)(Co + cb + (long)gm * 1024 + gn) =
                    __floats2half2_rn(acc[mt][nt][0], acc[mt][nt][1]);
                *(__half2*)(Co + cb + (long)(gm + 8) * 1024 + gn) =
                    __floats2half2_rn(acc[mt][nt][2], acc[mt][nt][3]);
            }
        }
    }
}

// ---------------------------------------------------------------------------
// Final part 2: out = tanh([exc|setc] @ W[:,1024:3072]^T + part + b).
// K=2048 (chunks 0-31 -> ecf, 32-63 -> scf).  CTA 256x128, grid (8, 80).
// ---------------------------------------------------------------------------
#define NCHF2 64

__global__ __launch_bounds__(256)
void mma_final2(const __half* __restrict__ ecf, const __half* __restrict__ scf,
                const __half* __restrict__ wf, const float* __restrict__ part,
                const float* __restrict__ bias, float* __restrict__ out)
{
    extern __shared__ char smem[];
    const uint32_t sb = smem_u32(smem);
    const int tid  = threadIdx.x;
    const int wid  = tid >> 5;
    const int lane = tid & 31;
    const long m0 = (long)blockIdx.y * 256;
    const int  n0 = blockIdx.x * 128;

    const int wm = (wid & 3) * 64;
    const int wn = (wid >> 2) * 64;
    const int laneR  = lane & 15;
    const int laneC8 = (lane >> 4) << 3;
    const uint32_t aRow = (uint32_t)((wm + laneR) * 40 + laneC8) * 2;
    const uint32_t bRow = (uint32_t)((wn + laneR) * 40 + laneC8) * 2;

    const int r0 = tid >> 2, s0 = tid & 3;

    auto issue = [&](int c) {
        const int k0 = c << 5;
        const __half* Af = (k0 < 1024) ? ecf : scf;
        const int kin = k0 & 1023;
        const uint32_t st = sb + (uint32_t)(c % 3) * PV_STAGE;
        #pragma unroll
        for (int j = 0; j < 4; j++) {
            int row = r0 + j * 64;
            cp16(st + (uint32_t)(row * 40 + s0 * 8) * 2,
                 Af + (m0 + row) * 1024 + kin + s0 * 8);
        }
        #pragma unroll
        for (int j = 0; j < 2; j++) {
            int row = r0 + j * 64;
            cp16(st + PV_A_B + (uint32_t)(row * 40 + s0 * 8) * 2,
                 wf + (long)(n0 + row) * 3072 + 1024 + k0 + s0 * 8);
        }
        CP_COMMIT();
    };

    float acc[4][8][4];
    #pragma unroll
    for (int i = 0; i < 4; i++)
        #pragma unroll
        for (int j = 0; j < 8; j++)
            #pragma unroll
            for (int k = 0; k < 4; k++) acc[i][j][k] = 0.0f;

    issue(0); issue(1);

    for (int c = 0; c < NCHF2; c++) {
        if (c + 1 < NCHF2) CP_WAIT1(); else CP_WAIT0();
        __syncthreads();
        if (c + 2 < NCHF2) issue(c + 2);

        const uint32_t st = sb + (uint32_t)(c % 3) * PV_STAGE;
        #pragma unroll
        for (int ks = 0; ks < 2; ks++) {
            const uint32_t kOff = (uint32_t)(ks * 16) * 2;
            uint32_t af[4][4], bf[4][4];
            #pragma unroll
            for (int mt = 0; mt < 4; mt++)
                ldm4(af[mt], st + aRow + (uint32_t)(mt * 640) * 2 + kOff);
            #pragma unroll
            for (int np = 0; np < 4; np++)
                ldm4(bf[np], st + PV_A_B + bRow + (uint32_t)(np * 640) * 2 + kOff);
            #pragma unroll
            for (int mt = 0; mt < 4; mt++)
                #pragma unroll
                for (int nt = 0; nt < 8; nt++) {
                    const int np = nt >> 1, sel = nt & 1;
                    mma16816h(acc[mt][nt], af[mt], bf[np][sel], bf[np][sel + 2]);
                }
        }
        __syncthreads();
    }

    #pragma unroll
    for (int mt = 0; mt < 4; mt++) {
        const long gm = m0 + wm + mt * 16 + (lane >> 2);
        #pragma unroll
        for (int nt = 0; nt < 8; nt++) {
            const int gn = n0 + wn + nt * 8 + ((lane & 3) << 1);
            const float b0 = bias[gn], b1 = bias[gn + 1];
            float2 pa = *(const float2*)(part + gm * 1024 + gn);
            float2 pb = *(const float2*)(part + (gm + 8) * 1024 + gn);
            *(float2*)(out + gm * 1024 + gn) =
                make_float2(tanhf(acc[mt][nt][0] + pa.x + b0),
                            tanhf(acc[mt][nt][1] + pa.y + b1));
            *(float2*)(out + (gm + 8) * 1024 + gn) =
                make_float2(tanhf(acc[mt][nt][2] + pb.x + b0),
                            tanhf(acc[mt][nt][3] + pb.y + b1));
        }
    }
}

// ---------------------------------------------------------------------------
extern "C" void kernel_launch(void* const* d_in, const int* in_sizes, int n_in,
                              void* d_out, int out_size)
{
    const float* Q  = (const float*)d_in[0];
    const float* C0 = (const float*)d_in[1];
    const float* C1 = (const float*)d_in[2];
    // d_in[3] = mask (unused, faithful to reference)
    const float* W  = (const float*)d_in[4];
    const float* bb = (const float*)d_in[5];

    float* OUT = (float*)d_out;
    float* EXA = OUT + (long)BT * LQ * HD;
    float* SEA = EXA + (long)BT * LQ * LQ;

    #define SYM(t, v, s) void* p_##v; cudaGetSymbolAddress(&p_##v, s); \
                         t* v = (t*)p_##v
    SYM(__nv_bfloat16, qh,  g_qh);  SYM(__nv_bfloat16, ql,  g_ql);
    SYM(__nv_bfloat16, c0h, g_c0h); SYM(__nv_bfloat16, c0l, g_c0l);
    SYM(__nv_bfloat16, c1h, g_c1h); SYM(__nv_bfloat16, c1l, g_c1l);
    SYM(__half, qf,  g_qf);  SYM(__half, wf,  g_wf);
    SYM(__half, ecf, g_ecf); SYM(__half, scf, g_scf);
    SYM(__half, pef, g_pef); SYM(__half, psf, g_psf);
    SYM(__half, t0f, g_t0f); SYM(__half, t1f, g_t1f);
    SYM(float, part, g_part);
    #undef SYM

    cudaFuncSetAttribute(mma_logits, cudaFuncAttributeMaxDynamicSharedMemorySize, MM_SMEM);
    cudaFuncSetAttribute(mma_pvqw,   cudaFuncAttributeMaxDynamicSharedMemorySize, PV_SMEM);
    cudaFuncSetAttribute(mma_final2, cudaFuncAttributeMaxDynamicSharedMemorySize, PV_SMEM);

    // merged conversions
    conv_qw<<<23552, 256>>>(Q, qh, ql, qf, W, wf);
    conv_ctx2<<<24576, dim3(32, 8)>>>(C0, c0h, c0l, t0f, C1, c1h, c1l, t1f);

    // logits (combined ex+set, bf16 3-product)
    mma_logits<<<dim3(6, 2, BT), 256, MM_SMEM>>>(qh, ql, c0h, c0l, c1h, c1l, EXA, SEA);

    // softmax (combined), in place + fp16 prob copy
    softmax2<<<2 * BT * LQ, 256>>>(EXA, pef, SEA, psf);

    // PV + Q@W1 partial (combined, fp16 single product)
    mma_pvqw<<<dim3(24, 1, BT), 256, PV_SMEM>>>(qf, wf, part,
                                                pef, t0f, ecf, psf, t1f, scf);

    // final part 2 ([ec|sc] @ W23 + partial + bias -> tanh)
    mma_final2<<<dim3(8, 80), 256, PV_SMEM>>>(ecf, scf, wf, part, bb, OUT);
}

// round 16
// speedup vs baseline: 3.9656x; 1.0700x over previous
#include <cuda_runtime.h>
#include <cuda_bf16.h>
#include <cuda_fp16.h>
#include <cstdint>

#define BT 80
#define LQ 256
#define SS 512
#define HD 1024

// ---------------- scratch (device globals; allocation-free rule) -----------
__device__ __nv_bfloat16 g_qh[(size_t)BT*LQ*HD],  g_ql[(size_t)BT*LQ*HD];
__device__ __nv_bfloat16 g_c0h[(size_t)BT*LQ*HD], g_c0l[(size_t)BT*LQ*HD];
__device__ __nv_bfloat16 g_c1h[(size_t)8*SS*HD],  g_c1l[(size_t)8*SS*HD];
__device__ __half g_qf[(size_t)BT*LQ*HD];
__device__ __half g_wf[(size_t)HD*3*HD];
__device__ __half g_ecf[(size_t)BT*LQ*HD], g_scf[(size_t)BT*LQ*HD];
__device__ __half g_pef[(size_t)BT*LQ*LQ], g_psf[(size_t)BT*LQ*SS];
__device__ __half g_t0f[(size_t)BT*HD*LQ], g_t1f[(size_t)8*HD*SS];
__device__ float  g_part[(size_t)BT*LQ*HD];   // Q @ W1 fp32 partial

// ---------------- portable PTX helpers -------------------------------------
__device__ __forceinline__ uint32_t smem_u32(const void* p) {
    uint32_t a;
    asm("{ .reg .u64 t; cvta.to.shared.u64 t, %1; cvt.u32.u64 %0, t; }" : "=r"(a) : "l"(p));
    return a;
}
__device__ __forceinline__ void cp16(uint32_t dst, const void* src) {
    asm volatile("cp.async.cg.shared.global [%0], [%1], 16;" :: "r"(dst), "l"(src));
}
#define CP_COMMIT() asm volatile("cp.async.commit_group;" ::: "memory")
#define CP_WAIT1()  asm volatile("cp.async.wait_group 1;" ::: "memory")
#define CP_WAIT0()  asm volatile("cp.async.wait_group 0;" ::: "memory")

__device__ __forceinline__ void ldm4(uint32_t* r, uint32_t addr) {
    asm volatile("ldmatrix.sync.aligned.m8n8.x4.shared.b16 {%0,%1,%2,%3}, [%4];"
        : "=r"(r[0]), "=r"(r[1]), "=r"(r[2]), "=r"(r[3]) : "r"(addr));
}
__device__ __forceinline__ void mma16816(float* c, const uint32_t* a,
                                         uint32_t b0, uint32_t b1) {
    asm volatile(
        "mma.sync.aligned.m16n8k16.row.col.f32.bf16.bf16.f32 "
        "{%0,%1,%2,%3}, {%4,%5,%6,%7}, {%8,%9}, {%0,%1,%2,%3};"
        : "+f"(c[0]), "+f"(c[1]), "+f"(c[2]), "+f"(c[3])
        : "r"(a[0]), "r"(a[1]), "r"(a[2]), "r"(a[3]), "r"(b0), "r"(b1));
}
__device__ __forceinline__ void mma16816h(float* c, const uint32_t* a,
                                          uint32_t b0, uint32_t b1) {
    asm volatile(
        "mma.sync.aligned.m16n8k16.row.col.f32.f16.f16.f32 "
        "{%0,%1,%2,%3}, {%4,%5,%6,%7}, {%8,%9}, {%0,%1,%2,%3};"
        : "+f"(c[0]), "+f"(c[1]), "+f"(c[2]), "+f"(c[3])
        : "r"(a[0]), "r"(a[1]), "r"(a[2]), "r"(a[3]), "r"(b0), "r"(b1));
}
__device__ __forceinline__ void split1(float v, __nv_bfloat16& h, __nv_bfloat16& l) {
    h = __float2bfloat16(v);
    l = __float2bfloat16(v - __bfloat162float(h));
}

// ---------------------------------------------------------------------------
// All conversions in ONE launch.  Flat 256-thread blocks.
//   [0, 20480)        : Q  -> bf16 h/l + fp16            (4 elems/thread)
//   [20480, 23552)    : W  -> fp16
//   [23552, 44032)    : C0 -> bf16 h/l straight + fp16 transposed (32x32 tile)
//   [44032, 48128)    : C1 -> same
// ---------------------------------------------------------------------------
__global__ void conv_all(const float* __restrict__ Q,
                         __nv_bfloat16* __restrict__ qh, __nv_bfloat16* __restrict__ ql,
                         __half* __restrict__ qf,
                         const float* __restrict__ W, __half* __restrict__ wf,
                         const float* __restrict__ C0,
                         __nv_bfloat16* __restrict__ c0h, __nv_bfloat16* __restrict__ c0l,
                         __half* __restrict__ t0f,
                         const float* __restrict__ C1,
                         __nv_bfloat16* __restrict__ c1h, __nv_bfloat16* __restrict__ c1l,
                         __half* __restrict__ t1f)
{
    __shared__ float t[32][33];
    const int bid = blockIdx.x;
    const int tid = threadIdx.x;

    if (bid < 20480) {                       // Q
        long i = ((long)bid * 256 + tid) * 4;
        float4 v = *(const float4*)(Q + i);
        float vv[4] = {v.x, v.y, v.z, v.w};
        __nv_bfloat16 hh[4], ll[4];
        #pragma unroll
        for (int j = 0; j < 4; j++) split1(vv[j], hh[j], ll[j]);
        *(__nv_bfloat162*)(qh + i)     = __nv_bfloat162(hh[0], hh[1]);
        *(__nv_bfloat162*)(qh + i + 2) = __nv_bfloat162(hh[2], hh[3]);
        *(__nv_bfloat162*)(ql + i)     = __nv_bfloat162(ll[0], ll[1]);
        *(__nv_bfloat162*)(ql + i + 2) = __nv_bfloat162(ll[2], ll[3]);
        *(__half2*)(qf + i)     = __floats2half2_rn(v.x, v.y);
        *(__half2*)(qf + i + 2) = __floats2half2_rn(v.z, v.w);
        return;
    }
    if (bid < 23552) {                       // W
        long i = ((long)(bid - 20480) * 256 + tid) * 4;
        float4 v = *(const float4*)(W + i);
        *(__half2*)(wf + i)     = __floats2half2_rn(v.x, v.y);
        *(__half2*)(wf + i + 2) = __floats2half2_rn(v.z, v.w);
        return;
    }

    // context tiles
    const float* x; __nv_bfloat16 *h, *l; __half* tf; int S, b, st, dt;
    if (bid < 44032) {
        const int r = bid - 23552;
        x = C0; h = c0h; l = c0l; tf = t0f; S = LQ;
        st = r & 7; dt = (r >> 3) & 31; b = r >> 8;
    } else {
        const int r = bid - 44032;
        x = C1; h = c1h; l = c1l; tf = t1f; S = SS;
        st = r & 15; dt = (r >> 4) & 31; b = r >> 9;
    }
    const int s0 = st * 32, d0 = dt * 32;
    const int tx = tid & 31, ty = tid >> 5;

    const float* xp = x + (long)b * S * 1024;
    #pragma unroll
    for (int r = 0; r < 4; r++) {
        int s = ty + r * 8;
        float v = xp[(long)(s0 + s) * 1024 + d0 + tx];
        t[s][tx] = v;
        __nv_bfloat16 hh, ll;
        split1(v, hh, ll);
        long off = ((long)b * S + s0 + s) * 1024 + d0 + tx;
        h[off] = hh; l[off] = ll;
    }
    __syncthreads();
    const long ob = (long)b * 1024 * S;
    #pragma unroll
    for (int r = 0; r < 4; r++) {
        int d = ty + r * 8;
        tf[ob + (long)(d0 + d) * S + s0 + tx] = __float2half(t[tx][d]);
    }
}

// ---------------------------------------------------------------------------
// Vectorized softmax.  float4 per thread; 64 thr/row (ex, 4 rows/block) or
// 128 thr/row (set, 2 rows/block).  grid = 5120 + 10240 = 15360.
// ---------------------------------------------------------------------------
__global__ void softmax2v(float* __restrict__ exa, __half* __restrict__ pef,
                          float* __restrict__ sea, __half* __restrict__ psf)
{
    __shared__ float sm[8], ss[8];
    const int bid = blockIdx.x;
    const int tid = threadIdx.x;
    const int lane = tid & 31, wid = tid >> 5;

    float* p; __half* pf; int c4, w0, nw;
    if (bid < 5120) {                 // ex: 4 rows x 256, 64 thr/row
        const int row = bid * 4 + (tid >> 6);
        p  = exa + (long)row * LQ;
        pf = pef + (long)row * LQ;
        c4 = (tid & 63) * 4;
        w0 = wid & ~1; nw = 2;
    } else {                          // set: 2 rows x 512, 128 thr/row
        const int row = (bid - 5120) * 2 + (tid >> 7);
        p  = sea + (long)row * SS;
        pf = psf + (long)row * SS;
        c4 = (tid & 127) * 4;
        w0 = wid & ~3; nw = 4;
    }

    float4 v = *(const float4*)(p + c4);
    float m = fmaxf(fmaxf(v.x, v.y), fmaxf(v.z, v.w));
    #pragma unroll
    for (int o = 16; o > 0; o >>= 1) m = fmaxf(m, __shfl_xor_sync(~0u, m, o));
    if (lane == 0) sm[wid] = m;
    __syncthreads();
    float mx = sm[w0];
    for (int i = 1; i < nw; i++) mx = fmaxf(mx, sm[w0 + i]);

    float e0 = __expf(v.x - mx), e1 = __expf(v.y - mx);
    float e2 = __expf(v.z - mx), e3 = __expf(v.w - mx);
    float s = (e0 + e1) + (e2 + e3);
    #pragma unroll
    for (int o = 16; o > 0; o >>= 1) s += __shfl_xor_sync(~0u, s, o);
    if (lane == 0) ss[wid] = s;
    __syncthreads();
    float tot = ss[w0];
    for (int i = 1; i < nw; i++) tot += ss[w0 + i];
    const float inv = 1.0f / tot;

    float p0 = e0 * inv, p1 = e1 * inv, p2 = e2 * inv, p3 = e3 * inv;
    *(float4*)(p + c4) = make_float4(p0, p1, p2, p3);
    *(__half2*)(pf + c4)     = __floats2half2_rn(p0, p1);
    *(__half2*)(pf + c4 + 2) = __floats2half2_rn(p2, p3);
}

// ---------------------------------------------------------------------------
// bf16-split logits geometry
// ---------------------------------------------------------------------------
#define TILE_B   10240
#define OFF_AH   0
#define OFF_AL   (TILE_B)
#define OFF_BH   (2*TILE_B)
#define OFF_BL   (3*TILE_B)
#define STAGE_B  (4*TILE_B)
#define MM_SMEM  (3*STAGE_B)           // 122880

// ---------------------------------------------------------------------------
// Combined logits: grid (6, 2, 80).  bx<2 -> ex (N=256), else set (N=512).
// K=1024 both.  bf16 3-product.  (unchanged, proven)
// ---------------------------------------------------------------------------
__global__ __launch_bounds__(256)
void mma_logits(const __nv_bfloat16* __restrict__ Ah, const __nv_bfloat16* __restrict__ Al,
                const __nv_bfloat16* __restrict__ c0h, const __nv_bfloat16* __restrict__ c0l,
                const __nv_bfloat16* __restrict__ c1h, const __nv_bfloat16* __restrict__ c1l,
                float* __restrict__ exa, float* __restrict__ sea)
{
    extern __shared__ char smem[];
    const uint32_t sb = smem_u32(smem);
    const int tid  = threadIdx.x;
    const int wid  = tid >> 5;
    const int lane = tid & 31;
    const int bz = blockIdx.z;
    const int m0 = blockIdx.y * 128;

    const bool isSet = blockIdx.x >= 2;
    const int  n0 = (isSet ? blockIdx.x - 2 : blockIdx.x) * 128;
    const int  N  = isSet ? SS : LQ;
    const __nv_bfloat16* Bh = isSet ? c1h : c0h;
    const __nv_bfloat16* Bl = isSet ? c1l : c0l;
    float* Cf = isSet ? sea : exa;
    const long bBatch = isSet ? (long)SS * HD : (long)LQ * HD;
    const int  bDiv   = isSet ? 10 : 1;
    const int  K = HD;
    const int  NCH = K >> 5;

    const long aBase = (long)bz * 256 * K + (long)m0 * K;
    const long bBase = (long)(bz / bDiv) * bBatch + (long)n0 * K;

    const int wm = (wid & 3) * 32;
    const int wn = (wid >> 2) * 64;
    const int laneR  = lane & 15;
    const int laneC8 = (lane >> 4) << 3;
    const uint32_t aRow = (uint32_t)((wm + laneR) * 40 + laneC8) * 2;
    const uint32_t bRow = (uint32_t)((wn + laneR) * 40 + laneC8) * 2;

    const int r0 = tid >> 2, s0 = tid & 3;
    const int r1 = r0 + 64;

    auto issue = [&](int c) {
        const int k0 = c << 5;
        const uint32_t st = sb + (uint32_t)(c % 3) * STAGE_B;
        uint32_t so0 = (uint32_t)(r0 * 40 + s0 * 8) * 2;
        uint32_t so1 = (uint32_t)(r1 * 40 + s0 * 8) * 2;
        long ao0 = aBase + (long)r0 * K + k0 + s0 * 8;
        long ao1 = aBase + (long)r1 * K + k0 + s0 * 8;
        long bo0 = bBase + (long)r0 * K + k0 + s0 * 8;
        long bo1 = bBase + (long)r1 * K + k0 + s0 * 8;
        cp16(st + OFF_AH + so0, Ah + ao0);
        cp16(st + OFF_AH + so1, Ah + ao1);
        cp16(st + OFF_AL + so0, Al + ao0);
        cp16(st + OFF_AL + so1, Al + ao1);
        cp16(st + OFF_BH + so0, Bh + bo0);
        cp16(st + OFF_BH + so1, Bh + bo1);
        cp16(st + OFF_BL + so0, Bl + bo0);
        cp16(st + OFF_BL + so1, Bl + bo1);
        CP_COMMIT();
    };

    float acc[2][8][4];
    #pragma unroll
    for (int i = 0; i < 2; i++)
        #pragma unroll
        for (int j = 0; j < 8; j++)
            #pragma unroll
            for (int k = 0; k < 4; k++) acc[i][j][k] = 0.0f;

    issue(0); issue(1);

    for (int c = 0; c < NCH; c++) {
        if (c + 1 < NCH) CP_WAIT1(); else CP_WAIT0();
        __syncthreads();
        if (c + 2 < NCH) issue(c + 2);

        const uint32_t st = sb + (uint32_t)(c % 3) * STAGE_B;
        #pragma unroll
        for (int ks = 0; ks < 2; ks++) {
            const uint32_t kOff = (uint32_t)(ks * 16) * 2;
            uint32_t af[2][4], bh[4][4], bl[4][4];
            #pragma unroll
            for (int mt = 0; mt < 2; mt++)
                ldm4(af[mt], st + OFF_AH + aRow + (uint32_t)(mt * 640) * 2 + kOff);
            #pragma unroll
            for (int np = 0; np < 4; np++) {
                ldm4(bh[np], st + OFF_BH + bRow + (uint32_t)(np * 640) * 2 + kOff);
                ldm4(bl[np], st + OFF_BL + bRow + (uint32_t)(np * 640) * 2 + kOff);
            }
            #pragma unroll
            for (int mt = 0; mt < 2; mt++)
                #pragma unroll
                for (int nt = 0; nt < 8; nt++) {
                    const int np = nt >> 1, sel = nt & 1;
                    mma16816(acc[mt][nt], af[mt], bh[np][sel], bh[np][sel + 2]);
                    mma16816(acc[mt][nt], af[mt], bl[np][sel], bl[np][sel + 2]);
                }
            #pragma unroll
            for (int mt = 0; mt < 2; mt++)
                ldm4(af[mt], st + OFF_AL + aRow + (uint32_t)(mt * 640) * 2 + kOff);
            #pragma unroll
            for (int mt = 0; mt < 2; mt++)
                #pragma unroll
                for (int nt = 0; nt < 8; nt++) {
                    const int np = nt >> 1, sel = nt & 1;
                    mma16816(acc[mt][nt], af[mt], bh[np][sel], bh[np][sel + 2]);
                }
        }
        __syncthreads();
    }

    float* Cp = Cf + (long)bz * 256 * N;
    #pragma unroll
    for (int mt = 0; mt < 2; mt++) {
        const int gm = m0 + wm + mt * 16 + (lane >> 2);
        #pragma unroll
        for (int nt = 0; nt < 8; nt++) {
            const int gn = n0 + wn + nt * 8 + ((lane & 3) << 1);
            *(float2*)(Cp + (long)gm * N + gn) =
                make_float2(acc[mt][nt][0], acc[mt][nt][1]);
            *(float2*)(Cp + (long)(gm + 8) * N + gn) =
                make_float2(acc[mt][nt][2], acc[mt][nt][3]);
        }
    }
}

// ---------------------------------------------------------------------------
// fp16 single-product geometry (pvqw): CTA 256x128, warp 64x64.
// ---------------------------------------------------------------------------
#define PV_A_B   20480
#define PV_B_B   10240
#define PV_STAGE (PV_A_B + PV_B_B)
#define PV_SMEM  (3*PV_STAGE)          // 92160

// ---------------------------------------------------------------------------
// Combined PV + Q@W1 partial.  grid (24, 1, 80):
//   bx 0-7  : Q@W1  (K=1024) -> fp32 partial   [longest first]
//   bx 8-15 : set PV (K=512) -> fp16 scf
//   bx 16-23: ex PV  (K=256) -> fp16 ecf
// (unchanged, proven)
// ---------------------------------------------------------------------------
__global__ __launch_bounds__(256)
void mma_pvqw(const __half* __restrict__ qf, const __half* __restrict__ wf,
              float* __restrict__ part,
              const __half* __restrict__ pef, const __half* __restrict__ t0f,
              __half* __restrict__ ecf,
              const __half* __restrict__ psf, const __half* __restrict__ t1f,
              __half* __restrict__ scf)
{
    extern __shared__ char smem[];
    const uint32_t sb = smem_u32(smem);
    const int tid  = threadIdx.x;
    const int wid  = tid >> 5;
    const int lane = tid & 31;
    const int bz = blockIdx.z;
    const int bx = blockIdx.x;

    int kind, K, n0; const __half *Ap, *Bp; long aBase, bBase, bStr;
    if (bx < 8) {            // Q @ W1
        kind = 0; K = 1024; n0 = bx * 128;
        Ap = qf;  aBase = (long)bz * 256 * 1024;
        Bp = wf;  bBase = (long)n0 * 3072; bStr = 3072;
    } else if (bx < 16) {    // set PV
        kind = 1; K = SS; n0 = (bx - 8) * 128;
        Ap = psf; aBase = (long)bz * 256 * SS;
        Bp = t1f; bBase = (long)(bz / 10) * HD * SS + (long)n0 * SS; bStr = SS;
    } else {                 // ex PV
        kind = 2; K = LQ; n0 = (bx - 16) * 128;
        Ap = pef; aBase = (long)bz * 256 * LQ;
        Bp = t0f; bBase = (long)bz * HD * LQ + (long)n0 * LQ; bStr = LQ;
    }
    const int NCH = K >> 5;

    const int wm = (wid & 3) * 64;
    const int wn = (wid >> 2) * 64;
    const int laneR  = lane & 15;
    const int laneC8 = (lane >> 4) << 3;
    const uint32_t aRow = (uint32_t)((wm + laneR) * 40 + laneC8) * 2;
    const uint32_t bRow = (uint32_t)((wn + laneR) * 40 + laneC8) * 2;

    const int r0 = tid >> 2, s0 = tid & 3;

    auto issue = [&](int c) {
        const int k0 = c << 5;
        const uint32_t st = sb + (uint32_t)(c % 3) * PV_STAGE;
        #pragma unroll
        for (int j = 0; j < 4; j++) {
            int row = r0 + j * 64;
            cp16(st + (uint32_t)(row * 40 + s0 * 8) * 2,
                 Ap + aBase + (long)row * K + k0 + s0 * 8);
        }
        #pragma unroll
        for (int j = 0; j < 2; j++) {
            int row = r0 + j * 64;
            cp16(st + PV_A_B + (uint32_t)(row * 40 + s0 * 8) * 2,
                 Bp + bBase + (long)row * bStr + k0 + s0 * 8);
        }
        CP_COMMIT();
    };

    float acc[4][8][4];
    #pragma unroll
    for (int i = 0; i < 4; i++)
        #pragma unroll
        for (int j = 0; j < 8; j++)
            #pragma unroll
            for (int k = 0; k < 4; k++) acc[i][j][k] = 0.0f;

    issue(0); issue(1);

    for (int c = 0; c < NCH; c++) {
        if (c + 1 < NCH) CP_WAIT1(); else CP_WAIT0();
        __syncthreads();
        if (c + 2 < NCH) issue(c + 2);

        const uint32_t st = sb + (uint32_t)(c % 3) * PV_STAGE;
        #pragma unroll
        for (int ks = 0; ks < 2; ks++) {
            const uint32_t kOff = (uint32_t)(ks * 16) * 2;
            uint32_t af[4][4], bf[4][4];
            #pragma unroll
            for (int mt = 0; mt < 4; mt++)
                ldm4(af[mt], st + aRow + (uint32_t)(mt * 640) * 2 + kOff);
            #pragma unroll
            for (int np = 0; np < 4; np++)
                ldm4(bf[np], st + PV_A_B + bRow + (uint32_t)(np * 640) * 2 + kOff);
            #pragma unroll
            for (int mt = 0; mt < 4; mt++)
                #pragma unroll
                for (int nt = 0; nt < 8; nt++) {
                    const int np = nt >> 1, sel = nt & 1;
                    mma16816h(acc[mt][nt], af[mt], bf[np][sel], bf[np][sel + 2]);
                }
        }
        __syncthreads();
    }

    const long cb = (long)bz * 256 * 1024;
    if (kind == 0) {
        #pragma unroll
        for (int mt = 0; mt < 4; mt++) {
            const int gm = wm + mt * 16 + (lane >> 2);
            #pragma unroll
            for (int nt = 0; nt < 8; nt++) {
                const int gn = n0 + wn + nt * 8 + ((lane & 3) << 1);
                *(float2*)(part + cb + (long)gm * 1024 + gn) =
                    make_float2(acc[mt][nt][0], acc[mt][nt][1]);
                *(float2*)(part + cb + (long)(gm + 8) * 1024 + gn) =
                    make_float2(acc[mt][nt][2], acc[mt][nt][3]);
            }
        }
    } else {
        __half* Co = (kind == 1) ? scf : ecf;
        #pragma unroll
        for (int mt = 0; mt < 4; mt++) {
            const int gm = wm + mt * 16 + (lane >> 2);
            #pragma unroll
            for (int nt = 0; nt < 8; nt++) {
                const int gn = n0 + wn + nt * 8 + ((lane & 3) << 1);
                *(__half2*)(Co + cb + (long)gm * 1024 + gn) =
                    __floats2half2_rn(acc[mt][nt][0], acc[mt][nt][1]);
                *(__half2*)(Co + cb + (long)(gm + 8) * 1024 + gn) =
                    __floats2half2_rn(acc[mt][nt][2], acc[mt][nt][3]);
            }
        }
    }
}

// ---------------------------------------------------------------------------
// Final part 2: out = tanh([exc|setc] @ W[:,1024:3072]^T + part + b).
// K=2048 (chunks 0-31 -> ecf, 32-63 -> scf).
// CTA 128x128 (warp 32x64, proven-at-cap shape), grid (8, 160).
// ---------------------------------------------------------------------------
#define F2_TILE  10240
#define F2_STAGE (2*F2_TILE)
#define F2_SMEM  (3*F2_STAGE)          // 61440
#define NCHF2 64

__global__ __launch_bounds__(256)
void mma_final2(const __half* __restrict__ ecf, const __half* __restrict__ scf,
                const __half* __restrict__ wf, const float* __restrict__ part,
                const float* __restrict__ bias, float* __restrict__ out)
{
    extern __shared__ char smem[];
    const uint32_t sb = smem_u32(smem);
    const int tid  = threadIdx.x;
    const int wid  = tid >> 5;
    const int lane = tid & 31;
    const long m0 = (long)blockIdx.y * 128;
    const int  n0 = blockIdx.x * 128;

    const int wm = (wid & 3) * 32;
    const int wn = (wid >> 2) * 64;
    const int laneR  = lane & 15;
    const int laneC8 = (lane >> 4) << 3;
    const uint32_t aRow = (uint32_t)((wm + laneR) * 40 + laneC8) * 2;
    const uint32_t bRow = (uint32_t)((wn + laneR) * 40 + laneC8) * 2;

    const int r0 = tid >> 2, s0 = tid & 3;
    const int r1 = r0 + 64;

    auto issue = [&](int c) {
        const int k0 = c << 5;
        const __half* Af = (k0 < 1024) ? ecf : scf;
        const int kin = k0 & 1023;
        const uint32_t st = sb + (uint32_t)(c % 3) * F2_STAGE;
        uint32_t so0 = (uint32_t)(r0 * 40 + s0 * 8) * 2;
        uint32_t so1 = (uint32_t)(r1 * 40 + s0 * 8) * 2;
        cp16(st + so0, Af + (m0 + r0) * 1024 + kin + s0 * 8);
        cp16(st + so1, Af + (m0 + r1) * 1024 + kin + s0 * 8);
        cp16(st + F2_TILE + so0, wf + (long)(n0 + r0) * 3072 + 1024 + k0 + s0 * 8);
        cp16(st + F2_TILE + so1, wf + (long)(n0 + r1) * 3072 + 1024 + k0 + s0 * 8);
        CP_COMMIT();
    };

    float acc[2][8][4];
    #pragma unroll
    for (int i = 0; i < 2; i++)
        #pragma unroll
        for (int j = 0; j < 8; j++)
            #pragma unroll
            for (int k = 0; k < 4; k++) acc[i][j][k] = 0.0f;

    issue(0); issue(1);

    for (int c = 0; c < NCHF2; c++) {
        if (c + 1 < NCHF2) CP_WAIT1(); else CP_WAIT0();
        __syncthreads();
        if (c + 2 < NCHF2) issue(c + 2);

        const uint32_t st = sb + (uint32_t)(c % 3) * F2_STAGE;
        #pragma unroll
        for (int ks = 0; ks < 2; ks++) {
            const uint32_t kOff = (uint32_t)(ks * 16) * 2;
            uint32_t af[2][4], bf[4][4];
            #pragma unroll
            for (int mt = 0; mt < 2; mt++)
                ldm4(af[mt], st + aRow + (uint32_t)(mt * 640) * 2 + kOff);
            #pragma unroll
            for (int np = 0; np < 4; np++)
                ldm4(bf[np], st + F2_TILE + bRow + (uint32_t)(np * 640) * 2 + kOff);
            #pragma unroll
            for (int mt = 0; mt < 2; mt++)
                #pragma unroll
                for (int nt = 0; nt < 8; nt++) {
                    const int np = nt >> 1, sel = nt & 1;
                    mma16816h(acc[mt][nt], af[mt], bf[np][sel], bf[np][sel + 2]);
                }
        }
        __syncthreads();
    }

    #pragma unroll
    for (int mt = 0; mt < 2; mt++) {
        const long gm = m0 + wm + mt * 16 + (lane >> 2);
        #pragma unroll
        for (int nt = 0; nt < 8; nt++) {
            const int gn = n0 + wn + nt * 8 + ((lane & 3) << 1);
            const float b0 = bias[gn], b1 = bias[gn + 1];
            float2 pa = *(const float2*)(part + gm * 1024 + gn);
            float2 pb = *(const float2*)(part + (gm + 8) * 1024 + gn);
            *(float2*)(out + gm * 1024 + gn) =
                make_float2(tanhf(acc[mt][nt][0] + pa.x + b0),
                            tanhf(acc[mt][nt][1] + pa.y + b1));
            *(float2*)(out + (gm + 8) * 1024 + gn) =
                make_float2(tanhf(acc[mt][nt][2] + pb.x + b0),
                            tanhf(acc[mt][nt][3] + pb.y + b1));
        }
    }
}

// ---------------------------------------------------------------------------
extern "C" void kernel_launch(void* const* d_in, const int* in_sizes, int n_in,
                              void* d_out, int out_size)
{
    const float* Q  = (const float*)d_in[0];
    const float* C0 = (const float*)d_in[1];
    const float* C1 = (const float*)d_in[2];
    // d_in[3] = mask (unused, faithful to reference)
    const float* W  = (const float*)d_in[4];
    const float* bb = (const float*)d_in[5];

    float* OUT = (float*)d_out;
    float* EXA = OUT + (long)BT * LQ * HD;
    float* SEA = EXA + (long)BT * LQ * LQ;

    #define SYM(t, v, s) void* p_##v; cudaGetSymbolAddress(&p_##v, s); \
                         t* v = (t*)p_##v
    SYM(__nv_bfloat16, qh,  g_qh);  SYM(__nv_bfloat16, ql,  g_ql);
    SYM(__nv_bfloat16, c0h, g_c0h); SYM(__nv_bfloat16, c0l, g_c0l);
    SYM(__nv_bfloat16, c1h, g_c1h); SYM(__nv_bfloat16, c1l, g_c1l);
    SYM(__half, qf,  g_qf);  SYM(__half, wf,  g_wf);
    SYM(__half, ecf, g_ecf); SYM(__half, scf, g_scf);
    SYM(__half, pef, g_pef); SYM(__half, psf, g_psf);
    SYM(__half, t0f, g_t0f); SYM(__half, t1f, g_t1f);
    SYM(float, part, g_part);
    #undef SYM

    cudaFuncSetAttribute(mma_logits, cudaFuncAttributeMaxDynamicSharedMemorySize, MM_SMEM);
    cudaFuncSetAttribute(mma_pvqw,   cudaFuncAttributeMaxDynamicSharedMemorySize, PV_SMEM);
    cudaFuncSetAttribute(mma_final2, cudaFuncAttributeMaxDynamicSharedMemorySize, F2_SMEM);

    // all conversions, one launch
    conv_all<<<48128, 256>>>(Q, qh, ql, qf, W, wf,
                             C0, c0h, c0l, t0f, C1, c1h, c1l, t1f);

    // logits (combined ex+set, bf16 3-product)
    mma_logits<<<dim3(6, 2, BT), 256, MM_SMEM>>>(qh, ql, c0h, c0l, c1h, c1l, EXA, SEA);

    // softmax (vectorized), in place + fp16 prob copy
    softmax2v<<<15360, 256>>>(EXA, pef, SEA, psf);

    // PV + Q@W1 partial (combined, fp16 single product)
    mma_pvqw<<<dim3(24, 1, BT), 256, PV_SMEM>>>(qf, wf, part,
                                                pef, t0f, ecf, psf, t1f, scf);

    // final part 2 ([ec|sc] @ W23 + partial + bias -> tanh), CTA 128x128
    mma_final2<<<dim3(8, 160), 256, F2_SMEM>>>(ecf, scf, wf, part, bb, OUT);
}